// round 2
// baseline (speedup 1.0000x reference)
#include <cuda_runtime.h>
#include <math.h>

#define Bsz  128
#define HW   512
#define Pp   64
#define ND   4
#define HWHW 262144

// scratch (static device globals)
__device__ float g_A [33554432];   // [128][512][512]  x  @ [o_xj | o_rel_xj]
__device__ float g_C2[33554432];   // [128][512][512]  xT @ [o_xi | o_rel_xi]
__device__ float g_G  [2 * Bsz * ND * Pp * Pp];
__device__ float g_cs [2 * Bsz * ND * Pp];
__device__ float g_tot[2 * Bsz * ND];
__device__ float g_meanv[Bsz];
__device__ float g_stdv [Bsz];

__global__ void __launch_bounds__(256) stats_kernel(const float* __restrict__ x) {
    int b = blockIdx.x, t = threadIdx.x;
    const float4* xv = reinterpret_cast<const float4*>(x + (size_t)b * HWHW);
    float s = 0.f, ss = 0.f;
    for (int i = t; i < HWHW / 4; i += 256) {
        float4 v = xv[i];
        s  += v.x + v.y + v.z + v.w;
        ss += v.x * v.x + v.y * v.y + v.z * v.z + v.w * v.w;
    }
    __shared__ float rs[256], rq[256];
    rs[t] = s; rq[t] = ss; __syncthreads();
    for (int off = 128; off > 0; off >>= 1) {
        if (t < off) { rs[t] += rs[t + off]; rq[t] += rq[t + off]; }
        __syncthreads();
    }
    if (t == 0) {
        float n = (float)HWHW;
        float mean = rs[0] / n;
        float var  = (rq[0] - rs[0] * rs[0] / n) / (n - 1.f);
        g_meanv[b] = mean * 64.f;
        g_stdv[b]  = sqrtf(var) * 64.f;
    }
}

// out[b] = (TRANSX ? x^T : x) @ [w0(4x64 cols) | w1(4x64 cols)]
template<bool TRANSX>
__global__ void __launch_bounds__(256) gemm_big(const float* __restrict__ x,
                                                const float* __restrict__ w0,
                                                const float* __restrict__ w1) {
    __shared__ float As[8][132];
    __shared__ float Bs[8][132];
    int b  = blockIdx.y;
    int mt = blockIdx.x >> 2, nt = blockIdx.x & 3;
    int m0 = mt * 128, n0 = nt * 128;
    int t  = threadIdx.x;
    const float* xb   = x + (size_t)b * HWHW;
    const float* wsrc = (n0 < 256) ? w0 : w1;
    int nbase = n0 & 255;
    int tx = t & 15, ty = t >> 4;

    float acc[8][8];
    #pragma unroll
    for (int i = 0; i < 8; i++)
        #pragma unroll
        for (int j = 0; j < 8; j++) acc[i][j] = 0.f;

    #pragma unroll
    for (int i = 0; i < 4; i++) {
        int id = t + i * 256;
        if (TRANSX) { int k = id >> 7, m = id & 127; As[k][m] = xb[k * HW + m0 + m]; }
        else        { int m = id >> 3, k = id & 7;   As[k][m] = xb[(m0 + m) * HW + k]; }
        int kB = id >> 7, n = id & 127;
        int ng = nbase + n, dd = ng >> 6, cc = ng & 63;
        Bs[kB][n] = wsrc[dd * (HW * Pp) + kB * Pp + cc];
    }
    __syncthreads();

    float pa[4], pb[4];
    for (int kb = 0; kb < 64; kb++) {
        if (kb < 63) {
            int k0n = (kb + 1) * 8;
            #pragma unroll
            for (int i = 0; i < 4; i++) {
                int id = t + i * 256;
                if (TRANSX) { int k = id >> 7, m = id & 127; pa[i] = xb[(k0n + k) * HW + m0 + m]; }
                else        { int m = id >> 3, k = id & 7;   pa[i] = xb[(m0 + m) * HW + k0n + k]; }
                int kB = id >> 7, n = id & 127;
                int ng = nbase + n, dd = ng >> 6, cc = ng & 63;
                pb[i] = wsrc[dd * (HW * Pp) + (k0n + kB) * Pp + cc];
            }
        }
        #pragma unroll
        for (int kk = 0; kk < 8; kk++) {
            float a[8], bb[8];
            *(float4*)(a)      = *(const float4*)&As[kk][ty * 8];
            *(float4*)(a + 4)  = *(const float4*)&As[kk][ty * 8 + 4];
            *(float4*)(bb)     = *(const float4*)&Bs[kk][tx * 8];
            *(float4*)(bb + 4) = *(const float4*)&Bs[kk][tx * 8 + 4];
            #pragma unroll
            for (int i = 0; i < 8; i++)
                #pragma unroll
                for (int j = 0; j < 8; j++)
                    acc[i][j] = fmaf(a[i], bb[j], acc[i][j]);
        }
        __syncthreads();
        if (kb < 63) {
            #pragma unroll
            for (int i = 0; i < 4; i++) {
                int id = t + i * 256;
                if (TRANSX) { int k = id >> 7, m = id & 127; As[k][m] = pa[i]; }
                else        { int m = id >> 3, k = id & 7;   As[k][m] = pa[i]; }
                int kB = id >> 7, n = id & 127;
                Bs[kB][n] = pb[i];
            }
            __syncthreads();
        }
    }

    float* ob = (TRANSX ? g_C2 : g_A) + (size_t)b * HWHW;
    #pragma unroll
    for (int i = 0; i < 8; i++) {
        int row = m0 + ty * 8 + i;
        *(float4*)&ob[row * HW + n0 + tx * 8]     = make_float4(acc[i][0], acc[i][1], acc[i][2], acc[i][3]);
        *(float4*)&ob[row * HW + n0 + tx * 8 + 4] = make_float4(acc[i][4], acc[i][5], acc[i][6], acc[i][7]);
    }
}

// exp colsums + totals of rel halves (cols 256..511)
__global__ void __launch_bounds__(512) relsum_kernel() {
    int d = blockIdx.x, side = blockIdx.y, b = blockIdx.z;
    const float* src = (side == 0 ? g_A : g_C2) + (size_t)b * HWHW + 256 + d * Pp;
    int t = threadIdx.x, col = t & 63, grp = t >> 6;
    float s = 0.f;
    for (int it = 0; it < 64; it++) {
        int r = grp + it * 8;
        s += expf(src[r * HW + col]);
    }
    __shared__ float red[8][64];
    __shared__ float cs[64];
    red[grp][col] = s; __syncthreads();
    if (t < 64) {
        float c = 0.f;
        #pragma unroll
        for (int g = 0; g < 8; g++) c += red[g][t];
        g_cs[((side * Bsz + b) * ND + d) * 64 + t] = c;
        cs[t] = c;
    }
    __syncthreads();
    if (t == 0) {
        float tot = 0.f;
        for (int i = 0; i < 64; i++) tot += cs[i];
        g_tot[(side * Bsz + b) * ND + d] = tot;
    }
}

// G[side][b][d] = A_o(d)^T @ p_x[d]   (64x64, K=512)
__global__ void __launch_bounds__(256) stage2_kernel(const float* __restrict__ p_xj,
                                                     const float* __restrict__ p_xi) {
    __shared__ float As2[64][68];
    __shared__ float Bs2[64][68];
    int d = blockIdx.x, side = blockIdx.y, b = blockIdx.z;
    const float* src  = (side == 0 ? g_A : g_C2) + (size_t)b * HWHW + d * Pp;
    const float* wsrc = (side == 0 ? p_xj : p_xi) + d * (HW * Pp);
    int t = threadIdx.x;
    int prw = (t >> 4) * 4, qcw = (t & 15) * 4;
    float acc[4][4];
    #pragma unroll
    for (int i = 0; i < 4; i++)
        #pragma unroll
        for (int j = 0; j < 4; j++) acc[i][j] = 0.f;

    for (int k0 = 0; k0 < HW; k0 += 64) {
        #pragma unroll
        for (int i = 0; i < 16; i++) {
            int id = t + i * 256;
            int kk = id >> 6, p = id & 63;
            As2[kk][p] = src[(k0 + kk) * HW + p];
            Bs2[kk][p] = wsrc[(k0 + kk) * Pp + p];
        }
        __syncthreads();
        #pragma unroll 16
        for (int kk = 0; kk < 64; kk++) {
            float4 a4 = *(const float4*)&As2[kk][prw];
            float4 b4 = *(const float4*)&Bs2[kk][qcw];
            acc[0][0] = fmaf(a4.x, b4.x, acc[0][0]); acc[0][1] = fmaf(a4.x, b4.y, acc[0][1]);
            acc[0][2] = fmaf(a4.x, b4.z, acc[0][2]); acc[0][3] = fmaf(a4.x, b4.w, acc[0][3]);
            acc[1][0] = fmaf(a4.y, b4.x, acc[1][0]); acc[1][1] = fmaf(a4.y, b4.y, acc[1][1]);
            acc[1][2] = fmaf(a4.y, b4.z, acc[1][2]); acc[1][3] = fmaf(a4.y, b4.w, acc[1][3]);
            acc[2][0] = fmaf(a4.z, b4.x, acc[2][0]); acc[2][1] = fmaf(a4.z, b4.y, acc[2][1]);
            acc[2][2] = fmaf(a4.z, b4.z, acc[2][2]); acc[2][3] = fmaf(a4.z, b4.w, acc[2][3]);
            acc[3][0] = fmaf(a4.w, b4.x, acc[3][0]); acc[3][1] = fmaf(a4.w, b4.y, acc[3][1]);
            acc[3][2] = fmaf(a4.w, b4.z, acc[3][2]); acc[3][3] = fmaf(a4.w, b4.w, acc[3][3]);
        }
        __syncthreads();
    }
    float* g = g_G + (size_t)((side * Bsz + b) * ND + d) * 4096;
    #pragma unroll
    for (int i = 0; i < 4; i++)
        #pragma unroll
        for (int j = 0; j < 4; j++)
            g[(prw + i) * 64 + qcw + j] = acc[i][j];
}

#define FINAL_SMEM_FLOATS (4096 + 4160 + 4096 + 256 + 256 + 64 + 64 + 64 + 8)

__global__ void __launch_bounds__(256) final_kernel(const float* __restrict__ p_rel_xj,
                                                    const float* __restrict__ p_rel_xi,
                                                    float* __restrict__ out) {
    extern __shared__ float sm[];
    float* sGj  = sm;
    float* sGi  = sGj + 4096;   // 64x65 padded
    float* sWR  = sGi + 4160;
    float* red  = sWR + 4096;
    float* red2 = red + 256;
    float* sfj  = red2 + 256;
    float* sfi  = sfj + 64;
    float* sCS  = sfi + 64;
    float* sTOT = sCS + 64;

    int b = blockIdx.x, t = threadIdx.x;
    float xmean = g_meanv[b], xstd = g_stdv[b];
    float proj[16];
    #pragma unroll
    for (int i = 0; i < 16; i++) proj[i] = 0.f;

    int prw = (t >> 4) * 4, qcw = (t & 15) * 4;
    int col = t & 63, grp = t >> 6;

    for (int d = 0; d < ND; d++) {
        #pragma unroll
        for (int i = 0; i < 16; i++) {
            int id = t + i * 256;
            int p = id >> 6, q = id & 63;
            sGj[p * 64 + q] = g_G[(size_t)((0 * Bsz + b) * ND + d) * 4096 + id];
            sGi[p * 65 + q] = g_G[(size_t)((1 * Bsz + b) * ND + d) * 4096 + id];
        }
        __syncthreads();

        for (int side = 0; side < 2; side++) {
            const float* prel = (side == 0 ? p_rel_xj : p_rel_xi) + d * 4096;
            #pragma unroll
            for (int i = 0; i < 16; i++) sWR[t + i * 256] = prel[t + i * 256];
            __syncthreads();

            const float* G = side ? sGi : sGj;
            int gs = side ? 65 : 64;
            float acc[4][4];
            #pragma unroll
            for (int i = 0; i < 4; i++)
                #pragma unroll
                for (int j = 0; j < 4; j++) acc[i][j] = 0.f;
            #pragma unroll 8
            for (int kk = 0; kk < 64; kk++) {
                float a0 = G[(prw + 0) * gs + kk];
                float a1 = G[(prw + 1) * gs + kk];
                float a2 = G[(prw + 2) * gs + kk];
                float a3 = G[(prw + 3) * gs + kk];
                float4 w4 = *(const float4*)&sWR[kk * 64 + qcw];
                acc[0][0] = fmaf(a0, w4.x, acc[0][0]); acc[0][1] = fmaf(a0, w4.y, acc[0][1]);
                acc[0][2] = fmaf(a0, w4.z, acc[0][2]); acc[0][3] = fmaf(a0, w4.w, acc[0][3]);
                acc[1][0] = fmaf(a1, w4.x, acc[1][0]); acc[1][1] = fmaf(a1, w4.y, acc[1][1]);
                acc[1][2] = fmaf(a1, w4.z, acc[1][2]); acc[1][3] = fmaf(a1, w4.w, acc[1][3]);
                acc[2][0] = fmaf(a2, w4.x, acc[2][0]); acc[2][1] = fmaf(a2, w4.y, acc[2][1]);
                acc[2][2] = fmaf(a2, w4.z, acc[2][2]); acc[2][3] = fmaf(a2, w4.w, acc[2][3]);
                acc[3][0] = fmaf(a3, w4.x, acc[3][0]); acc[3][1] = fmaf(a3, w4.y, acc[3][1]);
                acc[3][2] = fmaf(a3, w4.z, acc[3][2]); acc[3][3] = fmaf(a3, w4.w, acc[3][3]);
            }
            __syncthreads();
            #pragma unroll
            for (int i = 0; i < 4; i++)
                #pragma unroll
                for (int j = 0; j < 4; j++)
                    sWR[(prw + i) * 64 + qcw + j] = expf(acc[i][j]);
            __syncthreads();

            float s = 0.f;
            #pragma unroll
            for (int r = 0; r < 16; r++) s += sWR[(grp * 16 + r) * 64 + col];
            red[t] = s; __syncthreads();
            if (t < 64) sCS[t] = red[t] + red[t + 64] + red[t + 128] + red[t + 192];
            __syncthreads();
            if (t == 0) {
                float tot = 0.f;
                for (int i = 0; i < 64; i++) tot += sCS[i];
                sTOT[0] = tot;
            }
            __syncthreads();
            if (t < 64) {
                float ocs  = g_cs[((side * Bsz + b) * ND + d) * 64 + t];
                float otot = g_tot[(side * Bsz + b) * ND + d];
                float f = sqrtf((ocs * sTOT[0]) / (otot * sCS[t]));
                (side ? sfi : sfj)[t] = f;
            }
            __syncthreads();
        }

        float xb[16]; float s = 0.f, ss = 0.f;
        #pragma unroll
        for (int i = 0; i < 16; i++) {
            int id = t + i * 256;
            int p = id >> 6, q = id & 63;
            float v = sGj[p * 64 + q] * sfj[p] + sGi[q * 65 + p] * sfi[q];
            xb[i] = v; s += v; ss += v * v;
        }
        red[t] = s; red2[t] = ss; __syncthreads();
        for (int off = 128; off > 0; off >>= 1) {
            if (t < off) { red[t] += red[t + off]; red2[t] += red2[t + off]; }
            __syncthreads();
        }
        float n = 4096.f;
        float mean = red[0] / n;
        float var  = (red2[0] - red[0] * red[0] / n) / (n - 1.f);
        float istd = 1.f / (sqrtf(var) + 1e-5f);
        #pragma unroll
        for (int i = 0; i < 16; i++)
            proj[i] += (xb[i] - mean) * istd * xstd + xmean;
        __syncthreads();
    }
    #pragma unroll
    for (int i = 0; i < 16; i++)
        out[(size_t)b * 4096 + t + i * 256] = proj[i];
}

extern "C" void kernel_launch(void* const* d_in, const int* in_sizes, int n_in,
                              void* d_out, int out_size) {
    const float* x        = (const float*)d_in[0];
    const float* o_xj     = (const float*)d_in[1];
    const float* o_xi     = (const float*)d_in[2];
    const float* p_xj     = (const float*)d_in[3];
    const float* p_xi     = (const float*)d_in[4];
    const float* o_rel_xj = (const float*)d_in[5];
    const float* o_rel_xi = (const float*)d_in[6];
    const float* p_rel_xj = (const float*)d_in[7];
    const float* p_rel_xi = (const float*)d_in[8];
    float* out = (float*)d_out;

    cudaFuncSetAttribute(final_kernel, cudaFuncAttributeMaxDynamicSharedMemorySize,
                         FINAL_SMEM_FLOATS * sizeof(float));

    stats_kernel<<<Bsz, 256>>>(x);
    gemm_big<false><<<dim3(16, Bsz), 256>>>(x, o_xj, o_rel_xj);
    gemm_big<true ><<<dim3(16, Bsz), 256>>>(x, o_xi, o_rel_xi);
    relsum_kernel<<<dim3(ND, 2, Bsz), 512>>>();
    stage2_kernel<<<dim3(ND, 2, Bsz), 256>>>(p_xj, p_xi);
    final_kernel<<<Bsz, 256, FINAL_SMEM_FLOATS * sizeof(float)>>>(p_rel_xj, p_rel_xi, out);
}

// round 5
// speedup vs baseline: 2.3185x; 2.3185x over previous
#include <cuda_runtime.h>
#include <cuda_bf16.h>
#include <math.h>
#include <stdint.h>

#define Bsz  128
#define HW   512
#define Pp   64
#define ND   4
#define HWHW 262144

// ---------------- scratch (static device globals) ---------------------------
__device__ float g_A [33554432];   // [128][512][512]  x  @ [o_xj | o_rel_xj]
__device__ float g_C2[33554432];   // [128][512][512]  xT @ [o_xi | o_rel_xi]
__device__ float g_G  [2 * Bsz * ND * Pp * Pp];
__device__ float g_cs [2 * Bsz * ND * Pp];
__device__ float g_tot[2 * Bsz * ND];
__device__ float g_meanv[Bsz];
__device__ float g_stdv [Bsz];

__device__ __nv_bfloat16 g_xh [33554432];  // bf16 hi of x     (row-major)
__device__ __nv_bfloat16 g_xl [33554432];  // bf16 lo of x
__device__ __nv_bfloat16 g_xth[33554432];  // bf16 hi of x^T
__device__ __nv_bfloat16 g_xtl[33554432];  // bf16 lo of x^T
__device__ __nv_bfloat16 g_w1h[262144];    // gemm1 weights, [n][k], hi
__device__ __nv_bfloat16 g_w1l[262144];
__device__ __nv_bfloat16 g_w2h[262144];    // gemm2 weights
__device__ __nv_bfloat16 g_w2l[262144];

// ---------------- helpers (all plain sm_103-legal PTX) -----------------------
__device__ __forceinline__ uint32_t smem_u32(const void* p) {
    uint32_t a;
    asm("{ .reg .u64 t; cvta.to.shared.u64 t, %1; cvt.u32.u64 %0, t; }" : "=r"(a) : "l"(p));
    return a;
}
#define CP_ASYNC16(dst, src) \
    asm volatile("cp.async.cg.shared.global [%0], [%1], 16;" :: "r"(dst), "l"(src))
#define CP_COMMIT() asm volatile("cp.async.commit_group;" ::: "memory")
#define CP_WAIT(n)  asm volatile("cp.async.wait_group %0;" :: "n"(n) : "memory")

__device__ __forceinline__ void ldm_x4(uint32_t* r, uint32_t addr) {
    asm volatile("ldmatrix.sync.aligned.m8n8.x4.shared.b16 {%0,%1,%2,%3}, [%4];"
                 : "=r"(r[0]), "=r"(r[1]), "=r"(r[2]), "=r"(r[3]) : "r"(addr));
}
__device__ __forceinline__ void mma16816(float* c, const uint32_t* a, const uint32_t* b) {
    asm volatile(
        "mma.sync.aligned.m16n8k16.row.col.f32.bf16.bf16.f32 "
        "{%0,%1,%2,%3}, {%4,%5,%6,%7}, {%8,%9}, {%0,%1,%2,%3};"
        : "+f"(c[0]), "+f"(c[1]), "+f"(c[2]), "+f"(c[3])
        : "r"(a[0]), "r"(a[1]), "r"(a[2]), "r"(a[3]), "r"(b[0]), "r"(b[1]));
}
#define SWZ(o) ((o) ^ (((o) >> 3) & 0x70))

// ---------------- prep: weights -> [n][k] bf16 hi/lo ------------------------
__global__ void __launch_bounds__(256) convw_kernel(const float* __restrict__ o_xj,
                                                    const float* __restrict__ o_rel_xj,
                                                    const float* __restrict__ o_xi,
                                                    const float* __restrict__ o_rel_xi) {
    int n = blockIdx.x, side = blockIdx.y, t = threadIdx.x;
    const float* w = (side == 0) ? ((n < 256) ? o_xj : o_rel_xj)
                                 : ((n < 256) ? o_xi : o_rel_xi);
    int nn = n & 255, d = nn >> 6, c = nn & 63;
    __nv_bfloat16* oh = side ? g_w2h : g_w1h;
    __nv_bfloat16* ol = side ? g_w2l : g_w1l;
    #pragma unroll
    for (int i = 0; i < 2; i++) {
        int k = t + i * 256;
        float v = w[d * (HW * Pp) + k * Pp + c];
        __nv_bfloat16 h = __float2bfloat16(v);
        __nv_bfloat16 l = __float2bfloat16(v - __bfloat162float(h));
        oh[n * HW + k] = h;
        ol[n * HW + k] = l;
    }
}

// ---------------- prep: x -> bf16 hi/lo, both orientations ------------------
__global__ void __launch_bounds__(128) convx_kernel(const float* __restrict__ x) {
    __shared__ float tile[32][33];
    int b = blockIdx.z, r0 = blockIdx.y * 32, c0 = blockIdx.x * 32;
    int t = threadIdx.x;
    int tx = t & 15, ty = t >> 4;                  // 16 x 8
    const float* xb = x + (size_t)b * HWHW;
    #pragma unroll
    for (int i = 0; i < 4; i++) {
        int row = ty + i * 8;
        float2 v = *(const float2*)&xb[(r0 + row) * HW + c0 + tx * 2];
        tile[row][tx * 2]     = v.x;
        tile[row][tx * 2 + 1] = v.y;
        __nv_bfloat16 h0 = __float2bfloat16(v.x);
        __nv_bfloat16 h1 = __float2bfloat16(v.y);
        __nv_bfloat16 l0 = __float2bfloat16(v.x - __bfloat162float(h0));
        __nv_bfloat16 l1 = __float2bfloat16(v.y - __bfloat162float(h1));
        size_t o = (size_t)b * HWHW + (size_t)(r0 + row) * HW + c0 + tx * 2;
        *(__nv_bfloat162*)&g_xh[o] = __nv_bfloat162(h0, h1);
        *(__nv_bfloat162*)&g_xl[o] = __nv_bfloat162(l0, l1);
    }
    __syncthreads();
    #pragma unroll
    for (int i = 0; i < 4; i++) {
        int col = ty + i * 8;
        float v0 = tile[tx * 2][col];
        float v1 = tile[tx * 2 + 1][col];
        __nv_bfloat16 h0 = __float2bfloat16(v0);
        __nv_bfloat16 h1 = __float2bfloat16(v1);
        __nv_bfloat16 l0 = __float2bfloat16(v0 - __bfloat162float(h0));
        __nv_bfloat16 l1 = __float2bfloat16(v1 - __bfloat162float(h1));
        size_t o = (size_t)b * HWHW + (size_t)(c0 + col) * HW + r0 + tx * 2;
        *(__nv_bfloat162*)&g_xth[o] = __nv_bfloat162(h0, h1);
        *(__nv_bfloat162*)&g_xtl[o] = __nv_bfloat162(l0, l1);
    }
}

// ---------------- mma.sync GEMM: out[b] = X @ Wcat (3-term bf16 split) ------
// CTA tile 128x128, warps 2(M)x4(N), warp tile 64x32. K chunks of 64, double-
// buffered cp.async. smem per stage: Ah|Al|Bh|Bl, each 128 rows x 128B (SW128).
#define STG_BYTES 65536
#define OFF_AH 0
#define OFF_AL 16384
#define OFF_BH 32768
#define OFF_BL 49152
#define GEMM_DYNSM (2 * STG_BYTES)

__global__ void __launch_bounds__(256) gemm_mma() {
    extern __shared__ __align__(16) unsigned char smp[];
    uint32_t sbase = smem_u32(smp);

    int t = threadIdx.x, lane = t & 31, w = t >> 5;
    int wm = w >> 2, wn = w & 3;                 // warp tile origin (wm*64, wn*32)
    int mt = blockIdx.x >> 2, nt = blockIdx.x & 3;
    int b = blockIdx.y, z = blockIdx.z;
    int m0 = mt * 128, n0 = nt * 128;

    const __nv_bfloat16* xsh = (z ? g_xth : g_xh) + (size_t)b * HWHW;
    const __nv_bfloat16* xsl = (z ? g_xtl : g_xl) + (size_t)b * HWHW;
    const __nv_bfloat16* wsh = z ? g_w2h : g_w1h;
    const __nv_bfloat16* wsl = z ? g_w2l : g_w1l;
    float* outp = (z ? g_C2 : g_A) + (size_t)b * HWHW;

    // cp.async load mapping: 1024 16B-units per tile, 4 per thread
    int lrow = t >> 1;              // 0..127 (2 units per row handled over 4 iters)
    // simpler mapping: unit u = t + i*256: row = u>>3, seg = u&7
    // ldmatrix per-thread address components
    int a_row = (lane & 15);               // + wm*64 + mi*16
    int a_cb  = (lane >> 4) * 16;          // + ks*32
    int b_row = (lane & 7) + ((lane >> 4) & 1) * 8;   // + wn*32 + np*16
    int b_cb  = ((lane >> 3) & 1) * 16;    // + ks*32
    (void)lrow;

    float acc[4][4][4];
    #pragma unroll
    for (int mi = 0; mi < 4; mi++)
        #pragma unroll
        for (int ni = 0; ni < 4; ni++)
            #pragma unroll
            for (int q = 0; q < 4; q++) acc[mi][ni][q] = 0.f;

    // ---- prologue: load chunk 0 into stage 0
    {
        uint32_t tb = sbase;
        #pragma unroll
        for (int i = 0; i < 4; i++) {
            int u = t + i * 256;
            int row = u >> 3, seg = u & 7;
            uint32_t so = SWZ(row * 128 + seg * 16);
            CP_ASYNC16(tb + OFF_AH + so, xsh + (m0 + row) * HW + seg * 8);
            CP_ASYNC16(tb + OFF_AL + so, xsl + (m0 + row) * HW + seg * 8);
            CP_ASYNC16(tb + OFF_BH + so, wsh + (n0 + row) * HW + seg * 8);
            CP_ASYNC16(tb + OFF_BL + so, wsl + (n0 + row) * HW + seg * 8);
        }
        CP_COMMIT();
    }

    #pragma unroll 1
    for (int kt = 0; kt < 8; kt++) {
        if (kt + 1 < 8) {
            uint32_t tb = sbase + ((kt + 1) & 1) * STG_BYTES;
            int k0 = (kt + 1) * 64;
            #pragma unroll
            for (int i = 0; i < 4; i++) {
                int u = t + i * 256;
                int row = u >> 3, seg = u & 7;
                uint32_t so = SWZ(row * 128 + seg * 16);
                CP_ASYNC16(tb + OFF_AH + so, xsh + (m0 + row) * HW + k0 + seg * 8);
                CP_ASYNC16(tb + OFF_AL + so, xsl + (m0 + row) * HW + k0 + seg * 8);
                CP_ASYNC16(tb + OFF_BH + so, wsh + (n0 + row) * HW + k0 + seg * 8);
                CP_ASYNC16(tb + OFF_BL + so, wsl + (n0 + row) * HW + k0 + seg * 8);
            }
            CP_COMMIT();
            CP_WAIT(1);
        } else {
            CP_WAIT(0);
        }
        __syncthreads();

        uint32_t tb = sbase + (kt & 1) * STG_BYTES;
        #pragma unroll
        for (int ks = 0; ks < 4; ks++) {
            uint32_t ah[4][4], al[4][4], bh[4][2], bl[4][2];
            #pragma unroll
            for (int mi = 0; mi < 4; mi++) {
                uint32_t off = SWZ((uint32_t)((wm * 64 + mi * 16 + a_row) * 128 + ks * 32 + a_cb));
                ldm_x4(ah[mi], tb + OFF_AH + off);
                ldm_x4(al[mi], tb + OFF_AL + off);
            }
            #pragma unroll
            for (int np = 0; np < 2; np++) {
                uint32_t off = SWZ((uint32_t)((wn * 32 + np * 16 + b_row) * 128 + ks * 32 + b_cb));
                uint32_t rh[4], rl[4];
                ldm_x4(rh, tb + OFF_BH + off);
                ldm_x4(rl, tb + OFF_BL + off);
                bh[np * 2][0] = rh[0]; bh[np * 2][1] = rh[1];
                bh[np * 2 + 1][0] = rh[2]; bh[np * 2 + 1][1] = rh[3];
                bl[np * 2][0] = rl[0]; bl[np * 2][1] = rl[1];
                bl[np * 2 + 1][0] = rl[2]; bl[np * 2 + 1][1] = rl[3];
            }
            #pragma unroll
            for (int mi = 0; mi < 4; mi++)
                #pragma unroll
                for (int ni = 0; ni < 4; ni++) {
                    mma16816(acc[mi][ni], ah[mi], bh[ni]);
                    mma16816(acc[mi][ni], ah[mi], bl[ni]);
                    mma16816(acc[mi][ni], al[mi], bh[ni]);
                }
        }
        __syncthreads();
    }

    // ---- epilogue: direct coalesced float2 stores
    int g = lane >> 2, tig = lane & 3;
    #pragma unroll
    for (int mi = 0; mi < 4; mi++) {
        int row0 = m0 + wm * 64 + mi * 16 + g;
        #pragma unroll
        for (int ni = 0; ni < 4; ni++) {
            int col = n0 + wn * 32 + ni * 8 + tig * 2;
            *(float2*)&outp[(size_t)row0 * HW + col] =
                make_float2(acc[mi][ni][0], acc[mi][ni][1]);
            *(float2*)&outp[(size_t)(row0 + 8) * HW + col] =
                make_float2(acc[mi][ni][2], acc[mi][ni][3]);
        }
    }
}

// ---------------- per-batch mean/std ----------------------------------------
__global__ void __launch_bounds__(256) stats_kernel(const float* __restrict__ x) {
    int b = blockIdx.x, t = threadIdx.x;
    const float4* xv = reinterpret_cast<const float4*>(x + (size_t)b * HWHW);
    float s = 0.f, ss = 0.f;
    for (int i = t; i < HWHW / 4; i += 256) {
        float4 v = xv[i];
        s  += v.x + v.y + v.z + v.w;
        ss += v.x * v.x + v.y * v.y + v.z * v.z + v.w * v.w;
    }
    __shared__ float rs[256], rq[256];
    rs[t] = s; rq[t] = ss; __syncthreads();
    for (int off = 128; off > 0; off >>= 1) {
        if (t < off) { rs[t] += rs[t + off]; rq[t] += rq[t + off]; }
        __syncthreads();
    }
    if (t == 0) {
        float n = (float)HWHW;
        float mean = rs[0] / n;
        float var  = (rq[0] - rs[0] * rs[0] / n) / (n - 1.f);
        g_meanv[b] = mean * 64.f;
        g_stdv[b]  = sqrtf(var) * 64.f;
    }
}

// ---------------- exp colsums of rel halves ---------------------------------
__global__ void __launch_bounds__(512) relsum_kernel() {
    int d = blockIdx.x, side = blockIdx.y, b = blockIdx.z;
    const float* src = (side == 0 ? g_A : g_C2) + (size_t)b * HWHW + 256 + d * Pp;
    int t = threadIdx.x, col = t & 63, grp = t >> 6;
    float s = 0.f;
    for (int it = 0; it < 64; it++) {
        int r = grp + it * 8;
        s += expf(src[r * HW + col]);
    }
    __shared__ float red[8][64];
    __shared__ float cs[64];
    red[grp][col] = s; __syncthreads();
    if (t < 64) {
        float c = 0.f;
        #pragma unroll
        for (int g = 0; g < 8; g++) c += red[g][t];
        g_cs[((side * Bsz + b) * ND + d) * 64 + t] = c;
        cs[t] = c;
    }
    __syncthreads();
    if (t == 0) {
        float tot = 0.f;
        for (int i = 0; i < 64; i++) tot += cs[i];
        g_tot[(side * Bsz + b) * ND + d] = tot;
    }
}

// ---------------- stage-2: G = A_o^T @ p_x  (64x64, K=512) ------------------
__global__ void __launch_bounds__(256) stage2_kernel(const float* __restrict__ p_xj,
                                                     const float* __restrict__ p_xi) {
    __shared__ float As2[64][68];
    __shared__ float Bs2[64][68];
    int d = blockIdx.x, side = blockIdx.y, b = blockIdx.z;
    const float* src  = (side == 0 ? g_A : g_C2) + (size_t)b * HWHW + d * Pp;
    const float* wsrc = (side == 0 ? p_xj : p_xi) + d * (HW * Pp);
    int t = threadIdx.x;
    int prw = (t >> 4) * 4, qcw = (t & 15) * 4;
    float acc[4][4];
    #pragma unroll
    for (int i = 0; i < 4; i++)
        #pragma unroll
        for (int j = 0; j < 4; j++) acc[i][j] = 0.f;

    for (int k0 = 0; k0 < HW; k0 += 64) {
        #pragma unroll
        for (int i = 0; i < 16; i++) {
            int id = t + i * 256;
            int kk = id >> 6, p = id & 63;
            As2[kk][p] = src[(k0 + kk) * HW + p];
            Bs2[kk][p] = wsrc[(k0 + kk) * Pp + p];
        }
        __syncthreads();
        #pragma unroll 16
        for (int kk = 0; kk < 64; kk++) {
            float4 a4 = *(const float4*)&As2[kk][prw];
            float4 b4 = *(const float4*)&Bs2[kk][qcw];
            acc[0][0] = fmaf(a4.x, b4.x, acc[0][0]); acc[0][1] = fmaf(a4.x, b4.y, acc[0][1]);
            acc[0][2] = fmaf(a4.x, b4.z, acc[0][2]); acc[0][3] = fmaf(a4.x, b4.w, acc[0][3]);
            acc[1][0] = fmaf(a4.y, b4.x, acc[1][0]); acc[1][1] = fmaf(a4.y, b4.y, acc[1][1]);
            acc[1][2] = fmaf(a4.y, b4.z, acc[1][2]); acc[1][3] = fmaf(a4.y, b4.w, acc[1][3]);
            acc[2][0] = fmaf(a4.z, b4.x, acc[2][0]); acc[2][1] = fmaf(a4.z, b4.y, acc[2][1]);
            acc[2][2] = fmaf(a4.z, b4.z, acc[2][2]); acc[2][3] = fmaf(a4.z, b4.w, acc[2][3]);
            acc[3][0] = fmaf(a4.w, b4.x, acc[3][0]); acc[3][1] = fmaf(a4.w, b4.y, acc[3][1]);
            acc[3][2] = fmaf(a4.w, b4.z, acc[3][2]); acc[3][3] = fmaf(a4.w, b4.w, acc[3][3]);
        }
        __syncthreads();
    }
    float* g = g_G + (size_t)((side * Bsz + b) * ND + d) * 4096;
    #pragma unroll
    for (int i = 0; i < 4; i++)
        #pragma unroll
        for (int j = 0; j < 4; j++)
            g[(prw + i) * 64 + qcw + j] = acc[i][j];
}

// ---------------- final ------------------------------------------------------
#define FINAL_SMEM_FLOATS (4096 + 4160 + 4096 + 256 + 256 + 64 + 64 + 64 + 8)

__global__ void __launch_bounds__(256) final_kernel(const float* __restrict__ p_rel_xj,
                                                    const float* __restrict__ p_rel_xi,
                                                    float* __restrict__ out) {
    extern __shared__ float sm[];
    float* sGj  = sm;
    float* sGi  = sGj + 4096;   // 64x65 padded
    float* sWR  = sGi + 4160;
    float* red  = sWR + 4096;
    float* red2 = red + 256;
    float* sfj  = red2 + 256;
    float* sfi  = sfj + 64;
    float* sCS  = sfi + 64;
    float* sTOT = sCS + 64;

    int b = blockIdx.x, t = threadIdx.x;
    float xmean = g_meanv[b], xstd = g_stdv[b];
    float proj[16];
    #pragma unroll
    for (int i = 0; i < 16; i++) proj[i] = 0.f;

    int prw = (t >> 4) * 4, qcw = (t & 15) * 4;
    int col = t & 63, grp = t >> 6;

    for (int d = 0; d < ND; d++) {
        #pragma unroll
        for (int i = 0; i < 16; i++) {
            int id = t + i * 256;
            int p = id >> 6, q = id & 63;
            sGj[p * 64 + q] = g_G[(size_t)((0 * Bsz + b) * ND + d) * 4096 + id];
            sGi[p * 65 + q] = g_G[(size_t)((1 * Bsz + b) * ND + d) * 4096 + id];
        }
        __syncthreads();

        for (int side = 0; side < 2; side++) {
            const float* prel = (side == 0 ? p_rel_xj : p_rel_xi) + d * 4096;
            #pragma unroll
            for (int i = 0; i < 16; i++) sWR[t + i * 256] = prel[t + i * 256];
            __syncthreads();

            const float* G = side ? sGi : sGj;
            int gs = side ? 65 : 64;
            float acc[4][4];
            #pragma unroll
            for (int i = 0; i < 4; i++)
                #pragma unroll
                for (int j = 0; j < 4; j++) acc[i][j] = 0.f;
            #pragma unroll 8
            for (int kk = 0; kk < 64; kk++) {
                float a0 = G[(prw + 0) * gs + kk];
                float a1 = G[(prw + 1) * gs + kk];
                float a2 = G[(prw + 2) * gs + kk];
                float a3 = G[(prw + 3) * gs + kk];
                float4 w4 = *(const float4*)&sWR[kk * 64 + qcw];
                acc[0][0] = fmaf(a0, w4.x, acc[0][0]); acc[0][1] = fmaf(a0, w4.y, acc[0][1]);
                acc[0][2] = fmaf(a0, w4.z, acc[0][2]); acc[0][3] = fmaf(a0, w4.w, acc[0][3]);
                acc[1][0] = fmaf(a1, w4.x, acc[1][0]); acc[1][1] = fmaf(a1, w4.y, acc[1][1]);
                acc[1][2] = fmaf(a1, w4.z, acc[1][2]); acc[1][3] = fmaf(a1, w4.w, acc[1][3]);
                acc[2][0] = fmaf(a2, w4.x, acc[2][0]); acc[2][1] = fmaf(a2, w4.y, acc[2][1]);
                acc[2][2] = fmaf(a2, w4.z, acc[2][2]); acc[2][3] = fmaf(a2, w4.w, acc[2][3]);
                acc[3][0] = fmaf(a3, w4.x, acc[3][0]); acc[3][1] = fmaf(a3, w4.y, acc[3][1]);
                acc[3][2] = fmaf(a3, w4.z, acc[3][2]); acc[3][3] = fmaf(a3, w4.w, acc[3][3]);
            }
            __syncthreads();
            #pragma unroll
            for (int i = 0; i < 4; i++)
                #pragma unroll
                for (int j = 0; j < 4; j++)
                    sWR[(prw + i) * 64 + qcw + j] = expf(acc[i][j]);
            __syncthreads();

            float s = 0.f;
            #pragma unroll
            for (int r = 0; r < 16; r++) s += sWR[(grp * 16 + r) * 64 + col];
            red[t] = s; __syncthreads();
            if (t < 64) sCS[t] = red[t] + red[t + 64] + red[t + 128] + red[t + 192];
            __syncthreads();
            if (t == 0) {
                float tot = 0.f;
                for (int i = 0; i < 64; i++) tot += sCS[i];
                sTOT[0] = tot;
            }
            __syncthreads();
            if (t < 64) {
                float ocs  = g_cs[((side * Bsz + b) * ND + d) * 64 + t];
                float otot = g_tot[(side * Bsz + b) * ND + d];
                float f = sqrtf((ocs * sTOT[0]) / (otot * sCS[t]));
                (side ? sfi : sfj)[t] = f;
            }
            __syncthreads();
        }

        float xb[16]; float s = 0.f, ss = 0.f;
        #pragma unroll
        for (int i = 0; i < 16; i++) {
            int id = t + i * 256;
            int p = id >> 6, q = id & 63;
            float v = sGj[p * 64 + q] * sfj[p] + sGi[q * 65 + p] * sfi[q];
            xb[i] = v; s += v; ss += v * v;
        }
        red[t] = s; red2[t] = ss; __syncthreads();
        for (int off = 128; off > 0; off >>= 1) {
            if (t < off) { red[t] += red[t + off]; red2[t] += red2[t + off]; }
            __syncthreads();
        }
        float n = 4096.f;
        float mean = red[0] / n;
        float var  = (red2[0] - red[0] * red[0] / n) / (n - 1.f);
        float istd = 1.f / (sqrtf(var) + 1e-5f);
        #pragma unroll
        for (int i = 0; i < 16; i++)
            proj[i] += (xb[i] - mean) * istd * xstd + xmean;
        __syncthreads();
    }
    #pragma unroll
    for (int i = 0; i < 16; i++)
        out[(size_t)b * 4096 + t + i * 256] = proj[i];
}

// ---------------- launcher ---------------------------------------------------
extern "C" void kernel_launch(void* const* d_in, const int* in_sizes, int n_in,
                              void* d_out, int out_size) {
    const float* x        = (const float*)d_in[0];
    const float* o_xj     = (const float*)d_in[1];
    const float* o_xi     = (const float*)d_in[2];
    const float* p_xj     = (const float*)d_in[3];
    const float* p_xi     = (const float*)d_in[4];
    const float* o_rel_xj = (const float*)d_in[5];
    const float* o_rel_xi = (const float*)d_in[6];
    const float* p_rel_xj = (const float*)d_in[7];
    const float* p_rel_xi = (const float*)d_in[8];
    float* out = (float*)d_out;

    cudaFuncSetAttribute(final_kernel, cudaFuncAttributeMaxDynamicSharedMemorySize,
                         FINAL_SMEM_FLOATS * sizeof(float));
    cudaFuncSetAttribute(gemm_mma, cudaFuncAttributeMaxDynamicSharedMemorySize,
                         GEMM_DYNSM);

    convw_kernel<<<dim3(512, 2), 256>>>(o_xj, o_rel_xj, o_xi, o_rel_xi);
    convx_kernel<<<dim3(16, 16, Bsz), 128>>>(x);
    stats_kernel<<<Bsz, 256>>>(x);
    gemm_mma<<<dim3(16, Bsz, 2), 256, GEMM_DYNSM>>>();
    relsum_kernel<<<dim3(ND, 2, Bsz), 512>>>();
    stage2_kernel<<<dim3(ND, 2, Bsz), 256>>>(p_xj, p_xi);
    final_kernel<<<Bsz, 256, FINAL_SMEM_FLOATS * sizeof(float)>>>(p_rel_xj, p_rel_xi, out);
}

// round 7
// speedup vs baseline: 2.8521x; 1.2301x over previous
#include <cuda_runtime.h>
#include <cuda_bf16.h>
#include <math.h>
#include <stdint.h>

#define Bsz  128
#define HW   512
#define Pp   64
#define ND   4
#define HWHW 262144

// ---------------- scratch (static device globals) ---------------------------
__device__ float g_G  [2 * Bsz * ND * Pp * Pp];
__device__ float g_cs [2 * Bsz * ND * Pp];
__device__ float g_csp[2 * Bsz * 2 * 4 * 2 * 128];   // [z][b][nt2][mt][wm][128]
__device__ float g_meanv[Bsz];
__device__ float g_stdv [Bsz];

__device__ __nv_bfloat16 g_xh [33554432];  // bf16 hi of x     (row-major)
__device__ __nv_bfloat16 g_xl [33554432];
__device__ __nv_bfloat16 g_xth[33554432];  // bf16 hi of x^T
__device__ __nv_bfloat16 g_xtl[33554432];
__device__ __nv_bfloat16 g_w1h[262144];    // gemm1 weights, [n][k], hi
__device__ __nv_bfloat16 g_w1l[262144];
__device__ __nv_bfloat16 g_w2h[262144];    // gemm2 weights
__device__ __nv_bfloat16 g_w2l[262144];
// o-halves of the two GEMMs, [b][k=512][m=256], bf16 hi/lo
__device__ __nv_bfloat16 g_ojh[33554432 / 2];
__device__ __nv_bfloat16 g_ojl[33554432 / 2];
__device__ __nv_bfloat16 g_oih[33554432 / 2];
__device__ __nv_bfloat16 g_oil[33554432 / 2];
// p weights split, [d][k=512][n=64]
__device__ __nv_bfloat16 g_pjh[131072];
__device__ __nv_bfloat16 g_pjl[131072];
__device__ __nv_bfloat16 g_pih[131072];
__device__ __nv_bfloat16 g_pil[131072];

// ---------------- helpers (plain sm_103-legal PTX) ---------------------------
__device__ __forceinline__ uint32_t smem_u32(const void* p) {
    uint32_t a;
    asm("{ .reg .u64 t; cvta.to.shared.u64 t, %1; cvt.u32.u64 %0, t; }" : "=r"(a) : "l"(p));
    return a;
}
#define CP_ASYNC16(dst, src) \
    asm volatile("cp.async.cg.shared.global [%0], [%1], 16;" :: "r"(dst), "l"(src))
#define CP_COMMIT() asm volatile("cp.async.commit_group;" ::: "memory")
#define CP_WAIT(n)  asm volatile("cp.async.wait_group %0;" :: "n"(n) : "memory")

__device__ __forceinline__ void ldm_x4(uint32_t* r, uint32_t addr) {
    asm volatile("ldmatrix.sync.aligned.m8n8.x4.shared.b16 {%0,%1,%2,%3}, [%4];"
                 : "=r"(r[0]), "=r"(r[1]), "=r"(r[2]), "=r"(r[3]) : "r"(addr));
}
__device__ __forceinline__ void ldm_x4t(uint32_t* r, uint32_t addr) {
    asm volatile("ldmatrix.sync.aligned.m8n8.x4.trans.shared.b16 {%0,%1,%2,%3}, [%4];"
                 : "=r"(r[0]), "=r"(r[1]), "=r"(r[2]), "=r"(r[3]) : "r"(addr));
}
__device__ __forceinline__ void mma16816(float* c, const uint32_t* a, const uint32_t* b) {
    asm volatile(
        "mma.sync.aligned.m16n8k16.row.col.f32.bf16.bf16.f32 "
        "{%0,%1,%2,%3}, {%4,%5,%6,%7}, {%8,%9}, {%0,%1,%2,%3};"
        : "+f"(c[0]), "+f"(c[1]), "+f"(c[2]), "+f"(c[3])
        : "r"(a[0]), "r"(a[1]), "r"(a[2]), "r"(a[3]), "r"(b[0]), "r"(b[1]));
}
#define SWZ(o) ((o) ^ (((o) >> 3) & 0x70))

__device__ __forceinline__ void split2(float v0, float v1,
                                       __nv_bfloat162* h, __nv_bfloat162* l) {
    __nv_bfloat16 h0 = __float2bfloat16(v0), h1 = __float2bfloat16(v1);
    *h = __nv_bfloat162(h0, h1);
    *l = __nv_bfloat162(__float2bfloat16(v0 - __bfloat162float(h0)),
                        __float2bfloat16(v1 - __bfloat162float(h1)));
}

// ---------------- prep: big-GEMM weights -> [n][k] bf16 hi/lo ----------------
__global__ void __launch_bounds__(256) convw_kernel(const float* __restrict__ o_xj,
                                                    const float* __restrict__ o_rel_xj,
                                                    const float* __restrict__ o_xi,
                                                    const float* __restrict__ o_rel_xi) {
    int n = blockIdx.x, side = blockIdx.y, t = threadIdx.x;
    const float* w = (side == 0) ? ((n < 256) ? o_xj : o_rel_xj)
                                 : ((n < 256) ? o_xi : o_rel_xi);
    int nn = n & 255, d = nn >> 6, c = nn & 63;
    __nv_bfloat16* oh = side ? g_w2h : g_w1h;
    __nv_bfloat16* ol = side ? g_w2l : g_w1l;
    #pragma unroll
    for (int i = 0; i < 2; i++) {
        int k = t + i * 256;
        float v = w[d * (HW * Pp) + k * Pp + c];
        __nv_bfloat16 h = __float2bfloat16(v);
        oh[n * HW + k] = h;
        ol[n * HW + k] = __float2bfloat16(v - __bfloat162float(h));
    }
}

// ---------------- prep: p weights -> hi/lo (same [d][k][n] layout) ----------
__global__ void __launch_bounds__(256) convp_kernel(const float* __restrict__ p_xj,
                                                    const float* __restrict__ p_xi) {
    int i = blockIdx.x * 256 + threadIdx.x;     // 0..131071
    int side = blockIdx.y;
    const float* src = side ? p_xi : p_xj;
    __nv_bfloat16* oh = side ? g_pih : g_pjh;
    __nv_bfloat16* ol = side ? g_pil : g_pjl;
    float v = src[i];
    __nv_bfloat16 h = __float2bfloat16(v);
    oh[i] = h;
    ol[i] = __float2bfloat16(v - __bfloat162float(h));
}

// ---------------- prep: x -> bf16 hi/lo, both orientations ------------------
__global__ void __launch_bounds__(128) convx_kernel(const float* __restrict__ x) {
    __shared__ float tile[32][33];
    int b = blockIdx.z, r0 = blockIdx.y * 32, c0 = blockIdx.x * 32;
    int t = threadIdx.x;
    int tx = t & 15, ty = t >> 4;                  // 16 x 8
    const float* xb = x + (size_t)b * HWHW;
    #pragma unroll
    for (int i = 0; i < 4; i++) {
        int row = ty + i * 8;
        float2 v = *(const float2*)&xb[(r0 + row) * HW + c0 + tx * 2];
        tile[row][tx * 2]     = v.x;
        tile[row][tx * 2 + 1] = v.y;
        size_t o = (size_t)b * HWHW + (size_t)(r0 + row) * HW + c0 + tx * 2;
        split2(v.x, v.y, (__nv_bfloat162*)&g_xh[o], (__nv_bfloat162*)&g_xl[o]);
    }
    __syncthreads();
    #pragma unroll
    for (int i = 0; i < 4; i++) {
        int col = ty + i * 8;
        float v0 = tile[tx * 2][col];
        float v1 = tile[tx * 2 + 1][col];
        size_t o = (size_t)b * HWHW + (size_t)(c0 + col) * HW + r0 + tx * 2;
        split2(v0, v1, (__nv_bfloat162*)&g_xth[o], (__nv_bfloat162*)&g_xtl[o]);
    }
}

// ---------------- mma.sync GEMM: X @ Wcat (3-term bf16 split) ----------------
// CTA 128x128, warps 2(M)x4(N), warp tile 64x32, K chunks 64, double buffer.
// Epilogue: nt<2 (o-half) -> bf16 hi/lo [b][k][m]; nt>=2 (rel) -> exp colsum
// partials (deterministic, no fp32 matrix ever written).
#define STG_BYTES 65536
#define OFF_AH 0
#define OFF_AL 16384
#define OFF_BH 32768
#define OFF_BL 49152
#define GEMM_DYNSM (2 * STG_BYTES)

__global__ void __launch_bounds__(256) gemm_mma() {
    extern __shared__ __align__(16) unsigned char smp[];
    uint32_t sbase = smem_u32(smp);

    int t = threadIdx.x, lane = t & 31, w = t >> 5;
    int wm = w >> 2, wn = w & 3;
    int mt = blockIdx.x >> 2, nt = blockIdx.x & 3;
    int b = blockIdx.y, z = blockIdx.z;
    int m0 = mt * 128, n0 = nt * 128;

    const __nv_bfloat16* xsh = (z ? g_xth : g_xh) + (size_t)b * HWHW;
    const __nv_bfloat16* xsl = (z ? g_xtl : g_xl) + (size_t)b * HWHW;
    const __nv_bfloat16* wsh = z ? g_w2h : g_w1h;
    const __nv_bfloat16* wsl = z ? g_w2l : g_w1l;

    int a_row = (lane & 15);
    int a_cb  = (lane >> 4) * 16;
    int b_row = (lane & 7) + ((lane >> 4) & 1) * 8;
    int b_cb  = ((lane >> 3) & 1) * 16;

    float acc[4][4][4];
    #pragma unroll
    for (int mi = 0; mi < 4; mi++)
        #pragma unroll
        for (int ni = 0; ni < 4; ni++)
            #pragma unroll
            for (int q = 0; q < 4; q++) acc[mi][ni][q] = 0.f;

    {
        uint32_t tb = sbase;
        #pragma unroll
        for (int i = 0; i < 4; i++) {
            int u = t + i * 256;
            int row = u >> 3, seg = u & 7;
            uint32_t so = SWZ(row * 128 + seg * 16);
            CP_ASYNC16(tb + OFF_AH + so, xsh + (m0 + row) * HW + seg * 8);
            CP_ASYNC16(tb + OFF_AL + so, xsl + (m0 + row) * HW + seg * 8);
            CP_ASYNC16(tb + OFF_BH + so, wsh + (n0 + row) * HW + seg * 8);
            CP_ASYNC16(tb + OFF_BL + so, wsl + (n0 + row) * HW + seg * 8);
        }
        CP_COMMIT();
    }

    #pragma unroll 1
    for (int kt = 0; kt < 8; kt++) {
        if (kt + 1 < 8) {
            uint32_t tb = sbase + ((kt + 1) & 1) * STG_BYTES;
            int k0 = (kt + 1) * 64;
            #pragma unroll
            for (int i = 0; i < 4; i++) {
                int u = t + i * 256;
                int row = u >> 3, seg = u & 7;
                uint32_t so = SWZ(row * 128 + seg * 16);
                CP_ASYNC16(tb + OFF_AH + so, xsh + (m0 + row) * HW + k0 + seg * 8);
                CP_ASYNC16(tb + OFF_AL + so, xsl + (m0 + row) * HW + k0 + seg * 8);
                CP_ASYNC16(tb + OFF_BH + so, wsh + (n0 + row) * HW + k0 + seg * 8);
                CP_ASYNC16(tb + OFF_BL + so, wsl + (n0 + row) * HW + k0 + seg * 8);
            }
            CP_COMMIT();
            CP_WAIT(1);
        } else {
            CP_WAIT(0);
        }
        __syncthreads();

        uint32_t tb = sbase + (kt & 1) * STG_BYTES;
        #pragma unroll
        for (int ks = 0; ks < 4; ks++) {
            uint32_t ah[4][4], al[4][4], bh[4][2], bl[4][2];
            #pragma unroll
            for (int mi = 0; mi < 4; mi++) {
                uint32_t off = SWZ((uint32_t)((wm * 64 + mi * 16 + a_row) * 128 + ks * 32 + a_cb));
                ldm_x4(ah[mi], tb + OFF_AH + off);
                ldm_x4(al[mi], tb + OFF_AL + off);
            }
            #pragma unroll
            for (int np = 0; np < 2; np++) {
                uint32_t off = SWZ((uint32_t)((wn * 32 + np * 16 + b_row) * 128 + ks * 32 + b_cb));
                uint32_t rh[4], rl[4];
                ldm_x4(rh, tb + OFF_BH + off);
                ldm_x4(rl, tb + OFF_BL + off);
                bh[np * 2][0] = rh[0]; bh[np * 2][1] = rh[1];
                bh[np * 2 + 1][0] = rh[2]; bh[np * 2 + 1][1] = rh[3];
                bl[np * 2][0] = rl[0]; bl[np * 2][1] = rl[1];
                bl[np * 2 + 1][0] = rl[2]; bl[np * 2 + 1][1] = rl[3];
            }
            #pragma unroll
            for (int mi = 0; mi < 4; mi++)
                #pragma unroll
                for (int ni = 0; ni < 4; ni++) {
                    mma16816(acc[mi][ni], ah[mi], bh[ni]);
                    mma16816(acc[mi][ni], ah[mi], bl[ni]);
                    mma16816(acc[mi][ni], al[mi], bh[ni]);
                }
        }
        __syncthreads();
    }

    int gq = lane >> 2, tig = lane & 3;
    if (nt < 2) {
        // o-half: bf16 hi/lo, layout [b][k=row][m=col(0..255)]
        __nv_bfloat16* oh = z ? g_oih : g_ojh;
        __nv_bfloat16* ol = z ? g_oil : g_ojl;
        size_t bb = (size_t)b * (512 * 256);
        #pragma unroll
        for (int mi = 0; mi < 4; mi++) {
            int row0 = m0 + wm * 64 + mi * 16 + gq;
            #pragma unroll
            for (int ni = 0; ni < 4; ni++) {
                int col = nt * 128 + wn * 32 + ni * 8 + tig * 2;
                split2(acc[mi][ni][0], acc[mi][ni][1],
                       (__nv_bfloat162*)&oh[bb + (size_t)row0 * 256 + col],
                       (__nv_bfloat162*)&ol[bb + (size_t)row0 * 256 + col]);
                split2(acc[mi][ni][2], acc[mi][ni][3],
                       (__nv_bfloat162*)&oh[bb + (size_t)(row0 + 8) * 256 + col],
                       (__nv_bfloat162*)&ol[bb + (size_t)(row0 + 8) * 256 + col]);
            }
        }
    } else {
        // rel-half: exp colsum partials (deterministic slots per CTA/warp)
        size_t p = ((((size_t)(z * Bsz + b) * 2 + (nt - 2)) * 4 + mt) * 2 + wm) * 128;
        #pragma unroll
        for (int ni = 0; ni < 4; ni++) {
            float s0 = 0.f, s1 = 0.f;
            #pragma unroll
            for (int mi = 0; mi < 4; mi++) {
                s0 += expf(acc[mi][ni][0]) + expf(acc[mi][ni][2]);
                s1 += expf(acc[mi][ni][1]) + expf(acc[mi][ni][3]);
            }
            #pragma unroll
            for (int o = 4; o < 32; o <<= 1) {
                s0 += __shfl_xor_sync(0xFFFFFFFFu, s0, o);
                s1 += __shfl_xor_sync(0xFFFFFFFFu, s1, o);
            }
            if (gq == 0) {
                int cl = wn * 32 + ni * 8 + tig * 2;
                g_csp[p + cl]     = s0;
                g_csp[p + cl + 1] = s1;
            }
        }
    }
}

// ---------------- fold colsum partials --------------------------------------
__global__ void __launch_bounds__(256) csred_kernel() {
    int i = blockIdx.x * 256 + threadIdx.x;     // 0..65535
    int side = i >> 15;
    int r = i & 32767;
    int b = r >> 8;
    int dc = r & 255;
    int d = dc >> 6, c = dc & 63;
    int nt2 = d >> 1;
    int cl = (d & 1) * 64 + c;
    size_t base = (((size_t)(side * Bsz + b) * 2 + nt2) * 4) * 2 * 128;
    float s = 0.f;
    #pragma unroll
    for (int mtw = 0; mtw < 8; mtw++) s += g_csp[base + (size_t)mtw * 128 + cl];
    g_cs[((side * Bsz + b) * ND + d) * 64 + c] = s;
}

// ---------------- per-batch mean/std ----------------------------------------
__global__ void __launch_bounds__(256) stats_kernel(const float* __restrict__ x) {
    int b = blockIdx.x, t = threadIdx.x;
    const float4* xv = reinterpret_cast<const float4*>(x + (size_t)b * HWHW);
    float s = 0.f, ss = 0.f;
    for (int i = t; i < HWHW / 4; i += 256) {
        float4 v = xv[i];
        s  += v.x + v.y + v.z + v.w;
        ss += v.x * v.x + v.y * v.y + v.z * v.z + v.w * v.w;
    }
    __shared__ float rs[256], rq[256];
    rs[t] = s; rq[t] = ss; __syncthreads();
    for (int off = 128; off > 0; off >>= 1) {
        if (t < off) { rs[t] += rs[t + off]; rq[t] += rq[t + off]; }
        __syncthreads();
    }
    if (t == 0) {
        float n = (float)HWHW;
        float mean = rs[0] / n;
        float var  = (rq[0] - rs[0] * rs[0] / n) / (n - 1.f);
        g_meanv[b] = mean * 64.f;
        g_stdv[b]  = sqrtf(var) * 64.f;
    }
}

// ---------------- stage-2 via mma: G = A_o^T @ p_x  (64x64, K=512) ----------
// A from [k][m] bf16 hi/lo (trans ldmatrix), W from [k][n] (trans ldmatrix).
#define S2_STG 32768
#define S2_AH 0
#define S2_AL 8192
#define S2_WH 16384
#define S2_WL 24576
#define S2_DYNSM (2 * S2_STG)

__global__ void __launch_bounds__(128) stage2_mma() {
    extern __shared__ __align__(16) unsigned char smp2[];
    uint32_t sbase = smem_u32(smp2);

    int t = threadIdx.x, lane = t & 31, wn = t >> 5;   // 4 warps, each 16 N-cols
    int d = blockIdx.x, side = blockIdx.y, b = blockIdx.z;

    const __nv_bfloat16* Ah = (side ? g_oih : g_ojh) + (size_t)b * (512 * 256) + d * 64;
    const __nv_bfloat16* Al = (side ? g_oil : g_ojl) + (size_t)b * (512 * 256) + d * 64;
    const __nv_bfloat16* Wh = (side ? g_pih : g_pjh) + (size_t)d * (512 * 64);
    const __nv_bfloat16* Wl = (side ? g_pil : g_pjl) + (size_t)d * (512 * 64);

    // ldmatrix trans address components
    int a_r = (lane & 7) + ((lane >> 4) & 1) * 8;   // k within 16
    int a_c = ((lane >> 3) & 1) * 16;               // m byte within 32
    int w_r = (lane & 7) + ((lane >> 3) & 1) * 8;   // k within 16
    int w_c = ((lane >> 4) & 1) * 16;               // n byte within 32

    float acc[4][2][4];
    #pragma unroll
    for (int mi = 0; mi < 4; mi++)
        #pragma unroll
        for (int ni = 0; ni < 2; ni++)
            #pragma unroll
            for (int q = 0; q < 4; q++) acc[mi][ni][q] = 0.f;

    {
        uint32_t tb = sbase;
        #pragma unroll
        for (int i = 0; i < 4; i++) {
            int u = t + i * 128;
            int row = u >> 3, seg = u & 7;
            uint32_t so = SWZ(row * 128 + seg * 16);
            CP_ASYNC16(tb + S2_AH + so, Ah + (size_t)row * 256 + seg * 8);
            CP_ASYNC16(tb + S2_AL + so, Al + (size_t)row * 256 + seg * 8);
            CP_ASYNC16(tb + S2_WH + so, Wh + (size_t)row * 64 + seg * 8);
            CP_ASYNC16(tb + S2_WL + so, Wl + (size_t)row * 64 + seg * 8);
        }
        CP_COMMIT();
    }

    #pragma unroll 1
    for (int kt = 0; kt < 8; kt++) {
        if (kt + 1 < 8) {
            uint32_t tb = sbase + ((kt + 1) & 1) * S2_STG;
            int k0 = (kt + 1) * 64;
            #pragma unroll
            for (int i = 0; i < 4; i++) {
                int u = t + i * 128;
                int row = u >> 3, seg = u & 7;
                uint32_t so = SWZ(row * 128 + seg * 16);
                CP_ASYNC16(tb + S2_AH + so, Ah + (size_t)(k0 + row) * 256 + seg * 8);
                CP_ASYNC16(tb + S2_AL + so, Al + (size_t)(k0 + row) * 256 + seg * 8);
                CP_ASYNC16(tb + S2_WH + so, Wh + (size_t)(k0 + row) * 64 + seg * 8);
                CP_ASYNC16(tb + S2_WL + so, Wl + (size_t)(k0 + row) * 64 + seg * 8);
            }
            CP_COMMIT();
            CP_WAIT(1);
        } else {
            CP_WAIT(0);
        }
        __syncthreads();

        uint32_t tb = sbase + (kt & 1) * S2_STG;
        #pragma unroll
        for (int ks = 0; ks < 4; ks++) {
            uint32_t ah[4][4], al[4][4], wh[2][2], wl[2][2];
            #pragma unroll
            for (int mi = 0; mi < 4; mi++) {
                uint32_t off = SWZ((uint32_t)((ks * 16 + a_r) * 128 + mi * 32 + a_c));
                ldm_x4t(ah[mi], tb + S2_AH + off);
                ldm_x4t(al[mi], tb + S2_AL + off);
            }
            {
                uint32_t off = SWZ((uint32_t)((ks * 16 + w_r) * 128 + wn * 32 + w_c));
                uint32_t rh[4], rl[4];
                ldm_x4t(rh, tb + S2_WH + off);
                ldm_x4t(rl, tb + S2_WL + off);
                wh[0][0] = rh[0]; wh[0][1] = rh[1]; wh[1][0] = rh[2]; wh[1][1] = rh[3];
                wl[0][0] = rl[0]; wl[0][1] = rl[1]; wl[1][0] = rl[2]; wl[1][1] = rl[3];
            }
            #pragma unroll
            for (int mi = 0; mi < 4; mi++)
                #pragma unroll
                for (int ni = 0; ni < 2; ni++) {
                    mma16816(acc[mi][ni], ah[mi], wh[ni]);
                    mma16816(acc[mi][ni], ah[mi], wl[ni]);
                    mma16816(acc[mi][ni], al[mi], wh[ni]);
                }
        }
        __syncthreads();
    }

    float* g = g_G + (size_t)((side * Bsz + b) * ND + d) * 4096;
    int gq = lane >> 2, tig = lane & 3;
    #pragma unroll
    for (int mi = 0; mi < 4; mi++) {
        int m = mi * 16 + gq;
        #pragma unroll
        for (int ni = 0; ni < 2; ni++) {
            int n = wn * 16 + ni * 8 + tig * 2;
            *(float2*)&g[m * 64 + n]       = make_float2(acc[mi][ni][0], acc[mi][ni][1]);
            *(float2*)&g[(m + 8) * 64 + n] = make_float2(acc[mi][ni][2], acc[mi][ni][3]);
        }
    }
}

// ---------------- final ------------------------------------------------------
#define FINAL_SMEM_FLOATS (4096 + 4160 + 4096 + 256 + 256 + 64 + 64 + 64 + 64 + 16)

__global__ void __launch_bounds__(256) final_kernel2(const float* __restrict__ p_rel_xj,
                                                     const float* __restrict__ p_rel_xi,
                                                     float* __restrict__ out) {
    extern __shared__ float sm[];
    float* sGj  = sm;
    float* sGi  = sGj + 4096;   // 64x65 padded
    float* sWR  = sGi + 4160;
    float* red  = sWR + 4096;
    float* red2 = red + 256;
    float* sfj  = red2 + 256;
    float* sfi  = sfj + 64;
    float* sCS  = sfi + 64;
    float* sOCS = sCS + 64;
    float* sTOT = sOCS + 64;    // [0]=p total, [1]=o total

    int b = blockIdx.x, t = threadIdx.x;
    float xmean = g_meanv[b], xstd = g_stdv[b];
    float proj[16];
    #pragma unroll
    for (int i = 0; i < 16; i++) proj[i] = 0.f;

    int prw = (t >> 4) * 4, qcw = (t & 15) * 4;
    int col = t & 63, grp = t >> 6;

    for (int d = 0; d < ND; d++) {
        #pragma unroll
        for (int i = 0; i < 16; i++) {
            int id = t + i * 256;
            int p = id >> 6, q = id & 63;
            sGj[p * 64 + q] = g_G[(size_t)((0 * Bsz + b) * ND + d) * 4096 + id];
            sGi[p * 65 + q] = g_G[(size_t)((1 * Bsz + b) * ND + d) * 4096 + id];
        }
        __syncthreads();

        for (int side = 0; side < 2; side++) {
            const float* prel = (side == 0 ? p_rel_xj : p_rel_xi) + d * 4096;
            #pragma unroll
            for (int i = 0; i < 16; i++) sWR[t + i * 256] = prel[t + i * 256];
            if (t < 64) sOCS[t] = g_cs[((side * Bsz + b) * ND + d) * 64 + t];
            __syncthreads();

            const float* G = side ? sGi : sGj;
            int gs = side ? 65 : 64;
            float acc[4][4];
            #pragma unroll
            for (int i = 0; i < 4; i++)
                #pragma unroll
                for (int j = 0; j < 4; j++) acc[i][j] = 0.f;
            #pragma unroll 8
            for (int kk = 0; kk < 64; kk++) {
                float a0 = G[(prw + 0) * gs + kk];
                float a1 = G[(prw + 1) * gs + kk];
                float a2 = G[(prw + 2) * gs + kk];
                float a3 = G[(prw + 3) * gs + kk];
                float4 w4 = *(const float4*)&sWR[kk * 64 + qcw];
                acc[0][0] = fmaf(a0, w4.x, acc[0][0]); acc[0][1] = fmaf(a0, w4.y, acc[0][1]);
                acc[0][2] = fmaf(a0, w4.z, acc[0][2]); acc[0][3] = fmaf(a0, w4.w, acc[0][3]);
                acc[1][0] = fmaf(a1, w4.x, acc[1][0]); acc[1][1] = fmaf(a1, w4.y, acc[1][1]);
                acc[1][2] = fmaf(a1, w4.z, acc[1][2]); acc[1][3] = fmaf(a1, w4.w, acc[1][3]);
                acc[2][0] = fmaf(a2, w4.x, acc[2][0]); acc[2][1] = fmaf(a2, w4.y, acc[2][1]);
                acc[2][2] = fmaf(a2, w4.z, acc[2][2]); acc[2][3] = fmaf(a2, w4.w, acc[2][3]);
                acc[3][0] = fmaf(a3, w4.x, acc[3][0]); acc[3][1] = fmaf(a3, w4.y, acc[3][1]);
                acc[3][2] = fmaf(a3, w4.z, acc[3][2]); acc[3][3] = fmaf(a3, w4.w, acc[3][3]);
            }
            __syncthreads();
            #pragma unroll
            for (int i = 0; i < 4; i++)
                #pragma unroll
                for (int j = 0; j < 4; j++)
                    sWR[(prw + i) * 64 + qcw + j] = expf(acc[i][j]);
            __syncthreads();

            float s = 0.f;
            #pragma unroll
            for (int r = 0; r < 16; r++) s += sWR[(grp * 16 + r) * 64 + col];
            red[t] = s; __syncthreads();
            if (t < 64) sCS[t] = red[t] + red[t + 64] + red[t + 128] + red[t + 192];
            __syncthreads();
            if (t == 0) {
                float tp = 0.f, to = 0.f;
                for (int i = 0; i < 64; i++) { tp += sCS[i]; to += sOCS[i]; }
                sTOT[0] = tp; sTOT[1] = to;
            }
            __syncthreads();
            if (t < 64) {
                float f = sqrtf((sOCS[t] * sTOT[0]) / (sTOT[1] * sCS[t]));
                (side ? sfi : sfj)[t] = f;
            }
            __syncthreads();
        }

        float xb[16]; float s = 0.f, ss = 0.f;
        #pragma unroll
        for (int i = 0; i < 16; i++) {
            int id = t + i * 256;
            int p = id >> 6, q = id & 63;
            float v = sGj[p * 64 + q] * sfj[p] + sGi[q * 65 + p] * sfi[q];
            xb[i] = v; s += v; ss += v * v;
        }
        red[t] = s; red2[t] = ss; __syncthreads();
        for (int off = 128; off > 0; off >>= 1) {
            if (t < off) { red[t] += red[t + off]; red2[t] += red2[t + off]; }
            __syncthreads();
        }
        float n = 4096.f;
        float mean = red[0] / n;
        float var  = (red2[0] - red[0] * red[0] / n) / (n - 1.f);
        float istd = 1.f / (sqrtf(var) + 1e-5f);
        #pragma unroll
        for (int i = 0; i < 16; i++)
            proj[i] += (xb[i] - mean) * istd * xstd + xmean;
        __syncthreads();
    }
    #pragma unroll
    for (int i = 0; i < 16; i++)
        out[(size_t)b * 4096 + t + i * 256] = proj[i];
}

// ---------------- launcher ---------------------------------------------------
extern "C" void kernel_launch(void* const* d_in, const int* in_sizes, int n_in,
                              void* d_out, int out_size) {
    const float* x        = (const float*)d_in[0];
    const float* o_xj     = (const float*)d_in[1];
    const float* o_xi     = (const float*)d_in[2];
    const float* p_xj     = (const float*)d_in[3];
    const float* p_xi     = (const float*)d_in[4];
    const float* o_rel_xj = (const float*)d_in[5];
    const float* o_rel_xi = (const float*)d_in[6];
    const float* p_rel_xj = (const float*)d_in[7];
    const float* p_rel_xi = (const float*)d_in[8];
    float* out = (float*)d_out;

    cudaFuncSetAttribute(final_kernel2, cudaFuncAttributeMaxDynamicSharedMemorySize,
                         FINAL_SMEM_FLOATS * sizeof(float));
    cudaFuncSetAttribute(gemm_mma, cudaFuncAttributeMaxDynamicSharedMemorySize,
                         GEMM_DYNSM);
    cudaFuncSetAttribute(stage2_mma, cudaFuncAttributeMaxDynamicSharedMemorySize,
                         S2_DYNSM);

    convw_kernel<<<dim3(512, 2), 256>>>(o_xj, o_rel_xj, o_xi, o_rel_xi);
    convp_kernel<<<dim3(512, 2), 256>>>(p_xj, p_xi);
    convx_kernel<<<dim3(16, 16, Bsz), 128>>>(x);
    stats_kernel<<<Bsz, 256>>>(x);
    gemm_mma<<<dim3(16, Bsz, 2), 256, GEMM_DYNSM>>>();
    csred_kernel<<<256, 256>>>();
    stage2_mma<<<dim3(ND, 2, Bsz), 128, S2_DYNSM>>>();
    final_kernel2<<<Bsz, 256, FINAL_SMEM_FLOATS * sizeof(float)>>>(p_rel_xj, p_rel_xi, out);
}

// round 8
// speedup vs baseline: 2.9005x; 1.0170x over previous
#include <cuda_runtime.h>
#include <cuda_bf16.h>
#include <math.h>
#include <stdint.h>

#define Bsz  128
#define HW   512
#define Pp   64
#define ND   4
#define HWHW 262144

// ---------------- scratch (static device globals) ---------------------------
__device__ float g_G  [2 * Bsz * ND * Pp * Pp];
__device__ float g_cs [2 * Bsz * ND * Pp];
__device__ float g_csp[2 * Bsz * 2 * 4 * 2 * 128];   // [z][b][nt2][mt][wm][128]
__device__ float2 g_statp[Bsz * 256];                // per-tile (sum, sumsq)
__device__ float g_meanv[Bsz];
__device__ float g_stdv [Bsz];

__device__ __nv_bfloat16 g_xh [33554432];  // bf16 hi of x     (row-major)
__device__ __nv_bfloat16 g_xl [33554432];
__device__ __nv_bfloat16 g_xth[33554432];  // bf16 hi of x^T
__device__ __nv_bfloat16 g_xtl[33554432];
__device__ __nv_bfloat16 g_w1h[262144];    // gemm1 weights, [n][k], hi
__device__ __nv_bfloat16 g_w1l[262144];
__device__ __nv_bfloat16 g_w2h[262144];    // gemm2 weights
__device__ __nv_bfloat16 g_w2l[262144];
// o-halves of the two GEMMs, [b][k=512][m=256], bf16 hi/lo
__device__ __nv_bfloat16 g_ojh[33554432 / 2];
__device__ __nv_bfloat16 g_ojl[33554432 / 2];
__device__ __nv_bfloat16 g_oih[33554432 / 2];
__device__ __nv_bfloat16 g_oil[33554432 / 2];
// p weights split, [d][k=512][n=64]
__device__ __nv_bfloat16 g_pjh[131072];
__device__ __nv_bfloat16 g_pjl[131072];
__device__ __nv_bfloat16 g_pih[131072];
__device__ __nv_bfloat16 g_pil[131072];

// ---------------- helpers (plain sm_103-legal PTX) ---------------------------
__device__ __forceinline__ uint32_t smem_u32(const void* p) {
    uint32_t a;
    asm("{ .reg .u64 t; cvta.to.shared.u64 t, %1; cvt.u32.u64 %0, t; }" : "=r"(a) : "l"(p));
    return a;
}
#define CP_ASYNC16(dst, src) \
    asm volatile("cp.async.cg.shared.global [%0], [%1], 16;" :: "r"(dst), "l"(src))
#define CP_COMMIT() asm volatile("cp.async.commit_group;" ::: "memory")
#define CP_WAIT(n)  asm volatile("cp.async.wait_group %0;" :: "n"(n) : "memory")

__device__ __forceinline__ void ldm_x4(uint32_t* r, uint32_t addr) {
    asm volatile("ldmatrix.sync.aligned.m8n8.x4.shared.b16 {%0,%1,%2,%3}, [%4];"
                 : "=r"(r[0]), "=r"(r[1]), "=r"(r[2]), "=r"(r[3]) : "r"(addr));
}
__device__ __forceinline__ void ldm_x4t(uint32_t* r, uint32_t addr) {
    asm volatile("ldmatrix.sync.aligned.m8n8.x4.trans.shared.b16 {%0,%1,%2,%3}, [%4];"
                 : "=r"(r[0]), "=r"(r[1]), "=r"(r[2]), "=r"(r[3]) : "r"(addr));
}
__device__ __forceinline__ void mma16816(float* c, const uint32_t* a, const uint32_t* b) {
    asm volatile(
        "mma.sync.aligned.m16n8k16.row.col.f32.bf16.bf16.f32 "
        "{%0,%1,%2,%3}, {%4,%5,%6,%7}, {%8,%9}, {%0,%1,%2,%3};"
        : "+f"(c[0]), "+f"(c[1]), "+f"(c[2]), "+f"(c[3])
        : "r"(a[0]), "r"(a[1]), "r"(a[2]), "r"(a[3]), "r"(b[0]), "r"(b[1]));
}
#define SWZ(o) ((o) ^ (((o) >> 3) & 0x70))

__device__ __forceinline__ void split2(float v0, float v1,
                                       __nv_bfloat162* h, __nv_bfloat162* l) {
    __nv_bfloat16 h0 = __float2bfloat16(v0), h1 = __float2bfloat16(v1);
    *h = __nv_bfloat162(h0, h1);
    *l = __nv_bfloat162(__float2bfloat16(v0 - __bfloat162float(h0)),
                        __float2bfloat16(v1 - __bfloat162float(h1)));
}

// ---------------- prep: big-GEMM weights -> [n][k] bf16 hi/lo ----------------
__global__ void __launch_bounds__(256) convw_kernel(const float* __restrict__ o_xj,
                                                    const float* __restrict__ o_rel_xj,
                                                    const float* __restrict__ o_xi,
                                                    const float* __restrict__ o_rel_xi) {
    int n = blockIdx.x, side = blockIdx.y, t = threadIdx.x;
    const float* w = (side == 0) ? ((n < 256) ? o_xj : o_rel_xj)
                                 : ((n < 256) ? o_xi : o_rel_xi);
    int nn = n & 255, d = nn >> 6, c = nn & 63;
    __nv_bfloat16* oh = side ? g_w2h : g_w1h;
    __nv_bfloat16* ol = side ? g_w2l : g_w1l;
    #pragma unroll
    for (int i = 0; i < 2; i++) {
        int k = t + i * 256;
        float v = w[d * (HW * Pp) + k * Pp + c];
        __nv_bfloat16 h = __float2bfloat16(v);
        oh[n * HW + k] = h;
        ol[n * HW + k] = __float2bfloat16(v - __bfloat162float(h));
    }
}

// ---------------- prep: p weights -> hi/lo (same [d][k][n] layout) ----------
__global__ void __launch_bounds__(256) convp_kernel(const float* __restrict__ p_xj,
                                                    const float* __restrict__ p_xi) {
    int i = blockIdx.x * 256 + threadIdx.x;     // 0..131071
    int side = blockIdx.y;
    const float* src = side ? p_xi : p_xj;
    __nv_bfloat16* oh = side ? g_pih : g_pjh;
    __nv_bfloat16* ol = side ? g_pil : g_pjl;
    float v = src[i];
    __nv_bfloat16 h = __float2bfloat16(v);
    oh[i] = h;
    ol[i] = __float2bfloat16(v - __bfloat162float(h));
}

// ---------------- prep: x -> bf16 hi/lo both orientations + stat partials ---
__global__ void __launch_bounds__(128) convx_kernel(const float* __restrict__ x) {
    __shared__ float tile[32][33];
    __shared__ float rs[128], rq[128];
    int b = blockIdx.z, r0 = blockIdx.y * 32, c0 = blockIdx.x * 32;
    int t = threadIdx.x;
    int tx = t & 15, ty = t >> 4;                  // 16 x 8
    const float* xb = x + (size_t)b * HWHW;
    float ps = 0.f, pq = 0.f;
    #pragma unroll
    for (int i = 0; i < 4; i++) {
        int row = ty + i * 8;
        float2 v = *(const float2*)&xb[(r0 + row) * HW + c0 + tx * 2];
        tile[row][tx * 2]     = v.x;
        tile[row][tx * 2 + 1] = v.y;
        ps += v.x + v.y;
        pq += v.x * v.x + v.y * v.y;
        size_t o = (size_t)b * HWHW + (size_t)(r0 + row) * HW + c0 + tx * 2;
        split2(v.x, v.y, (__nv_bfloat162*)&g_xh[o], (__nv_bfloat162*)&g_xl[o]);
    }
    rs[t] = ps; rq[t] = pq;
    __syncthreads();
    #pragma unroll
    for (int i = 0; i < 4; i++) {
        int col = ty + i * 8;
        float v0 = tile[tx * 2][col];
        float v1 = tile[tx * 2 + 1][col];
        size_t o = (size_t)b * HWHW + (size_t)(c0 + col) * HW + r0 + tx * 2;
        split2(v0, v1, (__nv_bfloat162*)&g_xth[o], (__nv_bfloat162*)&g_xtl[o]);
    }
    // block reduce partials
    for (int off = 64; off > 0; off >>= 1) {
        __syncthreads();
        if (t < off) { rs[t] += rs[t + off]; rq[t] += rq[t + off]; }
    }
    if (t == 0)
        g_statp[b * 256 + blockIdx.y * 16 + blockIdx.x] = make_float2(rs[0], rq[0]);
}

// ---------------- stats: fold per-tile partials -----------------------------
__global__ void __launch_bounds__(256) stats_reduce() {
    __shared__ float rs[256], rq[256];
    int b = blockIdx.x, t = threadIdx.x;
    float2 p = g_statp[b * 256 + t];
    rs[t] = p.x; rq[t] = p.y;
    for (int off = 128; off > 0; off >>= 1) {
        __syncthreads();
        if (t < off) { rs[t] += rs[t + off]; rq[t] += rq[t + off]; }
    }
    if (t == 0) {
        float n = (float)HWHW;
        float mean = rs[0] / n;
        float var  = (rq[0] - rs[0] * rs[0] / n) / (n - 1.f);
        g_meanv[b] = mean * 64.f;
        g_stdv[b]  = sqrtf(var) * 64.f;
    }
}

// ---------------- mma.sync GEMM: X @ Wcat (3-term bf16 split) ----------------
// CTA 128x128, warps 2(M)x4(N), warp tile 64x32, K chunks 64, 3-stage pipeline.
#define STG_BYTES 65536
#define NSTG 3
#define OFF_AH 0
#define OFF_AL 16384
#define OFF_BH 32768
#define OFF_BL 49152
#define GEMM_DYNSM (NSTG * STG_BYTES)

__global__ void __launch_bounds__(256) gemm_mma() {
    extern __shared__ __align__(16) unsigned char smp[];
    uint32_t sbase = smem_u32(smp);

    int t = threadIdx.x, lane = t & 31, w = t >> 5;
    int wm = w >> 2, wn = w & 3;
    int mt = blockIdx.x >> 2, nt = blockIdx.x & 3;
    int b = blockIdx.y, z = blockIdx.z;
    int m0 = mt * 128, n0 = nt * 128;

    const __nv_bfloat16* xsh = (z ? g_xth : g_xh) + (size_t)b * HWHW;
    const __nv_bfloat16* xsl = (z ? g_xtl : g_xl) + (size_t)b * HWHW;
    const __nv_bfloat16* wsh = z ? g_w2h : g_w1h;
    const __nv_bfloat16* wsl = z ? g_w2l : g_w1l;

    int a_row = (lane & 15);
    int a_cb  = (lane >> 4) * 16;
    int b_row = (lane & 7) + ((lane >> 4) & 1) * 8;
    int b_cb  = ((lane >> 3) & 1) * 16;

    int ld_row = t >> 1;                 // unused helper removed
    (void)ld_row;

    float acc[4][4][4];
    #pragma unroll
    for (int mi = 0; mi < 4; mi++)
        #pragma unroll
        for (int ni = 0; ni < 4; ni++)
            #pragma unroll
            for (int q = 0; q < 4; q++) acc[mi][ni][q] = 0.f;

    // prologue: issue chunks 0 and 1
    #pragma unroll
    for (int c = 0; c < 2; c++) {
        uint32_t tb = sbase + c * STG_BYTES;
        int k0 = c * 64;
        #pragma unroll
        for (int i = 0; i < 4; i++) {
            int u = t + i * 256;
            int row = u >> 3, seg = u & 7;
            uint32_t so = SWZ(row * 128 + seg * 16);
            CP_ASYNC16(tb + OFF_AH + so, xsh + (m0 + row) * HW + k0 + seg * 8);
            CP_ASYNC16(tb + OFF_AL + so, xsl + (m0 + row) * HW + k0 + seg * 8);
            CP_ASYNC16(tb + OFF_BH + so, wsh + (n0 + row) * HW + k0 + seg * 8);
            CP_ASYNC16(tb + OFF_BL + so, wsl + (n0 + row) * HW + k0 + seg * 8);
        }
        CP_COMMIT();
    }

    #pragma unroll 1
    for (int kt = 0; kt < 8; kt++) {
        if (kt + 2 < 8) {
            uint32_t tb = sbase + ((kt + 2) % NSTG) * STG_BYTES;
            int k0 = (kt + 2) * 64;
            #pragma unroll
            for (int i = 0; i < 4; i++) {
                int u = t + i * 256;
                int row = u >> 3, seg = u & 7;
                uint32_t so = SWZ(row * 128 + seg * 16);
                CP_ASYNC16(tb + OFF_AH + so, xsh + (m0 + row) * HW + k0 + seg * 8);
                CP_ASYNC16(tb + OFF_AL + so, xsl + (m0 + row) * HW + k0 + seg * 8);
                CP_ASYNC16(tb + OFF_BH + so, wsh + (n0 + row) * HW + k0 + seg * 8);
                CP_ASYNC16(tb + OFF_BL + so, wsl + (n0 + row) * HW + k0 + seg * 8);
            }
            CP_COMMIT();
            CP_WAIT(2);
        } else if (kt == 6) {
            CP_WAIT(1);
        } else {
            CP_WAIT(0);
        }
        __syncthreads();

        uint32_t tb = sbase + (kt % NSTG) * STG_BYTES;
        #pragma unroll
        for (int ks = 0; ks < 4; ks++) {
            uint32_t ah[4][4], al[4][4], bh[4][2], bl[4][2];
            #pragma unroll
            for (int mi = 0; mi < 4; mi++) {
                uint32_t off = SWZ((uint32_t)((wm * 64 + mi * 16 + a_row) * 128 + ks * 32 + a_cb));
                ldm_x4(ah[mi], tb + OFF_AH + off);
                ldm_x4(al[mi], tb + OFF_AL + off);
            }
            #pragma unroll
            for (int np = 0; np < 2; np++) {
                uint32_t off = SWZ((uint32_t)((wn * 32 + np * 16 + b_row) * 128 + ks * 32 + b_cb));
                uint32_t rh[4], rl[4];
                ldm_x4(rh, tb + OFF_BH + off);
                ldm_x4(rl, tb + OFF_BL + off);
                bh[np * 2][0] = rh[0]; bh[np * 2][1] = rh[1];
                bh[np * 2 + 1][0] = rh[2]; bh[np * 2 + 1][1] = rh[3];
                bl[np * 2][0] = rl[0]; bl[np * 2][1] = rl[1];
                bl[np * 2 + 1][0] = rl[2]; bl[np * 2 + 1][1] = rl[3];
            }
            #pragma unroll
            for (int mi = 0; mi < 4; mi++)
                #pragma unroll
                for (int ni = 0; ni < 4; ni++) {
                    mma16816(acc[mi][ni], ah[mi], bh[ni]);
                    mma16816(acc[mi][ni], ah[mi], bl[ni]);
                    mma16816(acc[mi][ni], al[mi], bh[ni]);
                }
        }
        __syncthreads();
    }

    int gq = lane >> 2, tig = lane & 3;
    if (nt < 2) {
        // o-half: bf16 hi/lo, layout [b][k=row][m=col(0..255)]
        __nv_bfloat16* oh = z ? g_oih : g_ojh;
        __nv_bfloat16* ol = z ? g_oil : g_ojl;
        size_t bb = (size_t)b * (512 * 256);
        #pragma unroll
        for (int mi = 0; mi < 4; mi++) {
            int row0 = m0 + wm * 64 + mi * 16 + gq;
            #pragma unroll
            for (int ni = 0; ni < 4; ni++) {
                int col = nt * 128 + wn * 32 + ni * 8 + tig * 2;
                split2(acc[mi][ni][0], acc[mi][ni][1],
                       (__nv_bfloat162*)&oh[bb + (size_t)row0 * 256 + col],
                       (__nv_bfloat162*)&ol[bb + (size_t)row0 * 256 + col]);
                split2(acc[mi][ni][2], acc[mi][ni][3],
                       (__nv_bfloat162*)&oh[bb + (size_t)(row0 + 8) * 256 + col],
                       (__nv_bfloat162*)&ol[bb + (size_t)(row0 + 8) * 256 + col]);
            }
        }
    } else {
        // rel-half: exp colsum partials (deterministic slots per CTA/warp)
        size_t p = ((((size_t)(z * Bsz + b) * 2 + (nt - 2)) * 4 + mt) * 2 + wm) * 128;
        #pragma unroll
        for (int ni = 0; ni < 4; ni++) {
            float s0 = 0.f, s1 = 0.f;
            #pragma unroll
            for (int mi = 0; mi < 4; mi++) {
                s0 += expf(acc[mi][ni][0]) + expf(acc[mi][ni][2]);
                s1 += expf(acc[mi][ni][1]) + expf(acc[mi][ni][3]);
            }
            #pragma unroll
            for (int o = 4; o < 32; o <<= 1) {
                s0 += __shfl_xor_sync(0xFFFFFFFFu, s0, o);
                s1 += __shfl_xor_sync(0xFFFFFFFFu, s1, o);
            }
            if (gq == 0) {
                int cl = wn * 32 + ni * 8 + tig * 2;
                g_csp[p + cl]     = s0;
                g_csp[p + cl + 1] = s1;
            }
        }
    }
}

// ---------------- fold colsum partials --------------------------------------
__global__ void __launch_bounds__(256) csred_kernel() {
    int i = blockIdx.x * 256 + threadIdx.x;     // 0..65535
    int side = i >> 15;
    int r = i & 32767;
    int b = r >> 8;
    int dc = r & 255;
    int d = dc >> 6, c = dc & 63;
    int nt2 = d >> 1;
    int cl = (d & 1) * 64 + c;
    size_t base = (((size_t)(side * Bsz + b) * 2 + nt2) * 4) * 2 * 128;
    float s = 0.f;
    #pragma unroll
    for (int mtw = 0; mtw < 8; mtw++) s += g_csp[base + (size_t)mtw * 128 + cl];
    g_cs[((side * Bsz + b) * ND + d) * 64 + c] = s;
}

// ---------------- stage-2 via mma: G = A_o^T @ p_x  (64x64, K=512) ----------
#define S2_STG 32768
#define S2_AH 0
#define S2_AL 8192
#define S2_WH 16384
#define S2_WL 24576
#define S2_DYNSM (2 * S2_STG)

__global__ void __launch_bounds__(128) stage2_mma() {
    extern __shared__ __align__(16) unsigned char smp2[];
    uint32_t sbase = smem_u32(smp2);

    int t = threadIdx.x, lane = t & 31, wn = t >> 5;   // 4 warps, each 16 N-cols
    int d = blockIdx.x, side = blockIdx.y, b = blockIdx.z;

    const __nv_bfloat16* Ah = (side ? g_oih : g_ojh) + (size_t)b * (512 * 256) + d * 64;
    const __nv_bfloat16* Al = (side ? g_oil : g_ojl) + (size_t)b * (512 * 256) + d * 64;
    const __nv_bfloat16* Wh = (side ? g_pih : g_pjh) + (size_t)d * (512 * 64);
    const __nv_bfloat16* Wl = (side ? g_pil : g_pjl) + (size_t)d * (512 * 64);

    int a_r = (lane & 7) + ((lane >> 4) & 1) * 8;
    int a_c = ((lane >> 3) & 1) * 16;
    int w_r = (lane & 7) + ((lane >> 3) & 1) * 8;
    int w_c = ((lane >> 4) & 1) * 16;

    float acc[4][2][4];
    #pragma unroll
    for (int mi = 0; mi < 4; mi++)
        #pragma unroll
        for (int ni = 0; ni < 2; ni++)
            #pragma unroll
            for (int q = 0; q < 4; q++) acc[mi][ni][q] = 0.f;

    {
        uint32_t tb = sbase;
        #pragma unroll
        for (int i = 0; i < 4; i++) {
            int u = t + i * 128;
            int row = u >> 3, seg = u & 7;
            uint32_t so = SWZ(row * 128 + seg * 16);
            CP_ASYNC16(tb + S2_AH + so, Ah + (size_t)row * 256 + seg * 8);
            CP_ASYNC16(tb + S2_AL + so, Al + (size_t)row * 256 + seg * 8);
            CP_ASYNC16(tb + S2_WH + so, Wh + (size_t)row * 64 + seg * 8);
            CP_ASYNC16(tb + S2_WL + so, Wl + (size_t)row * 64 + seg * 8);
        }
        CP_COMMIT();
    }

    #pragma unroll 1
    for (int kt = 0; kt < 8; kt++) {
        if (kt + 1 < 8) {
            uint32_t tb = sbase + ((kt + 1) & 1) * S2_STG;
            int k0 = (kt + 1) * 64;
            #pragma unroll
            for (int i = 0; i < 4; i++) {
                int u = t + i * 128;
                int row = u >> 3, seg = u & 7;
                uint32_t so = SWZ(row * 128 + seg * 16);
                CP_ASYNC16(tb + S2_AH + so, Ah + (size_t)(k0 + row) * 256 + seg * 8);
                CP_ASYNC16(tb + S2_AL + so, Al + (size_t)(k0 + row) * 256 + seg * 8);
                CP_ASYNC16(tb + S2_WH + so, Wh + (size_t)(k0 + row) * 64 + seg * 8);
                CP_ASYNC16(tb + S2_WL + so, Wl + (size_t)(k0 + row) * 64 + seg * 8);
            }
            CP_COMMIT();
            CP_WAIT(1);
        } else {
            CP_WAIT(0);
        }
        __syncthreads();

        uint32_t tb = sbase + (kt & 1) * S2_STG;
        #pragma unroll
        for (int ks = 0; ks < 4; ks++) {
            uint32_t ah[4][4], al[4][4], wh[2][2], wl[2][2];
            #pragma unroll
            for (int mi = 0; mi < 4; mi++) {
                uint32_t off = SWZ((uint32_t)((ks * 16 + a_r) * 128 + mi * 32 + a_c));
                ldm_x4t(ah[mi], tb + S2_AH + off);
                ldm_x4t(al[mi], tb + S2_AL + off);
            }
            {
                uint32_t off = SWZ((uint32_t)((ks * 16 + w_r) * 128 + wn * 32 + w_c));
                uint32_t rh[4], rl[4];
                ldm_x4t(rh, tb + S2_WH + off);
                ldm_x4t(rl, tb + S2_WL + off);
                wh[0][0] = rh[0]; wh[0][1] = rh[1]; wh[1][0] = rh[2]; wh[1][1] = rh[3];
                wl[0][0] = rl[0]; wl[0][1] = rl[1]; wl[1][0] = rl[2]; wl[1][1] = rl[3];
            }
            #pragma unroll
            for (int mi = 0; mi < 4; mi++)
                #pragma unroll
                for (int ni = 0; ni < 2; ni++) {
                    mma16816(acc[mi][ni], ah[mi], wh[ni]);
                    mma16816(acc[mi][ni], ah[mi], wl[ni]);
                    mma16816(acc[mi][ni], al[mi], wh[ni]);
                }
        }
        __syncthreads();
    }

    float* g = g_G + (size_t)((side * Bsz + b) * ND + d) * 4096;
    int gq = lane >> 2, tig = lane & 3;
    #pragma unroll
    for (int mi = 0; mi < 4; mi++) {
        int m = mi * 16 + gq;
        #pragma unroll
        for (int ni = 0; ni < 2; ni++) {
            int n = wn * 16 + ni * 8 + tig * 2;
            *(float2*)&g[m * 64 + n]       = make_float2(acc[mi][ni][0], acc[mi][ni][1]);
            *(float2*)&g[(m + 8) * 64 + n] = make_float2(acc[mi][ni][2], acc[mi][ni][3]);
        }
    }
}

// ---------------- final ------------------------------------------------------
#define FINAL_SMEM_FLOATS (4096 + 4160 + 4096 + 256 + 256 + 64 + 64 + 64 + 64 + 16)

__global__ void __launch_bounds__(256) final_kernel2(const float* __restrict__ p_rel_xj,
                                                     const float* __restrict__ p_rel_xi,
                                                     float* __restrict__ out) {
    extern __shared__ float sm[];
    float* sGj  = sm;
    float* sGi  = sGj + 4096;   // 64x65 padded
    float* sWR  = sGi + 4160;
    float* red  = sWR + 4096;
    float* red2 = red + 256;
    float* sfj  = red2 + 256;
    float* sfi  = sfj + 64;
    float* sCS  = sfi + 64;
    float* sOCS = sCS + 64;
    float* sTOT = sOCS + 64;    // [0]=p total, [1]=o total

    int b = blockIdx.x, t = threadIdx.x;
    float xmean = g_meanv[b], xstd = g_stdv[b];
    float proj[16];
    #pragma unroll
    for (int i = 0; i < 16; i++) proj[i] = 0.f;

    int prw = (t >> 4) * 4, qcw = (t & 15) * 4;
    int col = t & 63, grp = t >> 6;

    for (int d = 0; d < ND; d++) {
        #pragma unroll
        for (int i = 0; i < 16; i++) {
            int id = t + i * 256;
            int p = id >> 6, q = id & 63;
            sGj[p * 64 + q] = g_G[(size_t)((0 * Bsz + b) * ND + d) * 4096 + id];
            sGi[p * 65 + q] = g_G[(size_t)((1 * Bsz + b) * ND + d) * 4096 + id];
        }
        __syncthreads();

        for (int side = 0; side < 2; side++) {
            const float* prel = (side == 0 ? p_rel_xj : p_rel_xi) + d * 4096;
            #pragma unroll
            for (int i = 0; i < 16; i++) sWR[t + i * 256] = prel[t + i * 256];
            if (t < 64) sOCS[t] = g_cs[((side * Bsz + b) * ND + d) * 64 + t];
            __syncthreads();

            const float* G = side ? sGi : sGj;
            int gs = side ? 65 : 64;
            float acc[4][4];
            #pragma unroll
            for (int i = 0; i < 4; i++)
                #pragma unroll
                for (int j = 0; j < 4; j++) acc[i][j] = 0.f;
            #pragma unroll 8
            for (int kk = 0; kk < 64; kk++) {
                float a0 = G[(prw + 0) * gs + kk];
                float a1 = G[(prw + 1) * gs + kk];
                float a2 = G[(prw + 2) * gs + kk];
                float a3 = G[(prw + 3) * gs + kk];
                float4 w4 = *(const float4*)&sWR[kk * 64 + qcw];
                acc[0][0] = fmaf(a0, w4.x, acc[0][0]); acc[0][1] = fmaf(a0, w4.y, acc[0][1]);
                acc[0][2] = fmaf(a0, w4.z, acc[0][2]); acc[0][3] = fmaf(a0, w4.w, acc[0][3]);
                acc[1][0] = fmaf(a1, w4.x, acc[1][0]); acc[1][1] = fmaf(a1, w4.y, acc[1][1]);
                acc[1][2] = fmaf(a1, w4.z, acc[1][2]); acc[1][3] = fmaf(a1, w4.w, acc[1][3]);
                acc[2][0] = fmaf(a2, w4.x, acc[2][0]); acc[2][1] = fmaf(a2, w4.y, acc[2][1]);
                acc[2][2] = fmaf(a2, w4.z, acc[2][2]); acc[2][3] = fmaf(a2, w4.w, acc[2][3]);
                acc[3][0] = fmaf(a3, w4.x, acc[3][0]); acc[3][1] = fmaf(a3, w4.y, acc[3][1]);
                acc[3][2] = fmaf(a3, w4.z, acc[3][2]); acc[3][3] = fmaf(a3, w4.w, acc[3][3]);
            }
            __syncthreads();
            #pragma unroll
            for (int i = 0; i < 4; i++)
                #pragma unroll
                for (int j = 0; j < 4; j++)
                    sWR[(prw + i) * 64 + qcw + j] = expf(acc[i][j]);
            __syncthreads();

            float s = 0.f;
            #pragma unroll
            for (int r = 0; r < 16; r++) s += sWR[(grp * 16 + r) * 64 + col];
            red[t] = s; __syncthreads();
            if (t < 64) sCS[t] = red[t] + red[t + 64] + red[t + 128] + red[t + 192];
            __syncthreads();
            if (t == 0) {
                float tp = 0.f, to = 0.f;
                for (int i = 0; i < 64; i++) { tp += sCS[i]; to += sOCS[i]; }
                sTOT[0] = tp; sTOT[1] = to;
            }
            __syncthreads();
            if (t < 64) {
                float f = sqrtf((sOCS[t] * sTOT[0]) / (sTOT[1] * sCS[t]));
                (side ? sfi : sfj)[t] = f;
            }
            __syncthreads();
        }

        float xb[16]; float s = 0.f, ss = 0.f;
        #pragma unroll
        for (int i = 0; i < 16; i++) {
            int id = t + i * 256;
            int p = id >> 6, q = id & 63;
            float v = sGj[p * 64 + q] * sfj[p] + sGi[q * 65 + p] * sfi[q];
            xb[i] = v; s += v; ss += v * v;
        }
        red[t] = s; red2[t] = ss; __syncthreads();
        for (int off = 128; off > 0; off >>= 1) {
            if (t < off) { red[t] += red[t + off]; red2[t] += red2[t + off]; }
            __syncthreads();
        }
        float n = 4096.f;
        float mean = red[0] / n;
        float var  = (red2[0] - red[0] * red[0] / n) / (n - 1.f);
        float istd = 1.f / (sqrtf(var) + 1e-5f);
        #pragma unroll
        for (int i = 0; i < 16; i++)
            proj[i] += (xb[i] - mean) * istd * xstd + xmean;
        __syncthreads();
    }
    #pragma unroll
    for (int i = 0; i < 16; i++)
        out[(size_t)b * 4096 + t + i * 256] = proj[i];
}

// ---------------- launcher ---------------------------------------------------
extern "C" void kernel_launch(void* const* d_in, const int* in_sizes, int n_in,
                              void* d_out, int out_size) {
    const float* x        = (const float*)d_in[0];
    const float* o_xj     = (const float*)d_in[1];
    const float* o_xi     = (const float*)d_in[2];
    const float* p_xj     = (const float*)d_in[3];
    const float* p_xi     = (const float*)d_in[4];
    const float* o_rel_xj = (const float*)d_in[5];
    const float* o_rel_xi = (const float*)d_in[6];
    const float* p_rel_xj = (const float*)d_in[7];
    const float* p_rel_xi = (const float*)d_in[8];
    float* out = (float*)d_out;

    cudaFuncSetAttribute(final_kernel2, cudaFuncAttributeMaxDynamicSharedMemorySize,
                         FINAL_SMEM_FLOATS * sizeof(float));
    cudaFuncSetAttribute(gemm_mma, cudaFuncAttributeMaxDynamicSharedMemorySize,
                         GEMM_DYNSM);
    cudaFuncSetAttribute(stage2_mma, cudaFuncAttributeMaxDynamicSharedMemorySize,
                         S2_DYNSM);

    convw_kernel<<<dim3(512, 2), 256>>>(o_xj, o_rel_xj, o_xi, o_rel_xi);
    convp_kernel<<<dim3(512, 2), 256>>>(p_xj, p_xi);
    convx_kernel<<<dim3(16, 16, Bsz), 128>>>(x);
    stats_reduce<<<Bsz, 256>>>();
    gemm_mma<<<dim3(16, Bsz, 2), 256, GEMM_DYNSM>>>();
    csred_kernel<<<256, 256>>>();
    stage2_mma<<<dim3(ND, 2, Bsz), 128, S2_DYNSM>>>();
    final_kernel2<<<Bsz, 256, FINAL_SMEM_FLOATS * sizeof(float)>>>(p_rel_xj, p_rel_xi, out);
}

// round 9
// speedup vs baseline: 6.5727x; 2.2661x over previous
#include <cuda_runtime.h>
#include <cuda_fp16.h>
#include <math.h>
#include <stdint.h>

#define Bsz  128
#define HW   512
#define Pp   64
#define ND   4
#define HWHW 262144

// ---------------- scratch (static device globals) ---------------------------
__device__ float g_G  [2 * Bsz * ND * Pp * Pp];
__device__ float g_cs [2 * Bsz * ND * Pp];
__device__ float g_csp[2 * Bsz * 2 * 4 * 2 * 128];   // [z][b][nt2][mt][wm][128]
__device__ float2 g_statp[Bsz * 256];                // per-tile (sum, sumsq)
__device__ float g_meanv[Bsz];
__device__ float g_stdv [Bsz];

__device__ __half g_xf [33554432];   // fp16 x   (row-major)
__device__ __half g_xtf[33554432];   // fp16 x^T
__device__ __half g_w1f[262144];     // gemm1 weights, [n][k]
__device__ __half g_w2f[262144];     // gemm2 weights
// o-halves of the two GEMMs, [b][k=512][m=256], fp16
__device__ __half g_ojf[16777216];
__device__ __half g_oif[16777216];
// p weights, [d][k=512][n=64], fp16
__device__ __half g_pjf[131072];
__device__ __half g_pif[131072];

// ---------------- helpers (plain sm_103-legal PTX) ---------------------------
__device__ __forceinline__ uint32_t smem_u32(const void* p) {
    uint32_t a;
    asm("{ .reg .u64 t; cvta.to.shared.u64 t, %1; cvt.u32.u64 %0, t; }" : "=r"(a) : "l"(p));
    return a;
}
#define CP_ASYNC16(dst, src) \
    asm volatile("cp.async.cg.shared.global [%0], [%1], 16;" :: "r"(dst), "l"(src))
#define CP_COMMIT() asm volatile("cp.async.commit_group;" ::: "memory")
#define CP_WAIT(n)  asm volatile("cp.async.wait_group %0;" :: "n"(n) : "memory")

__device__ __forceinline__ void ldm_x4(uint32_t* r, uint32_t addr) {
    asm volatile("ldmatrix.sync.aligned.m8n8.x4.shared.b16 {%0,%1,%2,%3}, [%4];"
                 : "=r"(r[0]), "=r"(r[1]), "=r"(r[2]), "=r"(r[3]) : "r"(addr));
}
__device__ __forceinline__ void ldm_x4t(uint32_t* r, uint32_t addr) {
    asm volatile("ldmatrix.sync.aligned.m8n8.x4.trans.shared.b16 {%0,%1,%2,%3}, [%4];"
                 : "=r"(r[0]), "=r"(r[1]), "=r"(r[2]), "=r"(r[3]) : "r"(addr));
}
__device__ __forceinline__ void mma16816f(float* c, const uint32_t* a, const uint32_t* b) {
    asm volatile(
        "mma.sync.aligned.m16n8k16.row.col.f32.f16.f16.f32 "
        "{%0,%1,%2,%3}, {%4,%5,%6,%7}, {%8,%9}, {%0,%1,%2,%3};"
        : "+f"(c[0]), "+f"(c[1]), "+f"(c[2]), "+f"(c[3])
        : "r"(a[0]), "r"(a[1]), "r"(a[2]), "r"(a[3]), "r"(b[0]), "r"(b[1]));
}
#define SWZ(o) ((o) ^ (((o) >> 3) & 0x70))

// ---------------- prep: big-GEMM weights -> [n][k] fp16 ----------------------
__global__ void __launch_bounds__(256) convw_kernel(const float* __restrict__ o_xj,
                                                    const float* __restrict__ o_rel_xj,
                                                    const float* __restrict__ o_xi,
                                                    const float* __restrict__ o_rel_xi) {
    int n = blockIdx.x, side = blockIdx.y, t = threadIdx.x;
    const float* w = (side == 0) ? ((n < 256) ? o_xj : o_rel_xj)
                                 : ((n < 256) ? o_xi : o_rel_xi);
    int nn = n & 255, d = nn >> 6, c = nn & 63;
    __half* of = side ? g_w2f : g_w1f;
    #pragma unroll
    for (int i = 0; i < 2; i++) {
        int k = t + i * 256;
        of[n * HW + k] = __float2half_rn(w[d * (HW * Pp) + k * Pp + c]);
    }
}

// ---------------- prep: p weights -> fp16 ([d][k][n] layout) -----------------
__global__ void __launch_bounds__(256) convp_kernel(const float* __restrict__ p_xj,
                                                    const float* __restrict__ p_xi) {
    int i = blockIdx.x * 256 + threadIdx.x;     // 0..131071
    int side = blockIdx.y;
    const float* src = side ? p_xi : p_xj;
    __half* of = side ? g_pif : g_pjf;
    of[i] = __float2half_rn(src[i]);
}

// ---------------- prep: x -> fp16 both orientations + stat partials ----------
__global__ void __launch_bounds__(128) convx_kernel(const float* __restrict__ x) {
    __shared__ float tile[32][33];
    __shared__ float rs[128], rq[128];
    int b = blockIdx.z, r0 = blockIdx.y * 32, c0 = blockIdx.x * 32;
    int t = threadIdx.x;
    int tx = t & 15, ty = t >> 4;                  // 16 x 8
    const float* xb = x + (size_t)b * HWHW;
    float ps = 0.f, pq = 0.f;
    #pragma unroll
    for (int i = 0; i < 4; i++) {
        int row = ty + i * 8;
        float2 v = *(const float2*)&xb[(r0 + row) * HW + c0 + tx * 2];
        tile[row][tx * 2]     = v.x;
        tile[row][tx * 2 + 1] = v.y;
        ps += v.x + v.y;
        pq += v.x * v.x + v.y * v.y;
        size_t o = (size_t)b * HWHW + (size_t)(r0 + row) * HW + c0 + tx * 2;
        *(__half2*)&g_xf[o] = __floats2half2_rn(v.x, v.y);
    }
    rs[t] = ps; rq[t] = pq;
    __syncthreads();
    #pragma unroll
    for (int i = 0; i < 4; i++) {
        int col = ty + i * 8;
        float v0 = tile[tx * 2][col];
        float v1 = tile[tx * 2 + 1][col];
        size_t o = (size_t)b * HWHW + (size_t)(c0 + col) * HW + r0 + tx * 2;
        *(__half2*)&g_xtf[o] = __floats2half2_rn(v0, v1);
    }
    for (int off = 64; off > 0; off >>= 1) {
        __syncthreads();
        if (t < off) { rs[t] += rs[t + off]; rq[t] += rq[t + off]; }
    }
    if (t == 0)
        g_statp[b * 256 + blockIdx.y * 16 + blockIdx.x] = make_float2(rs[0], rq[0]);
}

// ---------------- stats: fold per-tile partials ------------------------------
__global__ void __launch_bounds__(256) stats_reduce() {
    __shared__ float rs[256], rq[256];
    int b = blockIdx.x, t = threadIdx.x;
    float2 p = g_statp[b * 256 + t];
    rs[t] = p.x; rq[t] = p.y;
    for (int off = 128; off > 0; off >>= 1) {
        __syncthreads();
        if (t < off) { rs[t] += rs[t + off]; rq[t] += rq[t + off]; }
    }
    if (t == 0) {
        float n = (float)HWHW;
        float mean = rs[0] / n;
        float var  = (rq[0] - rs[0] * rs[0] / n) / (n - 1.f);
        g_meanv[b] = mean * 64.f;
        g_stdv[b]  = sqrtf(var) * 64.f;
    }
}

// ---------------- mma.sync GEMM: X @ Wcat (single-pass fp16) -----------------
// CTA 128x128, warps 2(M)x4(N), warp tile 64x32, K chunks 64, 3-stage pipeline.
#define STG_BYTES 32768
#define NSTG 3
#define OFF_A 0
#define OFF_B 16384
#define GEMM_DYNSM (NSTG * STG_BYTES)

__global__ void __launch_bounds__(256, 2) gemm_mma() {
    extern __shared__ __align__(16) unsigned char smp[];
    uint32_t sbase = smem_u32(smp);

    int t = threadIdx.x, lane = t & 31, w = t >> 5;
    int wm = w >> 2, wn = w & 3;
    int mt = blockIdx.x >> 2, nt = blockIdx.x & 3;
    int b = blockIdx.y, z = blockIdx.z;
    int m0 = mt * 128, n0 = nt * 128;

    const __half* xs = (z ? g_xtf : g_xf) + (size_t)b * HWHW;
    const __half* ws = z ? g_w2f : g_w1f;

    int a_row = (lane & 15);
    int a_cb  = (lane >> 4) * 16;
    int b_row = (lane & 7) + ((lane >> 4) & 1) * 8;
    int b_cb  = ((lane >> 3) & 1) * 16;

    float acc[4][4][4];
    #pragma unroll
    for (int mi = 0; mi < 4; mi++)
        #pragma unroll
        for (int ni = 0; ni < 4; ni++)
            #pragma unroll
            for (int q = 0; q < 4; q++) acc[mi][ni][q] = 0.f;

    // prologue: issue chunks 0 and 1
    #pragma unroll
    for (int c = 0; c < 2; c++) {
        uint32_t tb = sbase + c * STG_BYTES;
        int k0 = c * 64;
        #pragma unroll
        for (int i = 0; i < 4; i++) {
            int u = t + i * 256;
            int row = u >> 3, seg = u & 7;
            uint32_t so = SWZ(row * 128 + seg * 16);
            CP_ASYNC16(tb + OFF_A + so, xs + (m0 + row) * HW + k0 + seg * 8);
            CP_ASYNC16(tb + OFF_B + so, ws + (n0 + row) * HW + k0 + seg * 8);
        }
        CP_COMMIT();
    }

    #pragma unroll 1
    for (int kt = 0; kt < 8; kt++) {
        if (kt + 2 < 8) {
            uint32_t tb = sbase + ((kt + 2) % NSTG) * STG_BYTES;
            int k0 = (kt + 2) * 64;
            #pragma unroll
            for (int i = 0; i < 4; i++) {
                int u = t + i * 256;
                int row = u >> 3, seg = u & 7;
                uint32_t so = SWZ(row * 128 + seg * 16);
                CP_ASYNC16(tb + OFF_A + so, xs + (m0 + row) * HW + k0 + seg * 8);
                CP_ASYNC16(tb + OFF_B + so, ws + (n0 + row) * HW + k0 + seg * 8);
            }
            CP_COMMIT();
            CP_WAIT(2);
        } else if (kt == 6) {
            CP_WAIT(1);
        } else {
            CP_WAIT(0);
        }
        __syncthreads();

        uint32_t tb = sbase + (kt % NSTG) * STG_BYTES;
        #pragma unroll
        for (int ks = 0; ks < 4; ks++) {
            uint32_t ah[4][4], bh[4][2];
            #pragma unroll
            for (int mi = 0; mi < 4; mi++) {
                uint32_t off = SWZ((uint32_t)((wm * 64 + mi * 16 + a_row) * 128 + ks * 32 + a_cb));
                ldm_x4(ah[mi], tb + OFF_A + off);
            }
            #pragma unroll
            for (int np = 0; np < 2; np++) {
                uint32_t off = SWZ((uint32_t)((wn * 32 + np * 16 + b_row) * 128 + ks * 32 + b_cb));
                uint32_t rh[4];
                ldm_x4(rh, tb + OFF_B + off);
                bh[np * 2][0] = rh[0]; bh[np * 2][1] = rh[1];
                bh[np * 2 + 1][0] = rh[2]; bh[np * 2 + 1][1] = rh[3];
            }
            #pragma unroll
            for (int mi = 0; mi < 4; mi++)
                #pragma unroll
                for (int ni = 0; ni < 4; ni++)
                    mma16816f(acc[mi][ni], ah[mi], bh[ni]);
        }
        __syncthreads();
    }

    int gq = lane >> 2, tig = lane & 3;
    if (nt < 2) {
        // o-half: fp16, layout [b][k=row][m=col(0..255)]
        __half* of = z ? g_oif : g_ojf;
        size_t bb = (size_t)b * (512 * 256);
        #pragma unroll
        for (int mi = 0; mi < 4; mi++) {
            int row0 = m0 + wm * 64 + mi * 16 + gq;
            #pragma unroll
            for (int ni = 0; ni < 4; ni++) {
                int col = nt * 128 + wn * 32 + ni * 8 + tig * 2;
                *(__half2*)&of[bb + (size_t)row0 * 256 + col] =
                    __floats2half2_rn(acc[mi][ni][0], acc[mi][ni][1]);
                *(__half2*)&of[bb + (size_t)(row0 + 8) * 256 + col] =
                    __floats2half2_rn(acc[mi][ni][2], acc[mi][ni][3]);
            }
        }
    } else {
        // rel-half: exp colsum partials (deterministic slots per CTA/warp)
        size_t p = ((((size_t)(z * Bsz + b) * 2 + (nt - 2)) * 4 + mt) * 2 + wm) * 128;
        #pragma unroll
        for (int ni = 0; ni < 4; ni++) {
            float s0 = 0.f, s1 = 0.f;
            #pragma unroll
            for (int mi = 0; mi < 4; mi++) {
                s0 += expf(acc[mi][ni][0]) + expf(acc[mi][ni][2]);
                s1 += expf(acc[mi][ni][1]) + expf(acc[mi][ni][3]);
            }
            #pragma unroll
            for (int o = 4; o < 32; o <<= 1) {
                s0 += __shfl_xor_sync(0xFFFFFFFFu, s0, o);
                s1 += __shfl_xor_sync(0xFFFFFFFFu, s1, o);
            }
            if (gq == 0) {
                int cl = wn * 32 + ni * 8 + tig * 2;
                g_csp[p + cl]     = s0;
                g_csp[p + cl + 1] = s1;
            }
        }
    }
}

// ---------------- fold colsum partials ---------------------------------------
__global__ void __launch_bounds__(256) csred_kernel() {
    int i = blockIdx.x * 256 + threadIdx.x;     // 0..65535
    int side = i >> 15;
    int r = i & 32767;
    int b = r >> 8;
    int dc = r & 255;
    int d = dc >> 6, c = dc & 63;
    int nt2 = d >> 1;
    int cl = (d & 1) * 64 + c;
    size_t base = (((size_t)(side * Bsz + b) * 2 + nt2) * 4) * 2 * 128;
    float s = 0.f;
    #pragma unroll
    for (int mtw = 0; mtw < 8; mtw++) s += g_csp[base + (size_t)mtw * 128 + cl];
    g_cs[((side * Bsz + b) * ND + d) * 64 + c] = s;
}

// ---------------- stage-2 via mma: G = A_o^T @ p_x  (64x64, K=512) -----------
#define S2_STG 16384
#define S2_A 0
#define S2_W 8192
#define S2_DYNSM (2 * S2_STG)

__global__ void __launch_bounds__(128) stage2_mma() {
    extern __shared__ __align__(16) unsigned char smp2[];
    uint32_t sbase = smem_u32(smp2);

    int t = threadIdx.x, lane = t & 31, wn = t >> 5;   // 4 warps, each 16 N-cols
    int d = blockIdx.x, side = blockIdx.y, b = blockIdx.z;

    const __half* A = (side ? g_oif : g_ojf) + (size_t)b * (512 * 256) + d * 64;
    const __half* W = (side ? g_pif : g_pjf) + (size_t)d * (512 * 64);

    int a_r = (lane & 7) + ((lane >> 4) & 1) * 8;   // k within 16
    int a_c = ((lane >> 3) & 1) * 16;               // m byte within 32
    int w_r = (lane & 7) + ((lane >> 3) & 1) * 8;   // k within 16
    int w_c = ((lane >> 4) & 1) * 16;               // n byte within 32

    float acc[4][2][4];
    #pragma unroll
    for (int mi = 0; mi < 4; mi++)
        #pragma unroll
        for (int ni = 0; ni < 2; ni++)
            #pragma unroll
            for (int q = 0; q < 4; q++) acc[mi][ni][q] = 0.f;

    {
        uint32_t tb = sbase;
        #pragma unroll
        for (int i = 0; i < 2; i++) {
            int u = t + i * 128;
            int row = u >> 1, seg = u & 1;   // 512 units? no: A chunk 64rowsx128B = 512 units
            (void)row; (void)seg;
        }
        // A chunk: 64 rows x 128B = 512 16B-units; W chunk same. 128 thr x 4 units each.
        #pragma unroll
        for (int i = 0; i < 4; i++) {
            int u = t + i * 128;
            int row = u >> 3, seg = u & 7;
            uint32_t so = SWZ(row * 128 + seg * 16);
            CP_ASYNC16(tb + S2_A + so, A + (size_t)row * 256 + seg * 8);
            CP_ASYNC16(tb + S2_W + so, W + (size_t)row * 64 + seg * 8);
        }
        CP_COMMIT();
    }

    #pragma unroll 1
    for (int kt = 0; kt < 8; kt++) {
        if (kt + 1 < 8) {
            uint32_t tb = sbase + ((kt + 1) & 1) * S2_STG;
            int k0 = (kt + 1) * 64;
            #pragma unroll
            for (int i = 0; i < 4; i++) {
                int u = t + i * 128;
                int row = u >> 3, seg = u & 7;
                uint32_t so = SWZ(row * 128 + seg * 16);
                CP_ASYNC16(tb + S2_A + so, A + (size_t)(k0 + row) * 256 + seg * 8);
                CP_ASYNC16(tb + S2_W + so, W + (size_t)(k0 + row) * 64 + seg * 8);
            }
            CP_COMMIT();
            CP_WAIT(1);
        } else {
            CP_WAIT(0);
        }
        __syncthreads();

        uint32_t tb = sbase + (kt & 1) * S2_STG;
        #pragma unroll
        for (int ks = 0; ks < 4; ks++) {
            uint32_t ah[4][4], wh[2][2];
            #pragma unroll
            for (int mi = 0; mi < 4; mi++) {
                uint32_t off = SWZ((uint32_t)((ks * 16 + a_r) * 128 + mi * 32 + a_c));
                ldm_x4t(ah[mi], tb + S2_A + off);
            }
            {
                uint32_t off = SWZ((uint32_t)((ks * 16 + w_r) * 128 + wn * 32 + w_c));
                uint32_t rh[4];
                ldm_x4t(rh, tb + S2_W + off);
                wh[0][0] = rh[0]; wh[0][1] = rh[1]; wh[1][0] = rh[2]; wh[1][1] = rh[3];
            }
            #pragma unroll
            for (int mi = 0; mi < 4; mi++)
                #pragma unroll
                for (int ni = 0; ni < 2; ni++)
                    mma16816f(acc[mi][ni], ah[mi], wh[ni]);
        }
        __syncthreads();
    }

    float* g = g_G + (size_t)((side * Bsz + b) * ND + d) * 4096;
    int gq = lane >> 2, tig = lane & 3;
    #pragma unroll
    for (int mi = 0; mi < 4; mi++) {
        int m = mi * 16 + gq;
        #pragma unroll
        for (int ni = 0; ni < 2; ni++) {
            int n = wn * 16 + ni * 8 + tig * 2;
            *(float2*)&g[m * 64 + n]       = make_float2(acc[mi][ni][0], acc[mi][ni][1]);
            *(float2*)&g[(m + 8) * 64 + n] = make_float2(acc[mi][ni][2], acc[mi][ni][3]);
        }
    }
}

// ---------------- final ------------------------------------------------------
#define FINAL_SMEM_FLOATS (4096 + 4160 + 4096 + 256 + 256 + 64 + 64 + 64 + 64 + 16)

__global__ void __launch_bounds__(256) final_kernel2(const float* __restrict__ p_rel_xj,
                                                     const float* __restrict__ p_rel_xi,
                                                     float* __restrict__ out) {
    extern __shared__ float sm[];
    float* sGj  = sm;
    float* sGi  = sGj + 4096;   // 64x65 padded
    float* sWR  = sGi + 4160;
    float* red  = sWR + 4096;
    float* red2 = red + 256;
    float* sfj  = red2 + 256;
    float* sfi  = sfj + 64;
    float* sCS  = sfi + 64;
    float* sOCS = sCS + 64;
    float* sTOT = sOCS + 64;    // [0]=p total, [1]=o total

    int b = blockIdx.x, t = threadIdx.x;
    float xmean = g_meanv[b], xstd = g_stdv[b];
    float proj[16];
    #pragma unroll
    for (int i = 0; i < 16; i++) proj[i] = 0.f;

    int prw = (t >> 4) * 4, qcw = (t & 15) * 4;
    int col = t & 63, grp = t >> 6;

    for (int d = 0; d < ND; d++) {
        #pragma unroll
        for (int i = 0; i < 16; i++) {
            int id = t + i * 256;
            int p = id >> 6, q = id & 63;
            sGj[p * 64 + q] = g_G[(size_t)((0 * Bsz + b) * ND + d) * 4096 + id];
            sGi[p * 65 + q] = g_G[(size_t)((1 * Bsz + b) * ND + d) * 4096 + id];
        }
        __syncthreads();

        for (int side = 0; side < 2; side++) {
            const float* prel = (side == 0 ? p_rel_xj : p_rel_xi) + d * 4096;
            #pragma unroll
            for (int i = 0; i < 16; i++) sWR[t + i * 256] = prel[t + i * 256];
            if (t < 64) sOCS[t] = g_cs[((side * Bsz + b) * ND + d) * 64 + t];
            __syncthreads();

            const float* G = side ? sGi : sGj;
            int gs = side ? 65 : 64;
            float acc[4][4];
            #pragma unroll
            for (int i = 0; i < 4; i++)
                #pragma unroll
                for (int j = 0; j < 4; j++) acc[i][j] = 0.f;
            #pragma unroll 8
            for (int kk = 0; kk < 64; kk++) {
                float a0 = G[(prw + 0) * gs + kk];
                float a1 = G[(prw + 1) * gs + kk];
                float a2 = G[(prw + 2) * gs + kk];
                float a3 = G[(prw + 3) * gs + kk];
                float4 w4 = *(const float4*)&sWR[kk * 64 + qcw];
                acc[0][0] = fmaf(a0, w4.x, acc[0][0]); acc[0][1] = fmaf(a0, w4.y, acc[0][1]);
                acc[0][2] = fmaf(a0, w4.z, acc[0][2]); acc[0][3] = fmaf(a0, w4.w, acc[0][3]);
                acc[1][0] = fmaf(a1, w4.x, acc[1][0]); acc[1][1] = fmaf(a1, w4.y, acc[1][1]);
                acc[1][2] = fmaf(a1, w4.z, acc[1][2]); acc[1][3] = fmaf(a1, w4.w, acc[1][3]);
                acc[2][0] = fmaf(a2, w4.x, acc[2][0]); acc[2][1] = fmaf(a2, w4.y, acc[2][1]);
                acc[2][2] = fmaf(a2, w4.z, acc[2][2]); acc[2][3] = fmaf(a2, w4.w, acc[2][3]);
                acc[3][0] = fmaf(a3, w4.x, acc[3][0]); acc[3][1] = fmaf(a3, w4.y, acc[3][1]);
                acc[3][2] = fmaf(a3, w4.z, acc[3][2]); acc[3][3] = fmaf(a3, w4.w, acc[3][3]);
            }
            __syncthreads();
            #pragma unroll
            for (int i = 0; i < 4; i++)
                #pragma unroll
                for (int j = 0; j < 4; j++)
                    sWR[(prw + i) * 64 + qcw + j] = expf(acc[i][j]);
            __syncthreads();

            float s = 0.f;
            #pragma unroll
            for (int r = 0; r < 16; r++) s += sWR[(grp * 16 + r) * 64 + col];
            red[t] = s; __syncthreads();
            if (t < 64) sCS[t] = red[t] + red[t + 64] + red[t + 128] + red[t + 192];
            __syncthreads();
            if (t == 0) {
                float tp = 0.f, to = 0.f;
                for (int i = 0; i < 64; i++) { tp += sCS[i]; to += sOCS[i]; }
                sTOT[0] = tp; sTOT[1] = to;
            }
            __syncthreads();
            if (t < 64) {
                float f = sqrtf((sOCS[t] * sTOT[0]) / (sTOT[1] * sCS[t]));
                (side ? sfi : sfj)[t] = f;
            }
            __syncthreads();
        }

        float xb[16]; float s = 0.f, ss = 0.f;
        #pragma unroll
        for (int i = 0; i < 16; i++) {
            int id = t + i * 256;
            int p = id >> 6, q = id & 63;
            float v = sGj[p * 64 + q] * sfj[p] + sGi[q * 65 + p] * sfi[q];
            xb[i] = v; s += v; ss += v * v;
        }
        red[t] = s; red2[t] = ss; __syncthreads();
        for (int off = 128; off > 0; off >>= 1) {
            if (t < off) { red[t] += red[t + off]; red2[t] += red2[t + off]; }
            __syncthreads();
        }
        float n = 4096.f;
        float mean = red[0] / n;
        float var  = (red2[0] - red[0] * red[0] / n) / (n - 1.f);
        float istd = 1.f / (sqrtf(var) + 1e-5f);
        #pragma unroll
        for (int i = 0; i < 16; i++)
            proj[i] += (xb[i] - mean) * istd * xstd + xmean;
        __syncthreads();
    }
    #pragma unroll
    for (int i = 0; i < 16; i++)
        out[(size_t)b * 4096 + t + i * 256] = proj[i];
}

// ---------------- launcher ---------------------------------------------------
extern "C" void kernel_launch(void* const* d_in, const int* in_sizes, int n_in,
                              void* d_out, int out_size) {
    const float* x        = (const float*)d_in[0];
    const float* o_xj     = (const float*)d_in[1];
    const float* o_xi     = (const float*)d_in[2];
    const float* p_xj     = (const float*)d_in[3];
    const float* p_xi     = (const float*)d_in[4];
    const float* o_rel_xj = (const float*)d_in[5];
    const float* o_rel_xi = (const float*)d_in[6];
    const float* p_rel_xj = (const float*)d_in[7];
    const float* p_rel_xi = (const float*)d_in[8];
    float* out = (float*)d_out;

    cudaFuncSetAttribute(final_kernel2, cudaFuncAttributeMaxDynamicSharedMemorySize,
                         FINAL_SMEM_FLOATS * sizeof(float));
    cudaFuncSetAttribute(gemm_mma, cudaFuncAttributeMaxDynamicSharedMemorySize,
                         GEMM_DYNSM);
    cudaFuncSetAttribute(stage2_mma, cudaFuncAttributeMaxDynamicSharedMemorySize,
                         S2_DYNSM);

    convw_kernel<<<dim3(512, 2), 256>>>(o_xj, o_rel_xj, o_xi, o_rel_xi);
    convp_kernel<<<dim3(512, 2), 256>>>(p_xj, p_xi);
    convx_kernel<<<dim3(16, 16, Bsz), 128>>>(x);
    stats_reduce<<<Bsz, 256>>>();
    gemm_mma<<<dim3(16, Bsz, 2), 256, GEMM_DYNSM>>>();
    csred_kernel<<<256, 256>>>();
    stage2_mma<<<dim3(ND, 2, Bsz), 128, S2_DYNSM>>>();
    final_kernel2<<<Bsz, 256, FINAL_SMEM_FLOATS * sizeof(float)>>>(p_rel_xj, p_rel_xi, out);
}

// round 10
// speedup vs baseline: 6.7081x; 1.0206x over previous
#include <cuda_runtime.h>
#include <cuda_fp16.h>
#include <math.h>
#include <stdint.h>

#define Bsz  128
#define HW   512
#define Pp   64
#define ND   4
#define HWHW 262144

// ---------------- scratch (static device globals) ---------------------------
__device__ float g_G  [2 * Bsz * ND * Pp * Pp];
__device__ float g_cs [2 * Bsz * ND * Pp];
__device__ float g_csp[2 * Bsz * 2 * 4 * 2 * 128];   // [z][b][nt2][mt][wm][128]
__device__ float2 g_statp[Bsz * 256];                // per-tile (sum, sumsq)
__device__ float g_meanv[Bsz];
__device__ float g_stdv [Bsz];
__device__ float g_xbd [ND * Bsz * 4096];            // per-depth normalized contribs

__device__ __half g_xf [33554432];   // fp16 x   (row-major)
__device__ __half g_xtf[33554432];   // fp16 x^T
__device__ __half g_w1f[262144];     // gemm1 weights, [n][k]
__device__ __half g_w2f[262144];     // gemm2 weights
// o-halves of the two GEMMs, [b][k=512][m=256], fp16
__device__ __half g_ojf[16777216];
__device__ __half g_oif[16777216];
// p weights, [d][k=512][n=64], fp16
__device__ __half g_pjf[131072];
__device__ __half g_pif[131072];

// ---------------- helpers (plain sm_103-legal PTX) ---------------------------
__device__ __forceinline__ uint32_t smem_u32(const void* p) {
    uint32_t a;
    asm("{ .reg .u64 t; cvta.to.shared.u64 t, %1; cvt.u32.u64 %0, t; }" : "=r"(a) : "l"(p));
    return a;
}
#define CP_ASYNC16(dst, src) \
    asm volatile("cp.async.cg.shared.global [%0], [%1], 16;" :: "r"(dst), "l"(src))
#define CP_COMMIT() asm volatile("cp.async.commit_group;" ::: "memory")
#define CP_WAIT(n)  asm volatile("cp.async.wait_group %0;" :: "n"(n) : "memory")

__device__ __forceinline__ void ldm_x4(uint32_t* r, uint32_t addr) {
    asm volatile("ldmatrix.sync.aligned.m8n8.x4.shared.b16 {%0,%1,%2,%3}, [%4];"
                 : "=r"(r[0]), "=r"(r[1]), "=r"(r[2]), "=r"(r[3]) : "r"(addr));
}
__device__ __forceinline__ void ldm_x4t(uint32_t* r, uint32_t addr) {
    asm volatile("ldmatrix.sync.aligned.m8n8.x4.trans.shared.b16 {%0,%1,%2,%3}, [%4];"
                 : "=r"(r[0]), "=r"(r[1]), "=r"(r[2]), "=r"(r[3]) : "r"(addr));
}
__device__ __forceinline__ void mma16816f(float* c, const uint32_t* a, const uint32_t* b) {
    asm volatile(
        "mma.sync.aligned.m16n8k16.row.col.f32.f16.f16.f32 "
        "{%0,%1,%2,%3}, {%4,%5,%6,%7}, {%8,%9}, {%0,%1,%2,%3};"
        : "+f"(c[0]), "+f"(c[1]), "+f"(c[2]), "+f"(c[3])
        : "r"(a[0]), "r"(a[1]), "r"(a[2]), "r"(a[3]), "r"(b[0]), "r"(b[1]));
}
#define SWZ(o) ((o) ^ (((o) >> 3) & 0x70))

// ---------------- prep: big-GEMM weights -> [n][k] fp16 ----------------------
__global__ void __launch_bounds__(256) convw_kernel(const float* __restrict__ o_xj,
                                                    const float* __restrict__ o_rel_xj,
                                                    const float* __restrict__ o_xi,
                                                    const float* __restrict__ o_rel_xi) {
    int n = blockIdx.x, side = blockIdx.y, t = threadIdx.x;
    const float* w = (side == 0) ? ((n < 256) ? o_xj : o_rel_xj)
                                 : ((n < 256) ? o_xi : o_rel_xi);
    int nn = n & 255, d = nn >> 6, c = nn & 63;
    __half* of = side ? g_w2f : g_w1f;
    #pragma unroll
    for (int i = 0; i < 2; i++) {
        int k = t + i * 256;
        of[n * HW + k] = __float2half_rn(w[d * (HW * Pp) + k * Pp + c]);
    }
}

// ---------------- prep: p weights -> fp16 ([d][k][n] layout) -----------------
__global__ void __launch_bounds__(256) convp_kernel(const float* __restrict__ p_xj,
                                                    const float* __restrict__ p_xi) {
    int i = blockIdx.x * 256 + threadIdx.x;     // 0..131071
    int side = blockIdx.y;
    const float* src = side ? p_xi : p_xj;
    __half* of = side ? g_pif : g_pjf;
    of[i] = __float2half_rn(src[i]);
}

// ---------------- prep: x -> fp16 both orientations + stat partials ----------
__global__ void __launch_bounds__(128) convx_kernel(const float* __restrict__ x) {
    __shared__ float tile[32][33];
    __shared__ float rs[128], rq[128];
    int b = blockIdx.z, r0 = blockIdx.y * 32, c0 = blockIdx.x * 32;
    int t = threadIdx.x;
    int tx = t & 15, ty = t >> 4;                  // 16 x 8
    const float* xb = x + (size_t)b * HWHW;
    float ps = 0.f, pq = 0.f;
    #pragma unroll
    for (int i = 0; i < 4; i++) {
        int row = ty + i * 8;
        float2 v = *(const float2*)&xb[(r0 + row) * HW + c0 + tx * 2];
        tile[row][tx * 2]     = v.x;
        tile[row][tx * 2 + 1] = v.y;
        ps += v.x + v.y;
        pq += v.x * v.x + v.y * v.y;
        size_t o = (size_t)b * HWHW + (size_t)(r0 + row) * HW + c0 + tx * 2;
        *(__half2*)&g_xf[o] = __floats2half2_rn(v.x, v.y);
    }
    rs[t] = ps; rq[t] = pq;
    __syncthreads();
    #pragma unroll
    for (int i = 0; i < 4; i++) {
        int col = ty + i * 8;
        float v0 = tile[tx * 2][col];
        float v1 = tile[tx * 2 + 1][col];
        size_t o = (size_t)b * HWHW + (size_t)(c0 + col) * HW + r0 + tx * 2;
        *(__half2*)&g_xtf[o] = __floats2half2_rn(v0, v1);
    }
    for (int off = 64; off > 0; off >>= 1) {
        __syncthreads();
        if (t < off) { rs[t] += rs[t + off]; rq[t] += rq[t + off]; }
    }
    if (t == 0)
        g_statp[b * 256 + blockIdx.y * 16 + blockIdx.x] = make_float2(rs[0], rq[0]);
}

// ---------------- stats: fold per-tile partials ------------------------------
__global__ void __launch_bounds__(256) stats_reduce() {
    __shared__ float rs[256], rq[256];
    int b = blockIdx.x, t = threadIdx.x;
    float2 p = g_statp[b * 256 + t];
    rs[t] = p.x; rq[t] = p.y;
    for (int off = 128; off > 0; off >>= 1) {
        __syncthreads();
        if (t < off) { rs[t] += rs[t + off]; rq[t] += rq[t + off]; }
    }
    if (t == 0) {
        float n = (float)HWHW;
        float mean = rs[0] / n;
        float var  = (rq[0] - rs[0] * rs[0] / n) / (n - 1.f);
        g_meanv[b] = mean * 64.f;
        g_stdv[b]  = sqrtf(var) * 64.f;
    }
}

// ---------------- mma.sync GEMM: X @ Wcat (single-pass fp16) -----------------
// CTA 128x128, warps 2(M)x4(N), warp tile 64x32, K chunks 64, 3-stage pipeline.
#define STG_BYTES 32768
#define NSTG 3
#define OFF_A 0
#define OFF_B 16384
#define GEMM_DYNSM (NSTG * STG_BYTES)

__global__ void __launch_bounds__(256, 2) gemm_mma() {
    extern __shared__ __align__(16) unsigned char smp[];
    uint32_t sbase = smem_u32(smp);

    int t = threadIdx.x, lane = t & 31, w = t >> 5;
    int wm = w >> 2, wn = w & 3;
    int mt = blockIdx.x >> 2, nt = blockIdx.x & 3;
    int b = blockIdx.y, z = blockIdx.z;
    int m0 = mt * 128, n0 = nt * 128;

    const __half* xs = (z ? g_xtf : g_xf) + (size_t)b * HWHW;
    const __half* ws = z ? g_w2f : g_w1f;

    int a_row = (lane & 15);
    int a_cb  = (lane >> 4) * 16;
    int b_row = (lane & 7) + ((lane >> 4) & 1) * 8;
    int b_cb  = ((lane >> 3) & 1) * 16;

    float acc[4][4][4];
    #pragma unroll
    for (int mi = 0; mi < 4; mi++)
        #pragma unroll
        for (int ni = 0; ni < 4; ni++)
            #pragma unroll
            for (int q = 0; q < 4; q++) acc[mi][ni][q] = 0.f;

    // prologue: issue chunks 0 and 1
    #pragma unroll
    for (int c = 0; c < 2; c++) {
        uint32_t tb = sbase + c * STG_BYTES;
        int k0 = c * 64;
        #pragma unroll
        for (int i = 0; i < 4; i++) {
            int u = t + i * 256;
            int row = u >> 3, seg = u & 7;
            uint32_t so = SWZ(row * 128 + seg * 16);
            CP_ASYNC16(tb + OFF_A + so, xs + (m0 + row) * HW + k0 + seg * 8);
            CP_ASYNC16(tb + OFF_B + so, ws + (n0 + row) * HW + k0 + seg * 8);
        }
        CP_COMMIT();
    }

    #pragma unroll 1
    for (int kt = 0; kt < 8; kt++) {
        if (kt + 2 < 8) {
            uint32_t tb = sbase + ((kt + 2) % NSTG) * STG_BYTES;
            int k0 = (kt + 2) * 64;
            #pragma unroll
            for (int i = 0; i < 4; i++) {
                int u = t + i * 256;
                int row = u >> 3, seg = u & 7;
                uint32_t so = SWZ(row * 128 + seg * 16);
                CP_ASYNC16(tb + OFF_A + so, xs + (m0 + row) * HW + k0 + seg * 8);
                CP_ASYNC16(tb + OFF_B + so, ws + (n0 + row) * HW + k0 + seg * 8);
            }
            CP_COMMIT();
            CP_WAIT(2);
        } else if (kt == 6) {
            CP_WAIT(1);
        } else {
            CP_WAIT(0);
        }
        __syncthreads();

        uint32_t tb = sbase + (kt % NSTG) * STG_BYTES;
        #pragma unroll
        for (int ks = 0; ks < 4; ks++) {
            uint32_t ah[4][4], bh[4][2];
            #pragma unroll
            for (int mi = 0; mi < 4; mi++) {
                uint32_t off = SWZ((uint32_t)((wm * 64 + mi * 16 + a_row) * 128 + ks * 32 + a_cb));
                ldm_x4(ah[mi], tb + OFF_A + off);
            }
            #pragma unroll
            for (int np = 0; np < 2; np++) {
                uint32_t off = SWZ((uint32_t)((wn * 32 + np * 16 + b_row) * 128 + ks * 32 + b_cb));
                uint32_t rh[4];
                ldm_x4(rh, tb + OFF_B + off);
                bh[np * 2][0] = rh[0]; bh[np * 2][1] = rh[1];
                bh[np * 2 + 1][0] = rh[2]; bh[np * 2 + 1][1] = rh[3];
            }
            #pragma unroll
            for (int mi = 0; mi < 4; mi++)
                #pragma unroll
                for (int ni = 0; ni < 4; ni++)
                    mma16816f(acc[mi][ni], ah[mi], bh[ni]);
        }
        __syncthreads();
    }

    int gq = lane >> 2, tig = lane & 3;
    if (nt < 2) {
        // o-half: fp16, layout [b][k=row][m=col(0..255)]
        __half* of = z ? g_oif : g_ojf;
        size_t bb = (size_t)b * (512 * 256);
        #pragma unroll
        for (int mi = 0; mi < 4; mi++) {
            int row0 = m0 + wm * 64 + mi * 16 + gq;
            #pragma unroll
            for (int ni = 0; ni < 4; ni++) {
                int col = nt * 128 + wn * 32 + ni * 8 + tig * 2;
                *(__half2*)&of[bb + (size_t)row0 * 256 + col] =
                    __floats2half2_rn(acc[mi][ni][0], acc[mi][ni][1]);
                *(__half2*)&of[bb + (size_t)(row0 + 8) * 256 + col] =
                    __floats2half2_rn(acc[mi][ni][2], acc[mi][ni][3]);
            }
        }
    } else {
        // rel-half: exp colsum partials (deterministic slots per CTA/warp)
        size_t p = ((((size_t)(z * Bsz + b) * 2 + (nt - 2)) * 4 + mt) * 2 + wm) * 128;
        #pragma unroll
        for (int ni = 0; ni < 4; ni++) {
            float s0 = 0.f, s1 = 0.f;
            #pragma unroll
            for (int mi = 0; mi < 4; mi++) {
                s0 += expf(acc[mi][ni][0]) + expf(acc[mi][ni][2]);
                s1 += expf(acc[mi][ni][1]) + expf(acc[mi][ni][3]);
            }
            #pragma unroll
            for (int o = 4; o < 32; o <<= 1) {
                s0 += __shfl_xor_sync(0xFFFFFFFFu, s0, o);
                s1 += __shfl_xor_sync(0xFFFFFFFFu, s1, o);
            }
            if (gq == 0) {
                int cl = wn * 32 + ni * 8 + tig * 2;
                g_csp[p + cl]     = s0;
                g_csp[p + cl + 1] = s1;
            }
        }
    }
}

// ---------------- fold colsum partials ---------------------------------------
__global__ void __launch_bounds__(256) csred_kernel() {
    int i = blockIdx.x * 256 + threadIdx.x;     // 0..65535
    int side = i >> 15;
    int r = i & 32767;
    int b = r >> 8;
    int dc = r & 255;
    int d = dc >> 6, c = dc & 63;
    int nt2 = d >> 1;
    int cl = (d & 1) * 64 + c;
    size_t base = (((size_t)(side * Bsz + b) * 2 + nt2) * 4) * 2 * 128;
    float s = 0.f;
    #pragma unroll
    for (int mtw = 0; mtw < 8; mtw++) s += g_csp[base + (size_t)mtw * 128 + cl];
    g_cs[((side * Bsz + b) * ND + d) * 64 + c] = s;
}

// ---------------- stage-2 via mma: G = A_o^T @ p_x  (64x64, K=512) -----------
#define S2_STG 16384
#define S2_A 0
#define S2_W 8192
#define S2_DYNSM (2 * S2_STG)

__global__ void __launch_bounds__(128) stage2_mma() {
    extern __shared__ __align__(16) unsigned char smp2[];
    uint32_t sbase = smem_u32(smp2);

    int t = threadIdx.x, lane = t & 31, wn = t >> 5;   // 4 warps, each 16 N-cols
    int d = blockIdx.x, side = blockIdx.y, b = blockIdx.z;

    const __half* A = (side ? g_oif : g_ojf) + (size_t)b * (512 * 256) + d * 64;
    const __half* W = (side ? g_pif : g_pjf) + (size_t)d * (512 * 64);

    int a_r = (lane & 7) + ((lane >> 4) & 1) * 8;   // k within 16
    int a_c = ((lane >> 3) & 1) * 16;               // m byte within 32
    int w_r = (lane & 7) + ((lane >> 3) & 1) * 8;   // k within 16
    int w_c = ((lane >> 4) & 1) * 16;               // n byte within 32

    float acc[4][2][4];
    #pragma unroll
    for (int mi = 0; mi < 4; mi++)
        #pragma unroll
        for (int ni = 0; ni < 2; ni++)
            #pragma unroll
            for (int q = 0; q < 4; q++) acc[mi][ni][q] = 0.f;

    {
        uint32_t tb = sbase;
        #pragma unroll
        for (int i = 0; i < 4; i++) {
            int u = t + i * 128;
            int row = u >> 3, seg = u & 7;
            uint32_t so = SWZ(row * 128 + seg * 16);
            CP_ASYNC16(tb + S2_A + so, A + (size_t)row * 256 + seg * 8);
            CP_ASYNC16(tb + S2_W + so, W + (size_t)row * 64 + seg * 8);
        }
        CP_COMMIT();
    }

    #pragma unroll 1
    for (int kt = 0; kt < 8; kt++) {
        if (kt + 1 < 8) {
            uint32_t tb = sbase + ((kt + 1) & 1) * S2_STG;
            int k0 = (kt + 1) * 64;
            #pragma unroll
            for (int i = 0; i < 4; i++) {
                int u = t + i * 128;
                int row = u >> 3, seg = u & 7;
                uint32_t so = SWZ(row * 128 + seg * 16);
                CP_ASYNC16(tb + S2_A + so, A + (size_t)(k0 + row) * 256 + seg * 8);
                CP_ASYNC16(tb + S2_W + so, W + (size_t)(k0 + row) * 64 + seg * 8);
            }
            CP_COMMIT();
            CP_WAIT(1);
        } else {
            CP_WAIT(0);
        }
        __syncthreads();

        uint32_t tb = sbase + (kt & 1) * S2_STG;
        #pragma unroll
        for (int ks = 0; ks < 4; ks++) {
            uint32_t ah[4][4], wh[2][2];
            #pragma unroll
            for (int mi = 0; mi < 4; mi++) {
                uint32_t off = SWZ((uint32_t)((ks * 16 + a_r) * 128 + mi * 32 + a_c));
                ldm_x4t(ah[mi], tb + S2_A + off);
            }
            {
                uint32_t off = SWZ((uint32_t)((ks * 16 + w_r) * 128 + wn * 32 + w_c));
                uint32_t rh[4];
                ldm_x4t(rh, tb + S2_W + off);
                wh[0][0] = rh[0]; wh[0][1] = rh[1]; wh[1][0] = rh[2]; wh[1][1] = rh[3];
            }
            #pragma unroll
            for (int mi = 0; mi < 4; mi++)
                #pragma unroll
                for (int ni = 0; ni < 2; ni++)
                    mma16816f(acc[mi][ni], ah[mi], wh[ni]);
        }
        __syncthreads();
    }

    float* g = g_G + (size_t)((side * Bsz + b) * ND + d) * 4096;
    int gq = lane >> 2, tig = lane & 3;
    #pragma unroll
    for (int mi = 0; mi < 4; mi++) {
        int m = mi * 16 + gq;
        #pragma unroll
        for (int ni = 0; ni < 2; ni++) {
            int n = wn * 16 + ni * 8 + tig * 2;
            *(float2*)&g[m * 64 + n]       = make_float2(acc[mi][ni][0], acc[mi][ni][1]);
            *(float2*)&g[(m + 8) * 64 + n] = make_float2(acc[mi][ni][2], acc[mi][ni][3]);
        }
    }
}

// ---------------- final: one CTA per (d, b) ----------------------------------
#define FINAL_SMEM_FLOATS (4096 + 4160 + 4096 + 256 + 256 + 64 + 64 + 64 + 64 + 16)

__global__ void __launch_bounds__(256) final_depth(const float* __restrict__ p_rel_xj,
                                                   const float* __restrict__ p_rel_xi) {
    extern __shared__ float sm[];
    float* sGj  = sm;
    float* sGi  = sGj + 4096;   // 64x65 padded
    float* sWR  = sGi + 4160;
    float* red  = sWR + 4096;
    float* red2 = red + 256;
    float* sfj  = red2 + 256;
    float* sfi  = sfj + 64;
    float* sCS  = sfi + 64;
    float* sOCS = sCS + 64;
    float* sTOT = sOCS + 64;    // [0]=p total, [1]=o total

    int d = blockIdx.x, b = blockIdx.y, t = threadIdx.x;
    float xmean = g_meanv[b], xstd = g_stdv[b];

    int prw = (t >> 4) * 4, qcw = (t & 15) * 4;
    int col = t & 63, grp = t >> 6;

    #pragma unroll
    for (int i = 0; i < 16; i++) {
        int id = t + i * 256;
        int p = id >> 6, q = id & 63;
        sGj[p * 64 + q] = g_G[(size_t)((0 * Bsz + b) * ND + d) * 4096 + id];
        sGi[p * 65 + q] = g_G[(size_t)((1 * Bsz + b) * ND + d) * 4096 + id];
    }
    __syncthreads();

    for (int side = 0; side < 2; side++) {
        const float* prel = (side == 0 ? p_rel_xj : p_rel_xi) + d * 4096;
        #pragma unroll
        for (int i = 0; i < 16; i++) sWR[t + i * 256] = prel[t + i * 256];
        if (t < 64) sOCS[t] = g_cs[((side * Bsz + b) * ND + d) * 64 + t];
        __syncthreads();

        const float* G = side ? sGi : sGj;
        int gs = side ? 65 : 64;
        float acc[4][4];
        #pragma unroll
        for (int i = 0; i < 4; i++)
            #pragma unroll
            for (int j = 0; j < 4; j++) acc[i][j] = 0.f;
        #pragma unroll 8
        for (int kk = 0; kk < 64; kk++) {
            float a0 = G[(prw + 0) * gs + kk];
            float a1 = G[(prw + 1) * gs + kk];
            float a2 = G[(prw + 2) * gs + kk];
            float a3 = G[(prw + 3) * gs + kk];
            float4 w4 = *(const float4*)&sWR[kk * 64 + qcw];
            acc[0][0] = fmaf(a0, w4.x, acc[0][0]); acc[0][1] = fmaf(a0, w4.y, acc[0][1]);
            acc[0][2] = fmaf(a0, w4.z, acc[0][2]); acc[0][3] = fmaf(a0, w4.w, acc[0][3]);
            acc[1][0] = fmaf(a1, w4.x, acc[1][0]); acc[1][1] = fmaf(a1, w4.y, acc[1][1]);
            acc[1][2] = fmaf(a1, w4.z, acc[1][2]); acc[1][3] = fmaf(a1, w4.w, acc[1][3]);
            acc[2][0] = fmaf(a2, w4.x, acc[2][0]); acc[2][1] = fmaf(a2, w4.y, acc[2][1]);
            acc[2][2] = fmaf(a2, w4.z, acc[2][2]); acc[2][3] = fmaf(a2, w4.w, acc[2][3]);
            acc[3][0] = fmaf(a3, w4.x, acc[3][0]); acc[3][1] = fmaf(a3, w4.y, acc[3][1]);
            acc[3][2] = fmaf(a3, w4.z, acc[3][2]); acc[3][3] = fmaf(a3, w4.w, acc[3][3]);
        }
        __syncthreads();
        #pragma unroll
        for (int i = 0; i < 4; i++)
            #pragma unroll
            for (int j = 0; j < 4; j++)
                sWR[(prw + i) * 64 + qcw + j] = expf(acc[i][j]);
        __syncthreads();

        float s = 0.f;
        #pragma unroll
        for (int r = 0; r < 16; r++) s += sWR[(grp * 16 + r) * 64 + col];
        red[t] = s; __syncthreads();
        if (t < 64) sCS[t] = red[t] + red[t + 64] + red[t + 128] + red[t + 192];
        __syncthreads();
        if (t == 0) {
            float tp = 0.f, to = 0.f;
            for (int i = 0; i < 64; i++) { tp += sCS[i]; to += sOCS[i]; }
            sTOT[0] = tp; sTOT[1] = to;
        }
        __syncthreads();
        if (t < 64) {
            float f = sqrtf((sOCS[t] * sTOT[0]) / (sTOT[1] * sCS[t]));
            (side ? sfi : sfj)[t] = f;
        }
        __syncthreads();
    }

    float xb[16]; float s = 0.f, ss = 0.f;
    #pragma unroll
    for (int i = 0; i < 16; i++) {
        int id = t + i * 256;
        int p = id >> 6, q = id & 63;
        float v = sGj[p * 64 + q] * sfj[p] + sGi[q * 65 + p] * sfi[q];
        xb[i] = v; s += v; ss += v * v;
    }
    red[t] = s; red2[t] = ss; __syncthreads();
    for (int off = 128; off > 0; off >>= 1) {
        if (t < off) { red[t] += red[t + off]; red2[t] += red2[t + off]; }
        __syncthreads();
    }
    float n = 4096.f;
    float mean = red[0] / n;
    float var  = (red2[0] - red[0] * red[0] / n) / (n - 1.f);
    float istd = 1.f / (sqrtf(var) + 1e-5f);
    float* ob = g_xbd + (size_t)(d * Bsz + b) * 4096;
    #pragma unroll
    for (int i = 0; i < 16; i++)
        ob[t + i * 256] = (xb[i] - mean) * istd * xstd + xmean;
}

// ---------------- accumulate per-depth contributions (fixed d order) ---------
__global__ void __launch_bounds__(256) accum_kernel(float* __restrict__ out) {
    int i = blockIdx.x * 256 + threadIdx.x;      // 0 .. Bsz*4096-1
    int b = i >> 12, idx = i & 4095;
    float s = 0.f;
    #pragma unroll
    for (int d = 0; d < ND; d++)
        s += g_xbd[(size_t)(d * Bsz + b) * 4096 + idx];
    out[i] = s;
}

// ---------------- launcher ---------------------------------------------------
extern "C" void kernel_launch(void* const* d_in, const int* in_sizes, int n_in,
                              void* d_out, int out_size) {
    const float* x        = (const float*)d_in[0];
    const float* o_xj     = (const float*)d_in[1];
    const float* o_xi     = (const float*)d_in[2];
    const float* p_xj     = (const float*)d_in[3];
    const float* p_xi     = (const float*)d_in[4];
    const float* o_rel_xj = (const float*)d_in[5];
    const float* o_rel_xi = (const float*)d_in[6];
    const float* p_rel_xj = (const float*)d_in[7];
    const float* p_rel_xi = (const float*)d_in[8];
    float* out = (float*)d_out;

    cudaFuncSetAttribute(final_depth, cudaFuncAttributeMaxDynamicSharedMemorySize,
                         FINAL_SMEM_FLOATS * sizeof(float));
    cudaFuncSetAttribute(gemm_mma, cudaFuncAttributeMaxDynamicSharedMemorySize,
                         GEMM_DYNSM);
    cudaFuncSetAttribute(stage2_mma, cudaFuncAttributeMaxDynamicSharedMemorySize,
                         S2_DYNSM);

    convw_kernel<<<dim3(512, 2), 256>>>(o_xj, o_rel_xj, o_xi, o_rel_xi);
    convp_kernel<<<dim3(512, 2), 256>>>(p_xj, p_xi);
    convx_kernel<<<dim3(16, 16, Bsz), 128>>>(x);
    stats_reduce<<<Bsz, 256>>>();
    gemm_mma<<<dim3(16, Bsz, 2), 256, GEMM_DYNSM>>>();
    csred_kernel<<<256, 256>>>();
    stage2_mma<<<dim3(ND, 2, Bsz), 128, S2_DYNSM>>>();
    final_depth<<<dim3(ND, Bsz), 256, FINAL_SMEM_FLOATS * sizeof(float)>>>(p_rel_xj, p_rel_xi);
    accum_kernel<<<Bsz * 4096 / 256, 256>>>(out);
}

// round 12
// speedup vs baseline: 6.7410x; 1.0049x over previous
#include <cuda_runtime.h>
#include <cuda_fp16.h>
#include <math.h>
#include <stdint.h>

#define Bsz  128
#define HW   512
#define Pp   64
#define ND   4
#define HWHW 262144

// ---------------- scratch (static device globals) ---------------------------
__device__ float g_G  [2 * Bsz * ND * Pp * Pp];
__device__ float g_cs [2 * Bsz * ND * Pp];
__device__ float g_csp[2 * Bsz * 2 * 4 * 2 * 128];   // [z][b][nt2][mt][wm][128]
__device__ float2 g_statp[Bsz * 16];                 // per-chunk (sum, sumsq)
__device__ float g_meanv[Bsz];
__device__ float g_stdv [Bsz];
__device__ float g_xbd [ND * Bsz * 4096];            // per-depth normalized contribs

__device__ __half g_xf [33554432];   // fp16 x (row-major; also serves x^T GEMM)
__device__ __half g_w1f[262144];     // gemm1 weights, [n][k]
__device__ __half g_w2f[262144];     // gemm2 weights
// o-halves of the two GEMMs, [b][k=512][m=256], fp16
__device__ __half g_ojf[16777216];
__device__ __half g_oif[16777216];
// p weights, [d][k=512][n=64], fp16
__device__ __half g_pjf[131072];
__device__ __half g_pif[131072];

// ---------------- helpers (plain sm_103-legal PTX) ---------------------------
__device__ __forceinline__ uint32_t smem_u32(const void* p) {
    uint32_t a;
    asm("{ .reg .u64 t; cvta.to.shared.u64 t, %1; cvt.u32.u64 %0, t; }" : "=r"(a) : "l"(p));
    return a;
}
#define CP_ASYNC16(dst, src) \
    asm volatile("cp.async.cg.shared.global [%0], [%1], 16;" :: "r"(dst), "l"(src))
#define CP_COMMIT() asm volatile("cp.async.commit_group;" ::: "memory")
#define CP_WAIT(n)  asm volatile("cp.async.wait_group %0;" :: "n"(n) : "memory")

__device__ __forceinline__ void ldm_x4(uint32_t* r, uint32_t addr) {
    asm volatile("ldmatrix.sync.aligned.m8n8.x4.shared.b16 {%0,%1,%2,%3}, [%4];"
                 : "=r"(r[0]), "=r"(r[1]), "=r"(r[2]), "=r"(r[3]) : "r"(addr));
}
__device__ __forceinline__ void ldm_x4t(uint32_t* r, uint32_t addr) {
    asm volatile("ldmatrix.sync.aligned.m8n8.x4.trans.shared.b16 {%0,%1,%2,%3}, [%4];"
                 : "=r"(r[0]), "=r"(r[1]), "=r"(r[2]), "=r"(r[3]) : "r"(addr));
}
__device__ __forceinline__ void mma16816f(float* c, const uint32_t* a, const uint32_t* b) {
    asm volatile(
        "mma.sync.aligned.m16n8k16.row.col.f32.f16.f16.f32 "
        "{%0,%1,%2,%3}, {%4,%5,%6,%7}, {%8,%9}, {%0,%1,%2,%3};"
        : "+f"(c[0]), "+f"(c[1]), "+f"(c[2]), "+f"(c[3])
        : "r"(a[0]), "r"(a[1]), "r"(a[2]), "r"(a[3]), "r"(b[0]), "r"(b[1]));
}
#define SWZ(o) ((o) ^ (((o) >> 3) & 0x70))

// ---------------- prep: big-GEMM weights -> [n][k] fp16 ----------------------
__global__ void __launch_bounds__(256) convw_kernel(const float* __restrict__ o_xj,
                                                    const float* __restrict__ o_rel_xj,
                                                    const float* __restrict__ o_xi,
                                                    const float* __restrict__ o_rel_xi) {
    int n = blockIdx.x, side = blockIdx.y, t = threadIdx.x;
    const float* w = (side == 0) ? ((n < 256) ? o_xj : o_rel_xj)
                                 : ((n < 256) ? o_xi : o_rel_xi);
    int nn = n & 255, d = nn >> 6, c = nn & 63;
    __half* of = side ? g_w2f : g_w1f;
    #pragma unroll
    for (int i = 0; i < 2; i++) {
        int k = t + i * 256;
        of[n * HW + k] = __float2half_rn(w[d * (HW * Pp) + k * Pp + c]);
    }
}

// ---------------- prep: p weights -> fp16 ([d][k][n] layout) -----------------
__global__ void __launch_bounds__(256) convp_kernel(const float* __restrict__ p_xj,
                                                    const float* __restrict__ p_xi) {
    int i = blockIdx.x * 256 + threadIdx.x;     // 0..131071
    int side = blockIdx.y;
    const float* src = side ? p_xi : p_xj;
    __half* of = side ? g_pif : g_pjf;
    of[i] = __float2half_rn(src[i]);
}

// ---------------- prep: x -> fp16 (row-major only) + stat partials -----------
__global__ void __launch_bounds__(256) convx_kernel(const float* __restrict__ x) {
    __shared__ float rs[256], rq[256];
    int b = blockIdx.y, chunk = blockIdx.x;     // 16 chunks of 16384 floats
    int t = threadIdx.x;
    size_t base = (size_t)b * HWHW + (size_t)chunk * 16384;
    const float4* src = (const float4*)(x + base);
    __half2* dst = (__half2*)(g_xf + base);
    float ps = 0.f, pq = 0.f;
    #pragma unroll
    for (int i = 0; i < 16; i++) {
        int idx = t + i * 256;
        float4 v = src[idx];
        ps += v.x + v.y + v.z + v.w;
        pq += v.x * v.x + v.y * v.y + v.z * v.z + v.w * v.w;
        dst[idx * 2]     = __floats2half2_rn(v.x, v.y);
        dst[idx * 2 + 1] = __floats2half2_rn(v.z, v.w);
    }
    rs[t] = ps; rq[t] = pq;
    for (int off = 128; off > 0; off >>= 1) {
        __syncthreads();
        if (t < off) { rs[t] += rs[t + off]; rq[t] += rq[t + off]; }
    }
    if (t == 0) g_statp[b * 16 + chunk] = make_float2(rs[0], rq[0]);
}

// ---------------- stats: fold per-chunk partials ------------------------------
__global__ void __launch_bounds__(32) stats_reduce() {
    int b = blockIdx.x, t = threadIdx.x;
    float s = 0.f, q = 0.f;
    if (t < 16) { float2 p = g_statp[b * 16 + t]; s = p.x; q = p.y; }
    #pragma unroll
    for (int o = 8; o > 0; o >>= 1) {
        s += __shfl_down_sync(0xFFFFFFFFu, s, o);
        q += __shfl_down_sync(0xFFFFFFFFu, q, o);
    }
    if (t == 0) {
        float n = (float)HWHW;
        float mean = s / n;
        float var  = (q - s * s / n) / (n - 1.f);
        g_meanv[b] = mean * 64.f;
        g_stdv[b]  = sqrtf(var) * 64.f;
    }
}

// ---------------- mma.sync GEMM: X @ Wcat (single-pass fp16) -----------------
// CTA 128x128, warps 2(M)x4(N), warp tile 64x32, K chunks 64, 3-stage pipeline.
// z=0: A tiles from row-major x ([m][k], normal ldmatrix).
// z=1: A = x^T; tiles loaded from row-major x as [k][m] (two 64-m halves of
//      128B rows), fragments via trans ldmatrix (stage2-verified pattern).
#define STG_BYTES 32768
#define NSTG 3
#define OFF_A 0
#define OFF_B 16384
#define GEMM_DYNSM (NSTG * STG_BYTES)

__device__ __forceinline__ void load_a_tile(uint32_t tb, const __half* xs,
                                            int m0, int k0, int t, int z) {
    if (z == 0) {
        #pragma unroll
        for (int i = 0; i < 4; i++) {
            int u = t + i * 256;
            int row = u >> 3, seg = u & 7;
            CP_ASYNC16(tb + OFF_A + SWZ(row * 128 + seg * 16),
                       xs + (size_t)(m0 + row) * HW + k0 + seg * 8);
        }
    } else {
        #pragma unroll
        for (int i = 0; i < 4; i++) {
            int u = t + i * 256;
            int mh = u >> 9, k = (u >> 3) & 63, seg = u & 7;
            CP_ASYNC16(tb + OFF_A + mh * 8192 + SWZ(k * 128 + seg * 16),
                       xs + (size_t)(k0 + k) * HW + m0 + mh * 64 + seg * 8);
        }
    }
}

__global__ void __launch_bounds__(256, 2) gemm_mma() {
    extern __shared__ __align__(16) unsigned char smp[];
    uint32_t sbase = smem_u32(smp);

    int t = threadIdx.x, lane = t & 31, w = t >> 5;
    int wm = w >> 2, wn = w & 3;
    int mt = blockIdx.x >> 2, nt = blockIdx.x & 3;
    int b = blockIdx.y, z = blockIdx.z;
    int m0 = mt * 128, n0 = nt * 128;

    const __half* xs = g_xf + (size_t)b * HWHW;
    const __half* ws = z ? g_w2f : g_w1f;

    int a_row = (lane & 15);                         // z=0 (normal)
    int a_cb  = (lane >> 4) * 16;
    int a_rT  = (lane & 7) + ((lane >> 4) & 1) * 8;  // z=1 (trans)
    int a_cT  = ((lane >> 3) & 1) * 16;
    int b_row = (lane & 7) + ((lane >> 4) & 1) * 8;
    int b_cb  = ((lane >> 3) & 1) * 16;

    float acc[4][4][4];
    #pragma unroll
    for (int mi = 0; mi < 4; mi++)
        #pragma unroll
        for (int ni = 0; ni < 4; ni++)
            #pragma unroll
            for (int q = 0; q < 4; q++) acc[mi][ni][q] = 0.f;

    // prologue: issue chunks 0 and 1
    #pragma unroll
    for (int c = 0; c < 2; c++) {
        uint32_t tb = sbase + c * STG_BYTES;
        int k0 = c * 64;
        load_a_tile(tb, xs, m0, k0, t, z);
        #pragma unroll
        for (int i = 0; i < 4; i++) {
            int u = t + i * 256;
            int row = u >> 3, seg = u & 7;
            CP_ASYNC16(tb + OFF_B + SWZ(row * 128 + seg * 16),
                       ws + (size_t)(n0 + row) * HW + k0 + seg * 8);
        }
        CP_COMMIT();
    }

    #pragma unroll 1
    for (int kt = 0; kt < 8; kt++) {
        if (kt + 2 < 8) {
            uint32_t tb = sbase + ((kt + 2) % NSTG) * STG_BYTES;
            int k0 = (kt + 2) * 64;
            load_a_tile(tb, xs, m0, k0, t, z);
            #pragma unroll
            for (int i = 0; i < 4; i++) {
                int u = t + i * 256;
                int row = u >> 3, seg = u & 7;
                CP_ASYNC16(tb + OFF_B + SWZ(row * 128 + seg * 16),
                           ws + (size_t)(n0 + row) * HW + k0 + seg * 8);
            }
            CP_COMMIT();
            CP_WAIT(2);
        } else if (kt == 6) {
            CP_WAIT(1);
        } else {
            CP_WAIT(0);
        }
        __syncthreads();

        uint32_t tb = sbase + (kt % NSTG) * STG_BYTES;
        #pragma unroll
        for (int ks = 0; ks < 4; ks++) {
            uint32_t ah[4][4], bh[4][2];
            if (z == 0) {
                #pragma unroll
                for (int mi = 0; mi < 4; mi++) {
                    uint32_t off = SWZ((uint32_t)((wm * 64 + mi * 16 + a_row) * 128 + ks * 32 + a_cb));
                    ldm_x4(ah[mi], tb + OFF_A + off);
                }
            } else {
                #pragma unroll
                for (int mi = 0; mi < 4; mi++) {
                    uint32_t off = wm * 8192 +
                        SWZ((uint32_t)((ks * 16 + a_rT) * 128 + mi * 32 + a_cT));
                    ldm_x4t(ah[mi], tb + OFF_A + off);
                }
            }
            #pragma unroll
            for (int np = 0; np < 2; np++) {
                uint32_t off = SWZ((uint32_t)((wn * 32 + np * 16 + b_row) * 128 + ks * 32 + b_cb));
                uint32_t rh[4];
                ldm_x4(rh, tb + OFF_B + off);
                bh[np * 2][0] = rh[0]; bh[np * 2][1] = rh[1];
                bh[np * 2 + 1][0] = rh[2]; bh[np * 2 + 1][1] = rh[3];
            }
            #pragma unroll
            for (int mi = 0; mi < 4; mi++)
                #pragma unroll
                for (int ni = 0; ni < 4; ni++)
                    mma16816f(acc[mi][ni], ah[mi], bh[ni]);
        }
        __syncthreads();
    }

    int gq = lane >> 2, tig = lane & 3;
    if (nt < 2) {
        // o-half: fp16, layout [b][k=row][m=col(0..255)]
        __half* of = z ? g_oif : g_ojf;
        size_t bb = (size_t)b * (512 * 256);
        #pragma unroll
        for (int mi = 0; mi < 4; mi++) {
            int row0 = m0 + wm * 64 + mi * 16 + gq;
            #pragma unroll
            for (int ni = 0; ni < 4; ni++) {
                int col = nt * 128 + wn * 32 + ni * 8 + tig * 2;
                *(__half2*)&of[bb + (size_t)row0 * 256 + col] =
                    __floats2half2_rn(acc[mi][ni][0], acc[mi][ni][1]);
                *(__half2*)&of[bb + (size_t)(row0 + 8) * 256 + col] =
                    __floats2half2_rn(acc[mi][ni][2], acc[mi][ni][3]);
            }
        }
    } else {
        // rel-half: exp colsum partials (deterministic slots per CTA/warp)
        size_t p = ((((size_t)(z * Bsz + b) * 2 + (nt - 2)) * 4 + mt) * 2 + wm) * 128;
        #pragma unroll
        for (int ni = 0; ni < 4; ni++) {
            float s0 = 0.f, s1 = 0.f;
            #pragma unroll
            for (int mi = 0; mi < 4; mi++) {
                s0 += expf(acc[mi][ni][0]) + expf(acc[mi][ni][2]);
                s1 += expf(acc[mi][ni][1]) + expf(acc[mi][ni][3]);
            }
            #pragma unroll
            for (int o = 4; o < 32; o <<= 1) {
                s0 += __shfl_xor_sync(0xFFFFFFFFu, s0, o);
                s1 += __shfl_xor_sync(0xFFFFFFFFu, s1, o);
            }
            if (gq == 0) {
                int cl = wn * 32 + ni * 8 + tig * 2;
                g_csp[p + cl]     = s0;
                g_csp[p + cl + 1] = s1;
            }
        }
    }
}

// ---------------- fold colsum partials ---------------------------------------
__global__ void __launch_bounds__(256) csred_kernel() {
    int i = blockIdx.x * 256 + threadIdx.x;     // 0..65535
    int side = i >> 15;
    int r = i & 32767;
    int b = r >> 8;
    int dc = r & 255;
    int d = dc >> 6, c = dc & 63;
    int nt2 = d >> 1;
    int cl = (d & 1) * 64 + c;
    size_t base = (((size_t)(side * Bsz + b) * 2 + nt2) * 4) * 2 * 128;
    float s = 0.f;
    #pragma unroll
    for (int mtw = 0; mtw < 8; mtw++) s += g_csp[base + (size_t)mtw * 128 + cl];
    g_cs[((side * Bsz + b) * ND + d) * 64 + c] = s;
}

// ---------------- stage-2 via mma: G = A_o^T @ p_x  (64x64, K=512) -----------
#define S2_STG 16384
#define S2_A 0
#define S2_W 8192
#define S2_DYNSM (2 * S2_STG)

__global__ void __launch_bounds__(128) stage2_mma() {
    extern __shared__ __align__(16) unsigned char smp2[];
    uint32_t sbase = smem_u32(smp2);

    int t = threadIdx.x, lane = t & 31, wn = t >> 5;   // 4 warps, each 16 N-cols
    int d = blockIdx.x, side = blockIdx.y, b = blockIdx.z;

    const __half* A = (side ? g_oif : g_ojf) + (size_t)b * (512 * 256) + d * 64;
    const __half* W = (side ? g_pif : g_pjf) + (size_t)d * (512 * 64);

    int a_r = (lane & 7) + ((lane >> 4) & 1) * 8;   // k within 16
    int a_c = ((lane >> 3) & 1) * 16;               // m byte within 32
    int w_r = (lane & 7) + ((lane >> 3) & 1) * 8;   // k within 16
    int w_c = ((lane >> 4) & 1) * 16;               // n byte within 32

    float acc[4][2][4];
    #pragma unroll
    for (int mi = 0; mi < 4; mi++)
        #pragma unroll
        for (int ni = 0; ni < 2; ni++)
            #pragma unroll
            for (int q = 0; q < 4; q++) acc[mi][ni][q] = 0.f;

    {
        uint32_t tb = sbase;
        #pragma unroll
        for (int i = 0; i < 4; i++) {
            int u = t + i * 128;
            int row = u >> 3, seg = u & 7;
            uint32_t so = SWZ(row * 128 + seg * 16);
            CP_ASYNC16(tb + S2_A + so, A + (size_t)row * 256 + seg * 8);
            CP_ASYNC16(tb + S2_W + so, W + (size_t)row * 64 + seg * 8);
        }
        CP_COMMIT();
    }

    #pragma unroll 1
    for (int kt = 0; kt < 8; kt++) {
        if (kt + 1 < 8) {
            uint32_t tb = sbase + ((kt + 1) & 1) * S2_STG;
            int k0 = (kt + 1) * 64;
            #pragma unroll
            for (int i = 0; i < 4; i++) {
                int u = t + i * 128;
                int row = u >> 3, seg = u & 7;
                uint32_t so = SWZ(row * 128 + seg * 16);
                CP_ASYNC16(tb + S2_A + so, A + (size_t)(k0 + row) * 256 + seg * 8);
                CP_ASYNC16(tb + S2_W + so, W + (size_t)(k0 + row) * 64 + seg * 8);
            }
            CP_COMMIT();
            CP_WAIT(1);
        } else {
            CP_WAIT(0);
        }
        __syncthreads();

        uint32_t tb = sbase + (kt & 1) * S2_STG;
        #pragma unroll
        for (int ks = 0; ks < 4; ks++) {
            uint32_t ah[4][4], wh[2][2];
            #pragma unroll
            for (int mi = 0; mi < 4; mi++) {
                uint32_t off = SWZ((uint32_t)((ks * 16 + a_r) * 128 + mi * 32 + a_c));
                ldm_x4t(ah[mi], tb + S2_A + off);
            }
            {
                uint32_t off = SWZ((uint32_t)((ks * 16 + w_r) * 128 + wn * 32 + w_c));
                uint32_t rh[4];
                ldm_x4t(rh, tb + S2_W + off);
                wh[0][0] = rh[0]; wh[0][1] = rh[1]; wh[1][0] = rh[2]; wh[1][1] = rh[3];
            }
            #pragma unroll
            for (int mi = 0; mi < 4; mi++)
                #pragma unroll
                for (int ni = 0; ni < 2; ni++)
                    mma16816f(acc[mi][ni], ah[mi], wh[ni]);
        }
        __syncthreads();
    }

    float* g = g_G + (size_t)((side * Bsz + b) * ND + d) * 4096;
    int gq = lane >> 2, tig = lane & 3;
    #pragma unroll
    for (int mi = 0; mi < 4; mi++) {
        int m = mi * 16 + gq;
        #pragma unroll
        for (int ni = 0; ni < 2; ni++) {
            int n = wn * 16 + ni * 8 + tig * 2;
            *(float2*)&g[m * 64 + n]       = make_float2(acc[mi][ni][0], acc[mi][ni][1]);
            *(float2*)&g[(m + 8) * 64 + n] = make_float2(acc[mi][ni][2], acc[mi][ni][3]);
        }
    }
}

// ---------------- final: one CTA per (d, b) ----------------------------------
#define FINAL_SMEM_FLOATS (4096 + 4160 + 4096 + 256 + 256 + 64 + 64 + 64 + 64 + 16)

__global__ void __launch_bounds__(256) final_depth(const float* __restrict__ p_rel_xj,
                                                   const float* __restrict__ p_rel_xi) {
    extern __shared__ float sm[];
    float* sGj  = sm;
    float* sGi  = sGj + 4096;   // 64x65 padded
    float* sWR  = sGi + 4160;
    float* red  = sWR + 4096;
    float* red2 = red + 256;
    float* sfj  = red2 + 256;
    float* sfi  = sfj + 64;
    float* sCS  = sfi + 64;
    float* sOCS = sCS + 64;
    float* sTOT = sOCS + 64;    // [0]=p total, [1]=o total

    int d = blockIdx.x, b = blockIdx.y, t = threadIdx.x;
    float xmean = g_meanv[b], xstd = g_stdv[b];

    int prw = (t >> 4) * 4, qcw = (t & 15) * 4;
    int col = t & 63, grp = t >> 6;

    #pragma unroll
    for (int i = 0; i < 16; i++) {
        int id = t + i * 256;
        int p = id >> 6, q = id & 63;
        sGj[p * 64 + q] = g_G[(size_t)((0 * Bsz + b) * ND + d) * 4096 + id];
        sGi[p * 65 + q] = g_G[(size_t)((1 * Bsz + b) * ND + d) * 4096 + id];
    }
    __syncthreads();

    for (int side = 0; side < 2; side++) {
        const float* prel = (side == 0 ? p_rel_xj : p_rel_xi) + d * 4096;
        #pragma unroll
        for (int i = 0; i < 16; i++) sWR[t + i * 256] = prel[t + i * 256];
        if (t < 64) sOCS[t] = g_cs[((side * Bsz + b) * ND + d) * 64 + t];
        __syncthreads();

        const float* G = side ? sGi : sGj;
        int gs = side ? 65 : 64;
        float acc[4][4];
        #pragma unroll
        for (int i = 0; i < 4; i++)
            #pragma unroll
            for (int j = 0; j < 4; j++) acc[i][j] = 0.f;
        #pragma unroll 8
        for (int kk = 0; kk < 64; kk++) {
            float a0 = G[(prw + 0) * gs + kk];
            float a1 = G[(prw + 1) * gs + kk];
            float a2 = G[(prw + 2) * gs + kk];
            float a3 = G[(prw + 3) * gs + kk];
            float4 w4 = *(const float4*)&sWR[kk * 64 + qcw];
            acc[0][0] = fmaf(a0, w4.x, acc[0][0]); acc[0][1] = fmaf(a0, w4.y, acc[0][1]);
            acc[0][2] = fmaf(a0, w4.z, acc[0][2]); acc[0][3] = fmaf(a0, w4.w, acc[0][3]);
            acc[1][0] = fmaf(a1, w4.x, acc[1][0]); acc[1][1] = fmaf(a1, w4.y, acc[1][1]);
            acc[1][2] = fmaf(a1, w4.z, acc[1][2]); acc[1][3] = fmaf(a1, w4.w, acc[1][3]);
            acc[2][0] = fmaf(a2, w4.x, acc[2][0]); acc[2][1] = fmaf(a2, w4.y, acc[2][1]);
            acc[2][2] = fmaf(a2, w4.z, acc[2][2]); acc[2][3] = fmaf(a2, w4.w, acc[2][3]);
            acc[3][0] = fmaf(a3, w4.x, acc[3][0]); acc[3][1] = fmaf(a3, w4.y, acc[3][1]);
            acc[3][2] = fmaf(a3, w4.z, acc[3][2]); acc[3][3] = fmaf(a3, w4.w, acc[3][3]);
        }
        __syncthreads();
        #pragma unroll
        for (int i = 0; i < 4; i++)
            #pragma unroll
            for (int j = 0; j < 4; j++)
                sWR[(prw + i) * 64 + qcw + j] = expf(acc[i][j]);
        __syncthreads();

        float s = 0.f;
        #pragma unroll
        for (int r = 0; r < 16; r++) s += sWR[(grp * 16 + r) * 64 + col];
        red[t] = s; __syncthreads();
        if (t < 64) sCS[t] = red[t] + red[t + 64] + red[t + 128] + red[t + 192];
        __syncthreads();
        if (t == 0) {
            float tp = 0.f, to = 0.f;
            for (int i = 0; i < 64; i++) { tp += sCS[i]; to += sOCS[i]; }
            sTOT[0] = tp; sTOT[1] = to;
        }
        __syncthreads();
        if (t < 64) {
            float f = sqrtf((sOCS[t] * sTOT[0]) / (sTOT[1] * sCS[t]));
            (side ? sfi : sfj)[t] = f;
        }
        __syncthreads();
    }

    float xb[16]; float s = 0.f, ss = 0.f;
    #pragma unroll
    for (int i = 0; i < 16; i++) {
        int id = t + i * 256;
        int p = id >> 6, q = id & 63;
        float v = sGj[p * 64 + q] * sfj[p] + sGi[q * 65 + p] * sfi[q];
        xb[i] = v; s += v; ss += v * v;
    }
    red[t] = s; red2[t] = ss; __syncthreads();
    for (int off = 128; off > 0; off >>= 1) {
        if (t < off) { red[t] += red[t + off]; red2[t] += red2[t + off]; }
        __syncthreads();
    }
    float n = 4096.f;
    float mean = red[0] / n;
    float var  = (red2[0] - red[0] * red[0] / n) / (n - 1.f);
    float istd = 1.f / (sqrtf(var) + 1e-5f);
    float* ob = g_xbd + (size_t)(d * Bsz + b) * 4096;
    #pragma unroll
    for (int i = 0; i < 16; i++)
        ob[t + i * 256] = (xb[i] - mean) * istd * xstd + xmean;
}

// ---------------- accumulate per-depth contributions (fixed d order) ---------
__global__ void __launch_bounds__(256) accum_kernel(float* __restrict__ out) {
    int i = blockIdx.x * 256 + threadIdx.x;      // 0 .. Bsz*4096-1
    int b = i >> 12, idx = i & 4095;
    float s = 0.f;
    #pragma unroll
    for (int d = 0; d < ND; d++)
        s += g_xbd[(size_t)(d * Bsz + b) * 4096 + idx];
    out[i] = s;
}

// ---------------- launcher ---------------------------------------------------
extern "C" void kernel_launch(void* const* d_in, const int* in_sizes, int n_in,
                              void* d_out, int out_size) {
    const float* x        = (const float*)d_in[0];
    const float* o_xj     = (const float*)d_in[1];
    const float* o_xi     = (const float*)d_in[2];
    const float* p_xj     = (const float*)d_in[3];
    const float* p_xi     = (const float*)d_in[4];
    const float* o_rel_xj = (const float*)d_in[5];
    const float* o_rel_xi = (const float*)d_in[6];
    const float* p_rel_xj = (const float*)d_in[7];
    const float* p_rel_xi = (const float*)d_in[8];
    float* out = (float*)d_out;

    cudaFuncSetAttribute(final_depth, cudaFuncAttributeMaxDynamicSharedMemorySize,
                         FINAL_SMEM_FLOATS * sizeof(float));
    cudaFuncSetAttribute(gemm_mma, cudaFuncAttributeMaxDynamicSharedMemorySize,
                         GEMM_DYNSM);
    cudaFuncSetAttribute(stage2_mma, cudaFuncAttributeMaxDynamicSharedMemorySize,
                         S2_DYNSM);

    // gemm_mma is launch #4 so ncu (-s 5 -c 1) profiles it
    convw_kernel<<<dim3(512, 2), 256>>>(o_xj, o_rel_xj, o_xi, o_rel_xi);
    convp_kernel<<<dim3(512, 2), 256>>>(p_xj, p_xi);
    convx_kernel<<<dim3(16, Bsz), 256>>>(x);
    gemm_mma<<<dim3(16, Bsz, 2), 256, GEMM_DYNSM>>>();
    stats_reduce<<<Bsz, 32>>>();
    csred_kernel<<<256, 256>>>();
    stage2_mma<<<dim3(ND, 2, Bsz), 128, S2_DYNSM>>>();
    final_depth<<<dim3(ND, Bsz), 256, FINAL_SMEM_FLOATS * sizeof(float)>>>(p_rel_xj, p_rel_xi);
    accum_kernel<<<Bsz * 4096 / 256, 256>>>(out);
}

// round 13
// speedup vs baseline: 6.7846x; 1.0065x over previous
#include <cuda_runtime.h>
#include <cuda_fp16.h>
#include <math.h>
#include <stdint.h>

#define Bsz  128
#define HW   512
#define Pp   64
#define ND   4
#define HWHW 262144

// ---------------- scratch (static device globals) ---------------------------
__device__ float g_G  [2 * Bsz * ND * Pp * Pp];
__device__ float g_cs [2 * Bsz * ND * Pp];
__device__ float g_csp[2 * Bsz * 2 * 4 * 2 * 128];   // [z][b][nt2][mt][wm][128]
__device__ float2 g_statp[Bsz * 16];                 // per-chunk (sum, sumsq)
__device__ float g_meanv[Bsz];
__device__ float g_stdv [Bsz];
__device__ float g_xbd [ND * Bsz * 4096];            // per-depth normalized contribs

__device__ __half g_xf [33554432];   // fp16 x (row-major; also serves x^T GEMM)
__device__ __half g_w1f[262144];     // gemm1 weights, [n][k]
__device__ __half g_w2f[262144];     // gemm2 weights
// o-halves of the two GEMMs, [b][k=512][m=256], fp16
__device__ __half g_ojf[16777216];
__device__ __half g_oif[16777216];
// p weights, [d][k=512][n=64], fp16
__device__ __half g_pjf[131072];
__device__ __half g_pif[131072];

// ---------------- helpers (plain sm_103-legal PTX) ---------------------------
__device__ __forceinline__ uint32_t smem_u32(const void* p) {
    uint32_t a;
    asm("{ .reg .u64 t; cvta.to.shared.u64 t, %1; cvt.u32.u64 %0, t; }" : "=r"(a) : "l"(p));
    return a;
}
#define CP_ASYNC16(dst, src) \
    asm volatile("cp.async.cg.shared.global [%0], [%1], 16;" :: "r"(dst), "l"(src))
#define CP_COMMIT() asm volatile("cp.async.commit_group;" ::: "memory")
#define CP_WAIT(n)  asm volatile("cp.async.wait_group %0;" :: "n"(n) : "memory")

__device__ __forceinline__ void ldm_x4(uint32_t* r, uint32_t addr) {
    asm volatile("ldmatrix.sync.aligned.m8n8.x4.shared.b16 {%0,%1,%2,%3}, [%4];"
                 : "=r"(r[0]), "=r"(r[1]), "=r"(r[2]), "=r"(r[3]) : "r"(addr));
}
__device__ __forceinline__ void ldm_x4t(uint32_t* r, uint32_t addr) {
    asm volatile("ldmatrix.sync.aligned.m8n8.x4.trans.shared.b16 {%0,%1,%2,%3}, [%4];"
                 : "=r"(r[0]), "=r"(r[1]), "=r"(r[2]), "=r"(r[3]) : "r"(addr));
}
__device__ __forceinline__ void mma16816f(float* c, const uint32_t* a, const uint32_t* b) {
    asm volatile(
        "mma.sync.aligned.m16n8k16.row.col.f32.f16.f16.f32 "
        "{%0,%1,%2,%3}, {%4,%5,%6,%7}, {%8,%9}, {%0,%1,%2,%3};"
        : "+f"(c[0]), "+f"(c[1]), "+f"(c[2]), "+f"(c[3])
        : "r"(a[0]), "r"(a[1]), "r"(a[2]), "r"(a[3]), "r"(b[0]), "r"(b[1]));
}
#define SWZ(o) ((o) ^ (((o) >> 3) & 0x70))

// ---------------- prep: big-GEMM weights -> [n][k] fp16 ----------------------
__global__ void __launch_bounds__(256) convw_kernel(const float* __restrict__ o_xj,
                                                    const float* __restrict__ o_rel_xj,
                                                    const float* __restrict__ o_xi,
                                                    const float* __restrict__ o_rel_xi) {
    int n = blockIdx.x, side = blockIdx.y, t = threadIdx.x;
    const float* w = (side == 0) ? ((n < 256) ? o_xj : o_rel_xj)
                                 : ((n < 256) ? o_xi : o_rel_xi);
    int nn = n & 255, d = nn >> 6, c = nn & 63;
    __half* of = side ? g_w2f : g_w1f;
    #pragma unroll
    for (int i = 0; i < 2; i++) {
        int k = t + i * 256;
        of[n * HW + k] = __float2half_rn(w[d * (HW * Pp) + k * Pp + c]);
    }
}

// ---------------- prep: p weights -> fp16 ([d][k][n] layout) -----------------
__global__ void __launch_bounds__(256) convp_kernel(const float* __restrict__ p_xj,
                                                    const float* __restrict__ p_xi) {
    int i = blockIdx.x * 256 + threadIdx.x;     // 0..131071
    int side = blockIdx.y;
    const float* src = side ? p_xi : p_xj;
    __half* of = side ? g_pif : g_pjf;
    of[i] = __float2half_rn(src[i]);
}

// ---------------- prep: x -> fp16 (row-major only) + stat partials -----------
__global__ void __launch_bounds__(256) convx_kernel(const float* __restrict__ x) {
    __shared__ float rs[256], rq[256];
    int b = blockIdx.y, chunk = blockIdx.x;     // 16 chunks of 16384 floats
    int t = threadIdx.x;
    size_t base = (size_t)b * HWHW + (size_t)chunk * 16384;
    const float4* src = (const float4*)(x + base);
    __half2* dst = (__half2*)(g_xf + base);
    float ps = 0.f, pq = 0.f;
    #pragma unroll
    for (int i = 0; i < 16; i++) {
        int idx = t + i * 256;
        float4 v = src[idx];
        ps += v.x + v.y + v.z + v.w;
        pq += v.x * v.x + v.y * v.y + v.z * v.z + v.w * v.w;
        dst[idx * 2]     = __floats2half2_rn(v.x, v.y);
        dst[idx * 2 + 1] = __floats2half2_rn(v.z, v.w);
    }
    rs[t] = ps; rq[t] = pq;
    for (int off = 128; off > 0; off >>= 1) {
        __syncthreads();
        if (t < off) { rs[t] += rs[t + off]; rq[t] += rq[t + off]; }
    }
    if (t == 0) g_statp[b * 16 + chunk] = make_float2(rs[0], rq[0]);
}

// ---------------- stats: fold per-chunk partials ------------------------------
__global__ void __launch_bounds__(32) stats_reduce() {
    int b = blockIdx.x, t = threadIdx.x;
    float s = 0.f, q = 0.f;
    if (t < 16) { float2 p = g_statp[b * 16 + t]; s = p.x; q = p.y; }
    #pragma unroll
    for (int o = 8; o > 0; o >>= 1) {
        s += __shfl_down_sync(0xFFFFFFFFu, s, o);
        q += __shfl_down_sync(0xFFFFFFFFu, q, o);
    }
    if (t == 0) {
        float n = (float)HWHW;
        float mean = s / n;
        float var  = (q - s * s / n) / (n - 1.f);
        g_meanv[b] = mean * 64.f;
        g_stdv[b]  = sqrtf(var) * 64.f;
    }
}

// ---------------- mma.sync GEMM: X @ Wcat (single-pass fp16) -----------------
// CTA 128x128, warps 2(M)x4(N), warp tile 64x32, K chunks 64, 3-stage pipeline.
// Single barrier per chunk: wait -> sync -> prefetch(kt+2) -> compute(kt).
#define STG_BYTES 32768
#define NSTG 3
#define OFF_A 0
#define OFF_B 16384
#define GEMM_DYNSM (NSTG * STG_BYTES)

__global__ void __launch_bounds__(256, 2) gemm_mma() {
    extern __shared__ __align__(16) unsigned char smp[];
    uint32_t sbase = smem_u32(smp);

    int t = threadIdx.x, lane = t & 31, w = t >> 5;
    int wm = w >> 2, wn = w & 3;
    int mt = blockIdx.x >> 2, nt = blockIdx.x & 3;
    int b = blockIdx.y, z = blockIdx.z;
    int m0 = mt * 128, n0 = nt * 128;

    const __half* xs = g_xf + (size_t)b * HWHW;
    const __half* ws = z ? g_w2f : g_w1f;

    // ---- per-thread cp.async descriptors (chunk-invariant) ----
    const __half* asrc[4]; uint32_t adst[4];
    const __half* bsrc[4]; uint32_t bdst[4];
    size_t astep = (z == 0) ? 64 : (size_t)64 * HW;
    #pragma unroll
    for (int i = 0; i < 4; i++) {
        int u = t + i * 256;
        int row = u >> 3, seg = u & 7;
        if (z == 0) {
            adst[i] = OFF_A + SWZ(row * 128 + seg * 16);
            asrc[i] = xs + (size_t)(m0 + row) * HW + seg * 8;
        } else {
            int mh = u >> 9, k = (u >> 3) & 63;
            adst[i] = OFF_A + mh * 8192 + SWZ(k * 128 + seg * 16);
            asrc[i] = xs + (size_t)k * HW + m0 + mh * 64 + seg * 8;
        }
        bdst[i] = OFF_B + SWZ(row * 128 + seg * 16);
        bsrc[i] = ws + (size_t)(n0 + row) * HW + seg * 8;
    }

    // ---- per-thread ldmatrix address components (hoisted swizzle) ----
    // SWZ(R*128 + C) = R*128 + (C ^ ((R&7)<<4)) for C < 128
    int a_row = (lane & 15), a_cb = (lane >> 4) * 16;
    int a_rT  = (lane & 7) + ((lane >> 4) & 1) * 8;
    int a_cT  = ((lane >> 3) & 1) * 16;
    int b_row = (lane & 7) + ((lane >> 4) & 1) * 8;
    int b_cb  = ((lane >> 3) & 1) * 16;

    uint32_t aRow0, aColk[4];      // z=0: addr = tb + aRow0 + mi*2048 + aColk[ks]
    uint32_t aRowT[4], aColT0;     // z=1: addr = tb + wm*8192 + aRowT[ks] + aColT0 + mi-term
    uint32_t aMaskT;
    if (z == 0) {
        aRow0 = OFF_A + (uint32_t)((wm * 64 + a_row) * 128);
        uint32_t m = (uint32_t)((a_row & 7) << 4);
        #pragma unroll
        for (int ks = 0; ks < 4; ks++) aColk[ks] = ((uint32_t)(ks * 32 + a_cb)) ^ m;
        aRowT[0] = aRowT[1] = aRowT[2] = aRowT[3] = 0; aColT0 = 0; aMaskT = 0;
    } else {
        aMaskT = (uint32_t)((a_rT & 7) << 4);
        #pragma unroll
        for (int ks = 0; ks < 4; ks++) aRowT[ks] = OFF_A + (uint32_t)((ks * 16 + a_rT) * 128);
        aColT0 = ((uint32_t)a_cT) ^ aMaskT;   // mi*32 is >= bit5 and xor-mask only bits [6:4]:
        // (mi*32 + a_cT) ^ m == (a_cT ^ m) + mi*32 only when no bit collision between mi*32
        // and m in bits [5:6]; m has bits [4:6], mi*32 has bits [5:6] -> collision possible.
        // So compute full per-mi column terms instead:
        aRow0 = 0; aColk[0] = aColk[1] = aColk[2] = aColk[3] = 0;
    }
    uint32_t aColTmi[4];
    if (z != 0) {
        #pragma unroll
        for (int mi = 0; mi < 4; mi++) aColTmi[mi] = ((uint32_t)(mi * 32 + a_cT)) ^ aMaskT;
    } else {
        aColTmi[0] = aColTmi[1] = aColTmi[2] = aColTmi[3] = 0;
    }
    uint32_t bRow[2], bColk[4];
    {
        uint32_t m = (uint32_t)((b_row & 7) << 4);
        #pragma unroll
        for (int np = 0; np < 2; np++)
            bRow[np] = OFF_B + (uint32_t)((wn * 32 + np * 16 + b_row) * 128);
        #pragma unroll
        for (int ks = 0; ks < 4; ks++) bColk[ks] = ((uint32_t)(ks * 32 + b_cb)) ^ m;
    }

    float acc[4][4][4];
    #pragma unroll
    for (int mi = 0; mi < 4; mi++)
        #pragma unroll
        for (int ni = 0; ni < 4; ni++)
            #pragma unroll
            for (int q = 0; q < 4; q++) acc[mi][ni][q] = 0.f;

    // prologue: issue chunks 0 and 1
    #pragma unroll
    for (int c = 0; c < 2; c++) {
        uint32_t tb = sbase + c * STG_BYTES;
        #pragma unroll
        for (int i = 0; i < 4; i++) {
            CP_ASYNC16(tb + adst[i], asrc[i] + (size_t)c * astep);
            CP_ASYNC16(tb + bdst[i], bsrc[i] + (size_t)c * 64);
        }
        CP_COMMIT();
    }

    #pragma unroll 1
    for (int kt = 0; kt < 8; kt++) {
        if (kt < 7) { CP_WAIT(1); } else { CP_WAIT(0); }
        __syncthreads();

        if (kt + 2 < 8) {
            uint32_t tb = sbase + ((kt + 2) % NSTG) * STG_BYTES;
            int c = kt + 2;
            #pragma unroll
            for (int i = 0; i < 4; i++) {
                CP_ASYNC16(tb + adst[i], asrc[i] + (size_t)c * astep);
                CP_ASYNC16(tb + bdst[i], bsrc[i] + (size_t)c * 64);
            }
            CP_COMMIT();
        }

        uint32_t tb = sbase + (kt % NSTG) * STG_BYTES;
        uint32_t tbw = tb + wm * 8192;   // z=1 half select
        #pragma unroll
        for (int ks = 0; ks < 4; ks++) {
            uint32_t ah[4][4], bh[4][2];
            if (z == 0) {
                uint32_t base = tb + aRow0 + aColk[ks];
                #pragma unroll
                for (int mi = 0; mi < 4; mi++)
                    ldm_x4(ah[mi], base + mi * 2048);
            } else {
                uint32_t base = tbw + aRowT[ks];
                #pragma unroll
                for (int mi = 0; mi < 4; mi++)
                    ldm_x4t(ah[mi], base + aColTmi[mi]);
            }
            #pragma unroll
            for (int np = 0; np < 2; np++) {
                uint32_t rh[4];
                ldm_x4(rh, tb + bRow[np] + bColk[ks]);
                bh[np * 2][0] = rh[0]; bh[np * 2][1] = rh[1];
                bh[np * 2 + 1][0] = rh[2]; bh[np * 2 + 1][1] = rh[3];
            }
            #pragma unroll
            for (int mi = 0; mi < 4; mi++)
                #pragma unroll
                for (int ni = 0; ni < 4; ni++)
                    mma16816f(acc[mi][ni], ah[mi], bh[ni]);
        }
    }
    __syncthreads();

    int gq = lane >> 2, tig = lane & 3;
    if (nt < 2) {
        // o-half: fp16, layout [b][k=row][m=col(0..255)]
        __half* of = z ? g_oif : g_ojf;
        size_t bb = (size_t)b * (512 * 256);
        #pragma unroll
        for (int mi = 0; mi < 4; mi++) {
            int row0 = m0 + wm * 64 + mi * 16 + gq;
            #pragma unroll
            for (int ni = 0; ni < 4; ni++) {
                int col = nt * 128 + wn * 32 + ni * 8 + tig * 2;
                *(__half2*)&of[bb + (size_t)row0 * 256 + col] =
                    __floats2half2_rn(acc[mi][ni][0], acc[mi][ni][1]);
                *(__half2*)&of[bb + (size_t)(row0 + 8) * 256 + col] =
                    __floats2half2_rn(acc[mi][ni][2], acc[mi][ni][3]);
            }
        }
    } else {
        // rel-half: exp colsum partials (deterministic slots per CTA/warp)
        size_t p = ((((size_t)(z * Bsz + b) * 2 + (nt - 2)) * 4 + mt) * 2 + wm) * 128;
        #pragma unroll
        for (int ni = 0; ni < 4; ni++) {
            float s0 = 0.f, s1 = 0.f;
            #pragma unroll
            for (int mi = 0; mi < 4; mi++) {
                s0 += expf(acc[mi][ni][0]) + expf(acc[mi][ni][2]);
                s1 += expf(acc[mi][ni][1]) + expf(acc[mi][ni][3]);
            }
            #pragma unroll
            for (int o = 4; o < 32; o <<= 1) {
                s0 += __shfl_xor_sync(0xFFFFFFFFu, s0, o);
                s1 += __shfl_xor_sync(0xFFFFFFFFu, s1, o);
            }
            if (gq == 0) {
                int cl = wn * 32 + ni * 8 + tig * 2;
                g_csp[p + cl]     = s0;
                g_csp[p + cl + 1] = s1;
            }
        }
    }
}

// ---------------- fold colsum partials ---------------------------------------
__global__ void __launch_bounds__(256) csred_kernel() {
    int i = blockIdx.x * 256 + threadIdx.x;     // 0..65535
    int side = i >> 15;
    int r = i & 32767;
    int b = r >> 8;
    int dc = r & 255;
    int d = dc >> 6, c = dc & 63;
    int nt2 = d >> 1;
    int cl = (d & 1) * 64 + c;
    size_t base = (((size_t)(side * Bsz + b) * 2 + nt2) * 4) * 2 * 128;
    float s = 0.f;
    #pragma unroll
    for (int mtw = 0; mtw < 8; mtw++) s += g_csp[base + (size_t)mtw * 128 + cl];
    g_cs[((side * Bsz + b) * ND + d) * 64 + c] = s;
}

// ---------------- stage-2 via mma: G = A_o^T @ p_x  (64x64, K=512) -----------
#define S2_STG 16384
#define S2_A 0
#define S2_W 8192
#define S2_DYNSM (2 * S2_STG)

__global__ void __launch_bounds__(128) stage2_mma() {
    extern __shared__ __align__(16) unsigned char smp2[];
    uint32_t sbase = smem_u32(smp2);

    int t = threadIdx.x, lane = t & 31, wn = t >> 5;   // 4 warps, each 16 N-cols
    int d = blockIdx.x, side = blockIdx.y, b = blockIdx.z;

    const __half* A = (side ? g_oif : g_ojf) + (size_t)b * (512 * 256) + d * 64;
    const __half* W = (side ? g_pif : g_pjf) + (size_t)d * (512 * 64);

    int a_r = (lane & 7) + ((lane >> 4) & 1) * 8;   // k within 16
    int a_c = ((lane >> 3) & 1) * 16;               // m byte within 32
    int w_r = (lane & 7) + ((lane >> 3) & 1) * 8;   // k within 16
    int w_c = ((lane >> 4) & 1) * 16;               // n byte within 32

    float acc[4][2][4];
    #pragma unroll
    for (int mi = 0; mi < 4; mi++)
        #pragma unroll
        for (int ni = 0; ni < 2; ni++)
            #pragma unroll
            for (int q = 0; q < 4; q++) acc[mi][ni][q] = 0.f;

    {
        uint32_t tb = sbase;
        #pragma unroll
        for (int i = 0; i < 4; i++) {
            int u = t + i * 128;
            int row = u >> 3, seg = u & 7;
            uint32_t so = SWZ(row * 128 + seg * 16);
            CP_ASYNC16(tb + S2_A + so, A + (size_t)row * 256 + seg * 8);
            CP_ASYNC16(tb + S2_W + so, W + (size_t)row * 64 + seg * 8);
        }
        CP_COMMIT();
    }

    #pragma unroll 1
    for (int kt = 0; kt < 8; kt++) {
        if (kt + 1 < 8) {
            uint32_t tb = sbase + ((kt + 1) & 1) * S2_STG;
            int k0 = (kt + 1) * 64;
            #pragma unroll
            for (int i = 0; i < 4; i++) {
                int u = t + i * 128;
                int row = u >> 3, seg = u & 7;
                uint32_t so = SWZ(row * 128 + seg * 16);
                CP_ASYNC16(tb + S2_A + so, A + (size_t)(k0 + row) * 256 + seg * 8);
                CP_ASYNC16(tb + S2_W + so, W + (size_t)(k0 + row) * 64 + seg * 8);
            }
            CP_COMMIT();
            CP_WAIT(1);
        } else {
            CP_WAIT(0);
        }
        __syncthreads();

        uint32_t tb = sbase + (kt & 1) * S2_STG;
        #pragma unroll
        for (int ks = 0; ks < 4; ks++) {
            uint32_t ah[4][4], wh[2][2];
            #pragma unroll
            for (int mi = 0; mi < 4; mi++) {
                uint32_t off = SWZ((uint32_t)((ks * 16 + a_r) * 128 + mi * 32 + a_c));
                ldm_x4t(ah[mi], tb + S2_A + off);
            }
            {
                uint32_t off = SWZ((uint32_t)((ks * 16 + w_r) * 128 + wn * 32 + w_c));
                uint32_t rh[4];
                ldm_x4t(rh, tb + S2_W + off);
                wh[0][0] = rh[0]; wh[0][1] = rh[1]; wh[1][0] = rh[2]; wh[1][1] = rh[3];
            }
            #pragma unroll
            for (int mi = 0; mi < 4; mi++)
                #pragma unroll
                for (int ni = 0; ni < 2; ni++)
                    mma16816f(acc[mi][ni], ah[mi], wh[ni]);
        }
        __syncthreads();
    }

    float* g = g_G + (size_t)((side * Bsz + b) * ND + d) * 4096;
    int gq = lane >> 2, tig = lane & 3;
    #pragma unroll
    for (int mi = 0; mi < 4; mi++) {
        int m = mi * 16 + gq;
        #pragma unroll
        for (int ni = 0; ni < 2; ni++) {
            int n = wn * 16 + ni * 8 + tig * 2;
            *(float2*)&g[m * 64 + n]       = make_float2(acc[mi][ni][0], acc[mi][ni][1]);
            *(float2*)&g[(m + 8) * 64 + n] = make_float2(acc[mi][ni][2], acc[mi][ni][3]);
        }
    }
}

// ---------------- final: one CTA per (d, b) ----------------------------------
#define FINAL_SMEM_FLOATS (4096 + 4160 + 4096 + 256 + 256 + 64 + 64 + 64 + 64 + 16)

__global__ void __launch_bounds__(256) final_depth(const float* __restrict__ p_rel_xj,
                                                   const float* __restrict__ p_rel_xi) {
    extern __shared__ float sm[];
    float* sGj  = sm;
    float* sGi  = sGj + 4096;   // 64x65 padded
    float* sWR  = sGi + 4160;
    float* red  = sWR + 4096;
    float* red2 = red + 256;
    float* sfj  = red2 + 256;
    float* sfi  = sfj + 64;
    float* sCS  = sfi + 64;
    float* sOCS = sCS + 64;
    float* sTOT = sOCS + 64;    // [0]=p total, [1]=o total

    int d = blockIdx.x, b = blockIdx.y, t = threadIdx.x;
    float xmean = g_meanv[b], xstd = g_stdv[b];

    int prw = (t >> 4) * 4, qcw = (t & 15) * 4;
    int col = t & 63, grp = t >> 6;

    #pragma unroll
    for (int i = 0; i < 16; i++) {
        int id = t + i * 256;
        int p = id >> 6, q = id & 63;
        sGj[p * 64 + q] = g_G[(size_t)((0 * Bsz + b) * ND + d) * 4096 + id];
        sGi[p * 65 + q] = g_G[(size_t)((1 * Bsz + b) * ND + d) * 4096 + id];
    }
    __syncthreads();

    for (int side = 0; side < 2; side++) {
        const float* prel = (side == 0 ? p_rel_xj : p_rel_xi) + d * 4096;
        #pragma unroll
        for (int i = 0; i < 16; i++) sWR[t + i * 256] = prel[t + i * 256];
        if (t < 64) sOCS[t] = g_cs[((side * Bsz + b) * ND + d) * 64 + t];
        __syncthreads();

        const float* G = side ? sGi : sGj;
        int gs = side ? 65 : 64;
        float acc[4][4];
        #pragma unroll
        for (int i = 0; i < 4; i++)
            #pragma unroll
            for (int j = 0; j < 4; j++) acc[i][j] = 0.f;
        #pragma unroll 8
        for (int kk = 0; kk < 64; kk++) {
            float a0 = G[(prw + 0) * gs + kk];
            float a1 = G[(prw + 1) * gs + kk];
            float a2 = G[(prw + 2) * gs + kk];
            float a3 = G[(prw + 3) * gs + kk];
            float4 w4 = *(const float4*)&sWR[kk * 64 + qcw];
            acc[0][0] = fmaf(a0, w4.x, acc[0][0]); acc[0][1] = fmaf(a0, w4.y, acc[0][1]);
            acc[0][2] = fmaf(a0, w4.z, acc[0][2]); acc[0][3] = fmaf(a0, w4.w, acc[0][3]);
            acc[1][0] = fmaf(a1, w4.x, acc[1][0]); acc[1][1] = fmaf(a1, w4.y, acc[1][1]);
            acc[1][2] = fmaf(a1, w4.z, acc[1][2]); acc[1][3] = fmaf(a1, w4.w, acc[1][3]);
            acc[2][0] = fmaf(a2, w4.x, acc[2][0]); acc[2][1] = fmaf(a2, w4.y, acc[2][1]);
            acc[2][2] = fmaf(a2, w4.z, acc[2][2]); acc[2][3] = fmaf(a2, w4.w, acc[2][3]);
            acc[3][0] = fmaf(a3, w4.x, acc[3][0]); acc[3][1] = fmaf(a3, w4.y, acc[3][1]);
            acc[3][2] = fmaf(a3, w4.z, acc[3][2]); acc[3][3] = fmaf(a3, w4.w, acc[3][3]);
        }
        __syncthreads();
        #pragma unroll
        for (int i = 0; i < 4; i++)
            #pragma unroll
            for (int j = 0; j < 4; j++)
                sWR[(prw + i) * 64 + qcw + j] = expf(acc[i][j]);
        __syncthreads();

        float s = 0.f;
        #pragma unroll
        for (int r = 0; r < 16; r++) s += sWR[(grp * 16 + r) * 64 + col];
        red[t] = s; __syncthreads();
        if (t < 64) sCS[t] = red[t] + red[t + 64] + red[t + 128] + red[t + 192];
        __syncthreads();
        if (t == 0) {
            float tp = 0.f, to = 0.f;
            for (int i = 0; i < 64; i++) { tp += sCS[i]; to += sOCS[i]; }
            sTOT[0] = tp; sTOT[1] = to;
        }
        __syncthreads();
        if (t < 64) {
            float f = sqrtf((sOCS[t] * sTOT[0]) / (sTOT[1] * sCS[t]));
            (side ? sfi : sfj)[t] = f;
        }
        __syncthreads();
    }

    float xb[16]; float s = 0.f, ss = 0.f;
    #pragma unroll
    for (int i = 0; i < 16; i++) {
        int id = t + i * 256;
        int p = id >> 6, q = id & 63;
        float v = sGj[p * 64 + q] * sfj[p] + sGi[q * 65 + p] * sfi[q];
        xb[i] = v; s += v; ss += v * v;
    }
    red[t] = s; red2[t] = ss; __syncthreads();
    for (int off = 128; off > 0; off >>= 1) {
        if (t < off) { red[t] += red[t + off]; red2[t] += red2[t + off]; }
        __syncthreads();
    }
    float n = 4096.f;
    float mean = red[0] / n;
    float var  = (red2[0] - red[0] * red[0] / n) / (n - 1.f);
    float istd = 1.f / (sqrtf(var) + 1e-5f);
    float* ob = g_xbd + (size_t)(d * Bsz + b) * 4096;
    #pragma unroll
    for (int i = 0; i < 16; i++)
        ob[t + i * 256] = (xb[i] - mean) * istd * xstd + xmean;
}

// ---------------- accumulate per-depth contributions (fixed d order) ---------
__global__ void __launch_bounds__(256) accum_kernel(float* __restrict__ out) {
    int i = blockIdx.x * 256 + threadIdx.x;      // 0 .. Bsz*4096-1
    int b = i >> 12, idx = i & 4095;
    float s = 0.f;
    #pragma unroll
    for (int d = 0; d < ND; d++)
        s += g_xbd[(size_t)(d * Bsz + b) * 4096 + idx];
    out[i] = s;
}

// ---------------- launcher ---------------------------------------------------
extern "C" void kernel_launch(void* const* d_in, const int* in_sizes, int n_in,
                              void* d_out, int out_size) {
    const float* x        = (const float*)d_in[0];
    const float* o_xj     = (const float*)d_in[1];
    const float* o_xi     = (const float*)d_in[2];
    const float* p_xj     = (const float*)d_in[3];
    const float* p_xi     = (const float*)d_in[4];
    const float* o_rel_xj = (const float*)d_in[5];
    const float* o_rel_xi = (const float*)d_in[6];
    const float* p_rel_xj = (const float*)d_in[7];
    const float* p_rel_xi = (const float*)d_in[8];
    float* out = (float*)d_out;

    cudaFuncSetAttribute(final_depth, cudaFuncAttributeMaxDynamicSharedMemorySize,
                         FINAL_SMEM_FLOATS * sizeof(float));
    cudaFuncSetAttribute(gemm_mma, cudaFuncAttributeMaxDynamicSharedMemorySize,
                         GEMM_DYNSM);
    cudaFuncSetAttribute(stage2_mma, cudaFuncAttributeMaxDynamicSharedMemorySize,
                         S2_DYNSM);

    // gemm_mma is launch #4 so ncu (-s 5 -c 1) profiles it
    convw_kernel<<<dim3(512, 2), 256>>>(o_xj, o_rel_xj, o_xi, o_rel_xi);
    convp_kernel<<<dim3(512, 2), 256>>>(p_xj, p_xi);
    convx_kernel<<<dim3(16, Bsz), 256>>>(x);
    gemm_mma<<<dim3(16, Bsz, 2), 256, GEMM_DYNSM>>>();
    stats_reduce<<<Bsz, 32>>>();
    csred_kernel<<<256, 256>>>();
    stage2_mma<<<dim3(ND, 2, Bsz), 128, S2_DYNSM>>>();
    final_depth<<<dim3(ND, Bsz), 256, FINAL_SMEM_FLOATS * sizeof(float)>>>(p_rel_xj, p_rel_xi);
    accum_kernel<<<Bsz * 4096 / 256, 256>>>(out);
}

// round 14
// speedup vs baseline: 7.1606x; 1.0554x over previous
#include <cuda_runtime.h>
#include <cuda_fp16.h>
#include <math.h>
#include <stdint.h>

#define Bsz  128
#define HW   512
#define Pp   64
#define ND   4
#define HWHW 262144

// ---------------- scratch (static device globals) ---------------------------
__device__ float g_G  [2 * Bsz * ND * Pp * Pp];
__device__ float g_cs [2 * Bsz * ND * Pp];
__device__ float g_csp[2 * Bsz * 2 * 4 * 2 * 128];   // [z][b][nt2][mt][wm][128]
__device__ float2 g_statp[Bsz * 16];                 // per-chunk (sum, sumsq)
__device__ float g_meanv[Bsz];
__device__ float g_stdv [Bsz];
__device__ float g_xbd [ND * Bsz * 4096];            // per-depth normalized contribs

__device__ __half g_xf [33554432];   // fp16 x (row-major; also serves x^T GEMM)
__device__ __half g_w1f[262144];     // gemm1 weights, [n][k]
__device__ __half g_w2f[262144];     // gemm2 weights
// o-halves of the two GEMMs, [b][k=512][m=256], fp16
__device__ __half g_ojf[16777216];
__device__ __half g_oif[16777216];
// p weights, [d][k=512][n=64], fp16
__device__ __half g_pjf[131072];
__device__ __half g_pif[131072];

// ---------------- helpers (plain sm_103-legal PTX) ---------------------------
__device__ __forceinline__ uint32_t smem_u32(const void* p) {
    uint32_t a;
    asm("{ .reg .u64 t; cvta.to.shared.u64 t, %1; cvt.u32.u64 %0, t; }" : "=r"(a) : "l"(p));
    return a;
}
#define CP_ASYNC16(dst, src) \
    asm volatile("cp.async.cg.shared.global [%0], [%1], 16;" :: "r"(dst), "l"(src))
#define CP_COMMIT() asm volatile("cp.async.commit_group;" ::: "memory")
#define CP_WAIT(n)  asm volatile("cp.async.wait_group %0;" :: "n"(n) : "memory")

__device__ __forceinline__ void ldm_x4(uint32_t* r, uint32_t addr) {
    asm volatile("ldmatrix.sync.aligned.m8n8.x4.shared.b16 {%0,%1,%2,%3}, [%4];"
                 : "=r"(r[0]), "=r"(r[1]), "=r"(r[2]), "=r"(r[3]) : "r"(addr));
}
__device__ __forceinline__ void ldm_x4t(uint32_t* r, uint32_t addr) {
    asm volatile("ldmatrix.sync.aligned.m8n8.x4.trans.shared.b16 {%0,%1,%2,%3}, [%4];"
                 : "=r"(r[0]), "=r"(r[1]), "=r"(r[2]), "=r"(r[3]) : "r"(addr));
}
__device__ __forceinline__ void mma16816f(float* c, const uint32_t* a, const uint32_t* b) {
    asm volatile(
        "mma.sync.aligned.m16n8k16.row.col.f32.f16.f16.f32 "
        "{%0,%1,%2,%3}, {%4,%5,%6,%7}, {%8,%9}, {%0,%1,%2,%3};"
        : "+f"(c[0]), "+f"(c[1]), "+f"(c[2]), "+f"(c[3])
        : "r"(a[0]), "r"(a[1]), "r"(a[2]), "r"(a[3]), "r"(b[0]), "r"(b[1]));
}
#define SWZ(o) ((o) ^ (((o) >> 3) & 0x70))

// ---------------- prep: big-GEMM weights -> [n][k] fp16 ----------------------
__global__ void __launch_bounds__(256) convw_kernel(const float* __restrict__ o_xj,
                                                    const float* __restrict__ o_rel_xj,
                                                    const float* __restrict__ o_xi,
                                                    const float* __restrict__ o_rel_xi) {
    int n = blockIdx.x, side = blockIdx.y, t = threadIdx.x;
    const float* w = (side == 0) ? ((n < 256) ? o_xj : o_rel_xj)
                                 : ((n < 256) ? o_xi : o_rel_xi);
    int nn = n & 255, d = nn >> 6, c = nn & 63;
    __half* of = side ? g_w2f : g_w1f;
    #pragma unroll
    for (int i = 0; i < 2; i++) {
        int k = t + i * 256;
        of[n * HW + k] = __float2half_rn(w[d * (HW * Pp) + k * Pp + c]);
    }
}

// ---------------- prep: p weights -> fp16 ([d][k][n] layout) -----------------
__global__ void __launch_bounds__(256) convp_kernel(const float* __restrict__ p_xj,
                                                    const float* __restrict__ p_xi) {
    int i = blockIdx.x * 256 + threadIdx.x;     // 0..131071
    int side = blockIdx.y;
    const float* src = side ? p_xi : p_xj;
    __half* of = side ? g_pif : g_pjf;
    of[i] = __float2half_rn(src[i]);
}

// ---------------- prep: x -> fp16 (row-major only) + stat partials -----------
__global__ void __launch_bounds__(256) convx_kernel(const float* __restrict__ x) {
    __shared__ float rs[256], rq[256];
    int b = blockIdx.y, chunk = blockIdx.x;     // 16 chunks of 16384 floats
    int t = threadIdx.x;
    size_t base = (size_t)b * HWHW + (size_t)chunk * 16384;
    const float4* src = (const float4*)(x + base);
    __half2* dst = (__half2*)(g_xf + base);
    float ps = 0.f, pq = 0.f;
    #pragma unroll
    for (int i = 0; i < 16; i++) {
        int idx = t + i * 256;
        float4 v = src[idx];
        ps += v.x + v.y + v.z + v.w;
        pq += v.x * v.x + v.y * v.y + v.z * v.z + v.w * v.w;
        dst[idx * 2]     = __floats2half2_rn(v.x, v.y);
        dst[idx * 2 + 1] = __floats2half2_rn(v.z, v.w);
    }
    rs[t] = ps; rq[t] = pq;
    for (int off = 128; off > 0; off >>= 1) {
        __syncthreads();
        if (t < off) { rs[t] += rs[t + off]; rq[t] += rq[t + off]; }
    }
    if (t == 0) g_statp[b * 16 + chunk] = make_float2(rs[0], rq[0]);
}

// ---------------- mma.sync GEMM: X @ Wcat (single-pass fp16) -----------------
// CTA 128x128, warps 2(M)x4(N), warp tile 64x32, K chunks 64, 3-stage pipeline.
// Single barrier per chunk. Z is a template parameter: Z=0 row-major A,
// Z=1 transposed A ([k][m] tiles, trans ldmatrix). Keeps reg pressure minimal.
#define STG_BYTES 32768
#define NSTG 3
#define OFF_A 0
#define OFF_B 16384
#define GEMM_DYNSM (NSTG * STG_BYTES)

template<int Z>
__global__ void __launch_bounds__(256, 2) gemm_mma() {
    extern __shared__ __align__(16) unsigned char smp[];
    uint32_t sbase = smem_u32(smp);

    int t = threadIdx.x, lane = t & 31, w = t >> 5;
    int wm = w >> 2, wn = w & 3;
    int mt = blockIdx.x >> 2, nt = blockIdx.x & 3;
    int b = blockIdx.y;
    int m0 = mt * 128, n0 = nt * 128;

    const __half* xs = g_xf + (size_t)b * HWHW;
    const __half* ws = Z ? g_w2f : g_w1f;

    // ---- per-thread cp.async descriptors (32-bit offsets from base ptrs) ----
    uint32_t aoff[4], adst[4], boff[4], bdst[4];
    const uint32_t astep = (Z == 0) ? 64u : 64u * HW;
    #pragma unroll
    for (int i = 0; i < 4; i++) {
        int u = t + i * 256;
        int row = u >> 3, seg = u & 7;
        if (Z == 0) {
            adst[i] = OFF_A + SWZ(row * 128 + seg * 16);
            aoff[i] = (uint32_t)((m0 + row) * HW + seg * 8);
        } else {
            int mh = u >> 9, k = (u >> 3) & 63;
            adst[i] = OFF_A + mh * 8192 + SWZ(k * 128 + seg * 16);
            aoff[i] = (uint32_t)(k * HW + m0 + mh * 64 + seg * 8);
        }
        bdst[i] = OFF_B + SWZ(row * 128 + seg * 16);
        boff[i] = (uint32_t)((n0 + row) * HW + seg * 8);
    }

    // ---- per-thread ldmatrix address components (hoisted swizzle) ----
    uint32_t aRow0 = 0, aColk[4], aRowT[4], aColTmi[4];
    if (Z == 0) {
        int a_row = (lane & 15), a_cb = (lane >> 4) * 16;
        aRow0 = OFF_A + (uint32_t)((wm * 64 + a_row) * 128);
        uint32_t m = (uint32_t)((a_row & 7) << 4);
        #pragma unroll
        for (int ks = 0; ks < 4; ks++) aColk[ks] = ((uint32_t)(ks * 32 + a_cb)) ^ m;
    } else {
        int a_rT = (lane & 7) + ((lane >> 4) & 1) * 8;
        int a_cT = ((lane >> 3) & 1) * 16;
        uint32_t m = (uint32_t)((a_rT & 7) << 4);
        #pragma unroll
        for (int ks = 0; ks < 4; ks++) aRowT[ks] = OFF_A + (uint32_t)((ks * 16 + a_rT) * 128);
        #pragma unroll
        for (int mi = 0; mi < 4; mi++) aColTmi[mi] = ((uint32_t)(mi * 32 + a_cT)) ^ m;
    }
    uint32_t bRow[2], bColk[4];
    {
        int b_row = (lane & 7) + ((lane >> 4) & 1) * 8;
        int b_cb  = ((lane >> 3) & 1) * 16;
        uint32_t m = (uint32_t)((b_row & 7) << 4);
        #pragma unroll
        for (int np = 0; np < 2; np++)
            bRow[np] = OFF_B + (uint32_t)((wn * 32 + np * 16 + b_row) * 128);
        #pragma unroll
        for (int ks = 0; ks < 4; ks++) bColk[ks] = ((uint32_t)(ks * 32 + b_cb)) ^ m;
    }

    float acc[4][4][4];
    #pragma unroll
    for (int mi = 0; mi < 4; mi++)
        #pragma unroll
        for (int ni = 0; ni < 4; ni++)
            #pragma unroll
            for (int q = 0; q < 4; q++) acc[mi][ni][q] = 0.f;

    // prologue: issue chunks 0 and 1
    #pragma unroll
    for (int c = 0; c < 2; c++) {
        uint32_t tb = sbase + c * STG_BYTES;
        #pragma unroll
        for (int i = 0; i < 4; i++) {
            CP_ASYNC16(tb + adst[i], xs + aoff[i] + c * astep);
            CP_ASYNC16(tb + bdst[i], ws + boff[i] + c * 64u);
        }
        CP_COMMIT();
    }

    #pragma unroll 1
    for (int kt = 0; kt < 8; kt++) {
        if (kt < 7) { CP_WAIT(1); } else { CP_WAIT(0); }
        __syncthreads();

        if (kt + 2 < 8) {
            uint32_t tb = sbase + ((kt + 2) % NSTG) * STG_BYTES;
            uint32_t c = (uint32_t)(kt + 2);
            #pragma unroll
            for (int i = 0; i < 4; i++) {
                CP_ASYNC16(tb + adst[i], xs + aoff[i] + c * astep);
                CP_ASYNC16(tb + bdst[i], ws + boff[i] + c * 64u);
            }
            CP_COMMIT();
        }

        uint32_t tb = sbase + (kt % NSTG) * STG_BYTES;
        #pragma unroll
        for (int ks = 0; ks < 4; ks++) {
            uint32_t ah[4][4], bh[4][2];
            if (Z == 0) {
                uint32_t base = tb + aRow0 + aColk[ks];
                #pragma unroll
                for (int mi = 0; mi < 4; mi++)
                    ldm_x4(ah[mi], base + mi * 2048);
            } else {
                uint32_t base = tb + wm * 8192 + aRowT[ks];
                #pragma unroll
                for (int mi = 0; mi < 4; mi++)
                    ldm_x4t(ah[mi], base + aColTmi[mi]);
            }
            #pragma unroll
            for (int np = 0; np < 2; np++) {
                uint32_t rh[4];
                ldm_x4(rh, tb + bRow[np] + bColk[ks]);
                bh[np * 2][0] = rh[0]; bh[np * 2][1] = rh[1];
                bh[np * 2 + 1][0] = rh[2]; bh[np * 2 + 1][1] = rh[3];
            }
            #pragma unroll
            for (int mi = 0; mi < 4; mi++)
                #pragma unroll
                for (int ni = 0; ni < 4; ni++)
                    mma16816f(acc[mi][ni], ah[mi], bh[ni]);
        }
    }
    __syncthreads();

    int gq = lane >> 2, tig = lane & 3;
    if (nt < 2) {
        // o-half: fp16, layout [b][k=row][m=col(0..255)]
        __half* of = Z ? g_oif : g_ojf;
        size_t bb = (size_t)b * (512 * 256);
        #pragma unroll
        for (int mi = 0; mi < 4; mi++) {
            int row0 = m0 + wm * 64 + mi * 16 + gq;
            #pragma unroll
            for (int ni = 0; ni < 4; ni++) {
                int col = nt * 128 + wn * 32 + ni * 8 + tig * 2;
                *(__half2*)&of[bb + (size_t)row0 * 256 + col] =
                    __floats2half2_rn(acc[mi][ni][0], acc[mi][ni][1]);
                *(__half2*)&of[bb + (size_t)(row0 + 8) * 256 + col] =
                    __floats2half2_rn(acc[mi][ni][2], acc[mi][ni][3]);
            }
        }
    } else {
        // rel-half: exp colsum partials (deterministic slots per CTA/warp)
        size_t p = ((((size_t)(Z * Bsz + b) * 2 + (nt - 2)) * 4 + mt) * 2 + wm) * 128;
        #pragma unroll
        for (int ni = 0; ni < 4; ni++) {
            float s0 = 0.f, s1 = 0.f;
            #pragma unroll
            for (int mi = 0; mi < 4; mi++) {
                s0 += expf(acc[mi][ni][0]) + expf(acc[mi][ni][2]);
                s1 += expf(acc[mi][ni][1]) + expf(acc[mi][ni][3]);
            }
            #pragma unroll
            for (int o = 4; o < 32; o <<= 1) {
                s0 += __shfl_xor_sync(0xFFFFFFFFu, s0, o);
                s1 += __shfl_xor_sync(0xFFFFFFFFu, s1, o);
            }
            if (gq == 0) {
                int cl = wn * 32 + ni * 8 + tig * 2;
                g_csp[p + cl]     = s0;
                g_csp[p + cl + 1] = s1;
            }
        }
    }
}

// ---------------- fold colsum partials (+ per-batch stats in block 0) --------
__global__ void __launch_bounds__(256) csred_kernel() {
    int i = blockIdx.x * 256 + threadIdx.x;     // 0..65535
    int side = i >> 15;
    int r = i & 32767;
    int b = r >> 8;
    int dc = r & 255;
    int d = dc >> 6, c = dc & 63;
    int nt2 = d >> 1;
    int cl = (d & 1) * 64 + c;
    size_t base = (((size_t)(side * Bsz + b) * 2 + nt2) * 4) * 2 * 128;
    float s = 0.f;
    #pragma unroll
    for (int mtw = 0; mtw < 8; mtw++) s += g_csp[base + (size_t)mtw * 128 + cl];
    g_cs[((side * Bsz + b) * ND + d) * 64 + c] = s;

    if (blockIdx.x == 0 && threadIdx.x < 128) {
        int bb = threadIdx.x;
        float ps = 0.f, pq = 0.f;
        #pragma unroll
        for (int ch = 0; ch < 16; ch++) {
            float2 p = g_statp[bb * 16 + ch];
            ps += p.x; pq += p.y;
        }
        float n = (float)HWHW;
        float mean = ps / n;
        float var  = (pq - ps * ps / n) / (n - 1.f);
        g_meanv[bb] = mean * 64.f;
        g_stdv[bb]  = sqrtf(var) * 64.f;
    }
}

// ---------------- stage-2 via mma: G = A_o^T @ p_x  (64x64, K=512) -----------
#define S2_STG 16384
#define S2_A 0
#define S2_W 8192
#define S2_DYNSM (2 * S2_STG)

__global__ void __launch_bounds__(128) stage2_mma() {
    extern __shared__ __align__(16) unsigned char smp2[];
    uint32_t sbase = smem_u32(smp2);

    int t = threadIdx.x, lane = t & 31, wn = t >> 5;   // 4 warps, each 16 N-cols
    int d = blockIdx.x, side = blockIdx.y, b = blockIdx.z;

    const __half* A = (side ? g_oif : g_ojf) + (size_t)b * (512 * 256) + d * 64;
    const __half* W = (side ? g_pif : g_pjf) + (size_t)d * (512 * 64);

    int a_r = (lane & 7) + ((lane >> 4) & 1) * 8;   // k within 16
    int a_c = ((lane >> 3) & 1) * 16;               // m byte within 32
    int w_r = (lane & 7) + ((lane >> 3) & 1) * 8;   // k within 16
    int w_c = ((lane >> 4) & 1) * 16;               // n byte within 32

    float acc[4][2][4];
    #pragma unroll
    for (int mi = 0; mi < 4; mi++)
        #pragma unroll
        for (int ni = 0; ni < 2; ni++)
            #pragma unroll
            for (int q = 0; q < 4; q++) acc[mi][ni][q] = 0.f;

    {
        uint32_t tb = sbase;
        #pragma unroll
        for (int i = 0; i < 4; i++) {
            int u = t + i * 128;
            int row = u >> 3, seg = u & 7;
            uint32_t so = SWZ(row * 128 + seg * 16);
            CP_ASYNC16(tb + S2_A + so, A + (size_t)row * 256 + seg * 8);
            CP_ASYNC16(tb + S2_W + so, W + (size_t)row * 64 + seg * 8);
        }
        CP_COMMIT();
    }

    #pragma unroll 1
    for (int kt = 0; kt < 8; kt++) {
        if (kt + 1 < 8) {
            uint32_t tb = sbase + ((kt + 1) & 1) * S2_STG;
            int k0 = (kt + 1) * 64;
            #pragma unroll
            for (int i = 0; i < 4; i++) {
                int u = t + i * 128;
                int row = u >> 3, seg = u & 7;
                uint32_t so = SWZ(row * 128 + seg * 16);
                CP_ASYNC16(tb + S2_A + so, A + (size_t)(k0 + row) * 256 + seg * 8);
                CP_ASYNC16(tb + S2_W + so, W + (size_t)(k0 + row) * 64 + seg * 8);
            }
            CP_COMMIT();
            CP_WAIT(1);
        } else {
            CP_WAIT(0);
        }
        __syncthreads();

        uint32_t tb = sbase + (kt & 1) * S2_STG;
        #pragma unroll
        for (int ks = 0; ks < 4; ks++) {
            uint32_t ah[4][4], wh[2][2];
            #pragma unroll
            for (int mi = 0; mi < 4; mi++) {
                uint32_t off = SWZ((uint32_t)((ks * 16 + a_r) * 128 + mi * 32 + a_c));
                ldm_x4t(ah[mi], tb + S2_A + off);
            }
            {
                uint32_t off = SWZ((uint32_t)((ks * 16 + w_r) * 128 + wn * 32 + w_c));
                uint32_t rh[4];
                ldm_x4t(rh, tb + S2_W + off);
                wh[0][0] = rh[0]; wh[0][1] = rh[1]; wh[1][0] = rh[2]; wh[1][1] = rh[3];
            }
            #pragma unroll
            for (int mi = 0; mi < 4; mi++)
                #pragma unroll
                for (int ni = 0; ni < 2; ni++)
                    mma16816f(acc[mi][ni], ah[mi], wh[ni]);
        }
        __syncthreads();
    }

    float* g = g_G + (size_t)((side * Bsz + b) * ND + d) * 4096;
    int gq = lane >> 2, tig = lane & 3;
    #pragma unroll
    for (int mi = 0; mi < 4; mi++) {
        int m = mi * 16 + gq;
        #pragma unroll
        for (int ni = 0; ni < 2; ni++) {
            int n = wn * 16 + ni * 8 + tig * 2;
            *(float2*)&g[m * 64 + n]       = make_float2(acc[mi][ni][0], acc[mi][ni][1]);
            *(float2*)&g[(m + 8) * 64 + n] = make_float2(acc[mi][ni][2], acc[mi][ni][3]);
        }
    }
}

// ---------------- final: one CTA per (d, b) ----------------------------------
#define FINAL_SMEM_FLOATS (4096 + 4160 + 4096 + 256 + 256 + 64 + 64 + 64 + 64 + 16)

__global__ void __launch_bounds__(256) final_depth(const float* __restrict__ p_rel_xj,
                                                   const float* __restrict__ p_rel_xi) {
    extern __shared__ float sm[];
    float* sGj  = sm;
    float* sGi  = sGj + 4096;   // 64x65 padded
    float* sWR  = sGi + 4160;
    float* red  = sWR + 4096;
    float* red2 = red + 256;
    float* sfj  = red2 + 256;
    float* sfi  = sfj + 64;
    float* sCS  = sfi + 64;
    float* sOCS = sCS + 64;
    float* sTOT = sOCS + 64;    // [0]=p total, [1]=o total

    int d = blockIdx.x, b = blockIdx.y, t = threadIdx.x;
    float xmean = g_meanv[b], xstd = g_stdv[b];

    int prw = (t >> 4) * 4, qcw = (t & 15) * 4;
    int col = t & 63, grp = t >> 6;

    #pragma unroll
    for (int i = 0; i < 16; i++) {
        int id = t + i * 256;
        int p = id >> 6, q = id & 63;
        sGj[p * 64 + q] = g_G[(size_t)((0 * Bsz + b) * ND + d) * 4096 + id];
        sGi[p * 65 + q] = g_G[(size_t)((1 * Bsz + b) * ND + d) * 4096 + id];
    }
    __syncthreads();

    for (int side = 0; side < 2; side++) {
        const float* prel = (side == 0 ? p_rel_xj : p_rel_xi) + d * 4096;
        #pragma unroll
        for (int i = 0; i < 16; i++) sWR[t + i * 256] = prel[t + i * 256];
        if (t < 64) sOCS[t] = g_cs[((side * Bsz + b) * ND + d) * 64 + t];
        __syncthreads();

        const float* G = side ? sGi : sGj;
        int gs = side ? 65 : 64;
        float acc[4][4];
        #pragma unroll
        for (int i = 0; i < 4; i++)
            #pragma unroll
            for (int j = 0; j < 4; j++) acc[i][j] = 0.f;
        #pragma unroll 8
        for (int kk = 0; kk < 64; kk++) {
            float a0 = G[(prw + 0) * gs + kk];
            float a1 = G[(prw + 1) * gs + kk];
            float a2 = G[(prw + 2) * gs + kk];
            float a3 = G[(prw + 3) * gs + kk];
            float4 w4 = *(const float4*)&sWR[kk * 64 + qcw];
            acc[0][0] = fmaf(a0, w4.x, acc[0][0]); acc[0][1] = fmaf(a0, w4.y, acc[0][1]);
            acc[0][2] = fmaf(a0, w4.z, acc[0][2]); acc[0][3] = fmaf(a0, w4.w, acc[0][3]);
            acc[1][0] = fmaf(a1, w4.x, acc[1][0]); acc[1][1] = fmaf(a1, w4.y, acc[1][1]);
            acc[1][2] = fmaf(a1, w4.z, acc[1][2]); acc[1][3] = fmaf(a1, w4.w, acc[1][3]);
            acc[2][0] = fmaf(a2, w4.x, acc[2][0]); acc[2][1] = fmaf(a2, w4.y, acc[2][1]);
            acc[2][2] = fmaf(a2, w4.z, acc[2][2]); acc[2][3] = fmaf(a2, w4.w, acc[2][3]);
            acc[3][0] = fmaf(a3, w4.x, acc[3][0]); acc[3][1] = fmaf(a3, w4.y, acc[3][1]);
            acc[3][2] = fmaf(a3, w4.z, acc[3][2]); acc[3][3] = fmaf(a3, w4.w, acc[3][3]);
        }
        __syncthreads();
        #pragma unroll
        for (int i = 0; i < 4; i++)
            #pragma unroll
            for (int j = 0; j < 4; j++)
                sWR[(prw + i) * 64 + qcw + j] = expf(acc[i][j]);
        __syncthreads();

        float s = 0.f;
        #pragma unroll
        for (int r = 0; r < 16; r++) s += sWR[(grp * 16 + r) * 64 + col];
        red[t] = s; __syncthreads();
        if (t < 64) sCS[t] = red[t] + red[t + 64] + red[t + 128] + red[t + 192];
        __syncthreads();
        if (t == 0) {
            float tp = 0.f, to = 0.f;
            for (int i = 0; i < 64; i++) { tp += sCS[i]; to += sOCS[i]; }
            sTOT[0] = tp; sTOT[1] = to;
        }
        __syncthreads();
        if (t < 64) {
            float f = sqrtf((sOCS[t] * sTOT[0]) / (sTOT[1] * sCS[t]));
            (side ? sfi : sfj)[t] = f;
        }
        __syncthreads();
    }

    float xb[16]; float s = 0.f, ss = 0.f;
    #pragma unroll
    for (int i = 0; i < 16; i++) {
        int id = t + i * 256;
        int p = id >> 6, q = id & 63;
        float v = sGj[p * 64 + q] * sfj[p] + sGi[q * 65 + p] * sfi[q];
        xb[i] = v; s += v; ss += v * v;
    }
    red[t] = s; red2[t] = ss; __syncthreads();
    for (int off = 128; off > 0; off >>= 1) {
        if (t < off) { red[t] += red[t + off]; red2[t] += red2[t + off]; }
        __syncthreads();
    }
    float n = 4096.f;
    float mean = red[0] / n;
    float var  = (red2[0] - red[0] * red[0] / n) / (n - 1.f);
    float istd = 1.f / (sqrtf(var) + 1e-5f);
    float* ob = g_xbd + (size_t)(d * Bsz + b) * 4096;
    #pragma unroll
    for (int i = 0; i < 16; i++)
        ob[t + i * 256] = (xb[i] - mean) * istd * xstd + xmean;
}

// ---------------- accumulate per-depth contributions (fixed d order) ---------
__global__ void __launch_bounds__(256) accum_kernel(float* __restrict__ out) {
    int i = blockIdx.x * 256 + threadIdx.x;      // 0 .. Bsz*4096-1
    int b = i >> 12, idx = i & 4095;
    float s = 0.f;
    #pragma unroll
    for (int d = 0; d < ND; d++)
        s += g_xbd[(size_t)(d * Bsz + b) * 4096 + idx];
    out[i] = s;
}

// ---------------- launcher ---------------------------------------------------
extern "C" void kernel_launch(void* const* d_in, const int* in_sizes, int n_in,
                              void* d_out, int out_size) {
    const float* x        = (const float*)d_in[0];
    const float* o_xj     = (const float*)d_in[1];
    const float* o_xi     = (const float*)d_in[2];
    const float* p_xj     = (const float*)d_in[3];
    const float* p_xi     = (const float*)d_in[4];
    const float* o_rel_xj = (const float*)d_in[5];
    const float* o_rel_xi = (const float*)d_in[6];
    const float* p_rel_xj = (const float*)d_in[7];
    const float* p_rel_xi = (const float*)d_in[8];
    float* out = (float*)d_out;

    cudaFuncSetAttribute(final_depth, cudaFuncAttributeMaxDynamicSharedMemorySize,
                         FINAL_SMEM_FLOATS * sizeof(float));
    cudaFuncSetAttribute(gemm_mma<0>, cudaFuncAttributeMaxDynamicSharedMemorySize,
                         GEMM_DYNSM);
    cudaFuncSetAttribute(gemm_mma<1>, cudaFuncAttributeMaxDynamicSharedMemorySize,
                         GEMM_DYNSM);
    cudaFuncSetAttribute(stage2_mma, cudaFuncAttributeMaxDynamicSharedMemorySize,
                         S2_DYNSM);

    // gemm_mma<0> is launch #4 so ncu (-s 5 -c 1) profiles it
    convw_kernel<<<dim3(512, 2), 256>>>(o_xj, o_rel_xj, o_xi, o_rel_xi);
    convp_kernel<<<dim3(512, 2), 256>>>(p_xj, p_xi);
    convx_kernel<<<dim3(16, Bsz), 256>>>(x);
    gemm_mma<0><<<dim3(16, Bsz), 256, GEMM_DYNSM>>>();
    gemm_mma<1><<<dim3(16, Bsz), 256, GEMM_DYNSM>>>();
    csred_kernel<<<256, 256>>>();
    stage2_mma<<<dim3(ND, 2, Bsz), 128, S2_DYNSM>>>();
    final_depth<<<dim3(ND, Bsz), 256, FINAL_SMEM_FLOATS * sizeof(float)>>>(p_rel_xj, p_rel_xi);
    accum_kernel<<<Bsz * 4096 / 256, 256>>>(out);
}